// round 7
// baseline (speedup 1.0000x reference)
#include <cuda_runtime.h>
#include <cuda_bf16.h>
#include <math.h>
#include <stdint.h>

#define B_   2
#define SEQ  1024
#define DIM_ 2048
#define KVD  512
#define NH   32
#define NKV  8
#define HD   64
#define MTOT (B_ * SEQ)   // 2048
#define QKVW 3072         // fused q|k|v width

// ---------------- scratch (__device__ globals; allocation-guard safe) ------
__device__ float g_qkv[MTOT * QKVW];
__device__ __nv_bfloat16 g_xh[MTOT * DIM_], g_xl[MTOT * DIM_];
__device__ __nv_bfloat16 g_ah[MTOT * DIM_], g_al[MTOT * DIM_];
// fused transposed weights [3072][2048]: rows 0-2047 = wq^T, 2048-2559 = wk^T, 2560-3071 = wv^T
__device__ __nv_bfloat16 g_wh[QKVW * DIM_], g_wl[QKVW * DIM_];
__device__ __nv_bfloat16 g_woh[DIM_ * DIM_], g_wol[DIM_ * DIM_];

// ---------------- helpers ---------------------------------------------------
__device__ __forceinline__ uint32_t smem_u32(const void* p) {
    uint32_t a;
    asm("{ .reg .u64 t; cvta.to.shared.u64 t, %1; cvt.u32.u64 %0, t; }"
        : "=r"(a) : "l"(p));
    return a;
}
__device__ __forceinline__ void cp16(uint32_t dst, const void* src) {
    uint64_t g = __cvta_generic_to_global(src);
    asm volatile("cp.async.cg.shared.global [%0], [%1], 16;" :: "r"(dst), "l"(g));
}
__device__ __forceinline__ void ldmx4(uint32_t* r, uint32_t addr) {
    asm volatile("ldmatrix.sync.aligned.m8n8.x4.shared.b16 {%0,%1,%2,%3}, [%4];"
                 : "=r"(r[0]), "=r"(r[1]), "=r"(r[2]), "=r"(r[3]) : "r"(addr));
}
__device__ __forceinline__ void ldmx4t(uint32_t* r, uint32_t addr) {
    asm volatile("ldmatrix.sync.aligned.m8n8.x4.trans.shared.b16 {%0,%1,%2,%3}, [%4];"
                 : "=r"(r[0]), "=r"(r[1]), "=r"(r[2]), "=r"(r[3]) : "r"(addr));
}
__device__ __forceinline__ void mma16816(float* c, const uint32_t* a, const uint32_t* b) {
    asm volatile(
        "mma.sync.aligned.m16n8k16.row.col.f32.bf16.bf16.f32 "
        "{%0,%1,%2,%3}, {%4,%5,%6,%7}, {%8,%9}, {%0,%1,%2,%3};"
        : "+f"(c[0]), "+f"(c[1]), "+f"(c[2]), "+f"(c[3])
        : "r"(a[0]), "r"(a[1]), "r"(a[2]), "r"(a[3]), "r"(b[0]), "r"(b[1]));
}
// split pair (a,b) into packed bf16x2 hi and lo words
__device__ __forceinline__ void split2(float a, float b, uint32_t& hi, uint32_t& lo) {
    __nv_bfloat16 ha = __float2bfloat16(a), hb = __float2bfloat16(b);
    __nv_bfloat16 la = __float2bfloat16(a - __bfloat162float(ha));
    __nv_bfloat16 lb = __float2bfloat16(b - __bfloat162float(hb));
    __nv_bfloat162 th; th.x = ha; th.y = hb;
    __nv_bfloat162 tl; tl.x = la; tl.y = lb;
    hi = *reinterpret_cast<uint32_t*>(&th);
    lo = *reinterpret_cast<uint32_t*>(&tl);
}

// ---------------- conversion kernels ---------------------------------------
__global__ void split_bf16(const float* __restrict__ src,
                           __nv_bfloat16* __restrict__ hi,
                           __nv_bfloat16* __restrict__ lo, int n) {
    int i = blockIdx.x * blockDim.x + threadIdx.x;
    if (i >= n) return;
    float v = src[i];
    __nv_bfloat16 h = __float2bfloat16(v);
    hi[i] = h;
    lo[i] = __float2bfloat16(v - __bfloat162float(h));
}

// W [K,N] row-major -> hi/lo [N,K] row-major (N local to this call)
__global__ void transpose_split(const float* __restrict__ W,
                                __nv_bfloat16* __restrict__ hi,
                                __nv_bfloat16* __restrict__ lo, int K, int N) {
    __shared__ float t[32][33];
    int k0 = blockIdx.y * 32, n0 = blockIdx.x * 32;
    int tx = threadIdx.x, ty = threadIdx.y;   // 32 x 8
    #pragma unroll
    for (int r = ty; r < 32; r += 8)
        t[r][tx] = W[(size_t)(k0 + r) * N + n0 + tx];
    __syncthreads();
    #pragma unroll
    for (int r = ty; r < 32; r += 8) {
        float v = t[tx][r];   // W[k0+tx][n0+r]
        __nv_bfloat16 h = __float2bfloat16(v);
        size_t o = (size_t)(n0 + r) * K + k0 + tx;
        hi[o] = h;
        lo[o] = __float2bfloat16(v - __bfloat162float(h));
    }
}

// ---------------- mma.sync bf16 GEMM, 4-stage cp.async pipeline -------------
// C[M,N] = (Ah+Al)[M,K] @ (Bh+Bl)^T with B stored [N,K] row-major.
// 128x128 block tile, BK=16, 256 threads (8 warps, each 32m x 64n).
// SMEM rows: 32B data + 16B pad = 48B  (12r mod 32 banks -> conflict-free).
#define ROWB       48
#define TILE_B     (128 * ROWB)          // 6144
#define STAGE_B    (4 * TILE_B)          // 24576 (Ah, Al, Bh, Bl)
#define NSTAGE     4
#define GEMM_SMEM  (NSTAGE * STAGE_B)    // 98304

__global__ __launch_bounds__(256, 2)
void mma_gemm(const __nv_bfloat16* __restrict__ Ah, const __nv_bfloat16* __restrict__ Al,
              const __nv_bfloat16* __restrict__ Bh, const __nv_bfloat16* __restrict__ Bl,
              float* __restrict__ C, int N, int K) {
    extern __shared__ char sm[];
    const uint32_t sbase = smem_u32(sm);
    const int tid  = threadIdx.x;
    const int wid  = tid >> 5;
    const int lane = tid & 31;
    const int wm = wid & 3;
    const int wn = wid >> 2;
    const int m0 = blockIdx.y * 128, n0 = blockIdx.x * 128;

    float acc[2][8][4];
    #pragma unroll
    for (int i = 0; i < 2; i++)
        #pragma unroll
        for (int j = 0; j < 8; j++)
            #pragma unroll
            for (int q = 0; q < 4; q++) acc[i][j][q] = 0.0f;

    const __nv_bfloat16* base[4] = {
        Ah + (size_t)m0 * K, Al + (size_t)m0 * K,
        Bh + (size_t)n0 * K, Bl + (size_t)n0 * K };

    // per-thread load coords: one 16B chunk per operand tile per stage
    const int lrow = tid >> 1;            // 0..127
    const int lcol = (tid & 1) * 8;       // bf16 element offset (0 or 8)

    auto load_stage = [&](int cidx) {
        const uint32_t db = sbase + (uint32_t)(cidx & (NSTAGE - 1)) * STAGE_B;
        const int k0 = cidx << 4;
        #pragma unroll
        for (int t = 0; t < 4; t++)
            cp16(db + t * TILE_B + lrow * ROWB + (lcol ? 16 : 0),
                 base[t] + (size_t)lrow * K + k0 + lcol);
        asm volatile("cp.async.commit_group;");
    };

    const int aRow  = lane & 15;
    const uint32_t aColb = (uint32_t)(lane >> 4) * 16;
    const int bRow  = ((lane & 16) >> 1) + (lane & 7);
    const uint32_t bColb = (uint32_t)((lane >> 3) & 1) * 16;

    const int NC = K >> 4;
    load_stage(0); load_stage(1); load_stage(2);

    for (int c = 0; c < NC; c++) {
        asm volatile("cp.async.wait_group 2;");
        __syncthreads();
        if (c + 3 < NC) load_stage(c + 3);
        else            asm volatile("cp.async.commit_group;");

        const uint32_t db = sbase + (uint32_t)(c & (NSTAGE - 1)) * STAGE_B;

        uint32_t ah[2][4], al[2][4];
        #pragma unroll
        for (int mt = 0; mt < 2; mt++) {
            uint32_t addr = db + (uint32_t)(wm * 32 + mt * 16 + aRow) * ROWB + aColb;
            ldmx4(ah[mt], addr);
            ldmx4(al[mt], addr + TILE_B);
        }
        #pragma unroll
        for (int ng = 0; ng < 4; ng++) {
            uint32_t bh[4], bl[4];
            uint32_t addr = db + 2 * TILE_B +
                            (uint32_t)(wn * 64 + ng * 16 + bRow) * ROWB + bColb;
            ldmx4(bh, addr);
            ldmx4(bl, addr + TILE_B);
            #pragma unroll
            for (int mt = 0; mt < 2; mt++)
                #pragma unroll
                for (int jj = 0; jj < 2; jj++) {
                    const int nt = ng * 2 + jj, hf = jj * 2;
                    mma16816(acc[mt][nt], ah[mt], &bh[hf]);
                    mma16816(acc[mt][nt], ah[mt], &bl[hf]);
                    mma16816(acc[mt][nt], al[mt], &bh[hf]);
                }
        }
    }

    const int g = lane >> 2, tg = lane & 3;
    #pragma unroll
    for (int mt = 0; mt < 2; mt++)
        #pragma unroll
        for (int nt = 0; nt < 8; nt++) {
            const int row = m0 + wm * 32 + mt * 16 + g;
            const int col = n0 + wn * 64 + nt * 8 + tg * 2;
            *(float2*)&C[(size_t)row * N + col] =
                make_float2(acc[mt][nt][0], acc[mt][nt][1]);
            *(float2*)&C[(size_t)(row + 8) * N + col] =
                make_float2(acc[mt][nt][2], acc[mt][nt][3]);
        }
}

// ---------------- RoPE (strided view) ---------------------------------------
__global__ void rope2(float* __restrict__ x, int width, int stride) {
    const int pairsPerRow = width >> 1;
    int idx = blockIdx.x * blockDim.x + threadIdx.x;
    int total = MTOT * pairsPerRow;
    if (idx >= total) return;
    int row = idx / pairsPerRow;
    int p   = idx - row * pairsPerRow;
    int n   = row & (SEQ - 1);
    int i   = p & 31;
    float freq = expf(-(float)i * (9.2103403719761836f / 32.0f));
    float ph = (float)n * freq;
    float sn, cs;
    sincosf(ph, &sn, &cs);
    float* base = x + (size_t)row * stride + 2 * p;
    float x0 = base[0], x1 = base[1];
    base[0] = x0 * cs - x1 * sn;
    base[1] = x0 * sn + x1 * cs;
}

// ---------------- tensor-core flash attention --------------------------------
// block = 128 thr (4 warps), tile = 64 queries x 64 dim, key tiles of 64.
// smem: Qh Ql Kh Kl Vh Vl, each 64 rows x 144B stride (K-style layout for V;
// V^T fragments come from ldmatrix.trans).
#define SR 144
#define TSZ (64 * SR)            // 9216
#define FLASH_SMEM (6 * TSZ)     // 55296

__global__ __launch_bounds__(128)
void flash_tc(const float* __restrict__ qkv,
              __nv_bfloat16* __restrict__ oh, __nv_bfloat16* __restrict__ ol) {
    extern __shared__ char sm[];
    const uint32_t sb = smem_u32(sm);
    const int tid = threadIdx.x, w = tid >> 5, lane = tid & 31;
    const int qt = blockIdx.x, h = blockIdx.y, b = blockIdx.z, kvh = h >> 2;
    const int q0 = qt * 64;
    const int oQh = 0, oQl = TSZ, oKh = 2*TSZ, oKl = 3*TSZ, oVh = 4*TSZ, oVl = 5*TSZ;

    // ---- load Q tile (scaled by 1/sqrt(hd)=0.125), split hi/lo ----
    {
        int r = tid >> 1, dh = (tid & 1) * 32;
        const float* src = qkv + ((size_t)(b * SEQ + q0 + r)) * QKVW + h * 64 + dh;
        #pragma unroll
        for (int j = 0; j < 8; j++) {
            float4 v = *(const float4*)(src + j * 4);
            v.x *= 0.125f; v.y *= 0.125f; v.z *= 0.125f; v.w *= 0.125f;
            uint32_t h01, l01, h23, l23;
            split2(v.x, v.y, h01, l01);
            split2(v.z, v.w, h23, l23);
            int off = r * SR + (dh + j * 4) * 2;
            *(uint2*)(sm + oQh + off) = make_uint2(h01, h23);
            *(uint2*)(sm + oQl + off) = make_uint2(l01, l23);
        }
    }
    __syncthreads();

    // Q A-fragments (per warp: rows w*16..w*16+15, 4 k-steps over d)
    uint32_t qah[4][4], qal[4][4];
    {
        int aRow = lane & 15;
        uint32_t aCol = (uint32_t)(lane >> 4) * 16;
        #pragma unroll
        for (int ks = 0; ks < 4; ks++) {
            uint32_t ad = sb + oQh + (uint32_t)(w * 16 + aRow) * SR + aCol + ks * 32;
            ldmx4(qah[ks], ad);
            ldmx4(qal[ks], ad + TSZ);
        }
    }

    const int bRow = ((lane & 16) >> 1) | (lane & 7);
    const uint32_t bCol = (uint32_t)((lane >> 3) & 1) * 16;
    // trans-ldmatrix lane->addr for V (B-frag of P@V): row = key, col-half = d
    const int vRow = lane & 15;
    const uint32_t vColb = (uint32_t)((lane & 16) >> 1) * 2;  // 0 or 16 bytes (d offset 0/8)
    const int g = lane >> 2, tg = lane & 3;

    float oacc[8][4];
    #pragma unroll
    for (int nt = 0; nt < 8; nt++)
        #pragma unroll
        for (int q = 0; q < 4; q++) oacc[nt][q] = 0.0f;
    float m0v = -INFINITY, m1v = -INFINITY, l0v = 0.0f, l1v = 0.0f;

    for (int kt = 0; kt <= qt; kt++) {
        __syncthreads();   // protect smem K/V from previous iteration's readers
        // ---- load K,V tile (both [key][d] layout, hi/lo split) ----
        {
            int r = tid >> 1, dh = (tid & 1) * 32;
            const float* ksrc = qkv + ((size_t)(b * SEQ + kt * 64 + r)) * QKVW
                                + DIM_ + kvh * 64 + dh;
            const float* vsrc = ksrc + KVD;
            #pragma unroll
            for (int j = 0; j < 8; j++) {
                int off = r * SR + (dh + j * 4) * 2;
                float4 kv = *(const float4*)(ksrc + j * 4);
                uint32_t h01, l01, h23, l23;
                split2(kv.x, kv.y, h01, l01);
                split2(kv.z, kv.w, h23, l23);
                *(uint2*)(sm + oKh + off) = make_uint2(h01, h23);
                *(uint2*)(sm + oKl + off) = make_uint2(l01, l23);

                float4 vv = *(const float4*)(vsrc + j * 4);
                split2(vv.x, vv.y, h01, l01);
                split2(vv.z, vv.w, h23, l23);
                *(uint2*)(sm + oVh + off) = make_uint2(h01, h23);
                *(uint2*)(sm + oVl + off) = make_uint2(l01, l23);
            }
        }
        __syncthreads();

        // ---- S = Q @ K^T (hi/lo 3-product) ----
        float sacc[8][4];
        #pragma unroll
        for (int nt = 0; nt < 8; nt++)
            #pragma unroll
            for (int q = 0; q < 4; q++) sacc[nt][q] = 0.0f;

        #pragma unroll
        for (int ks = 0; ks < 4; ks++) {
            #pragma unroll
            for (int ng = 0; ng < 4; ng++) {
                uint32_t kbh[4], kbl[4];
                uint32_t adr = sb + oKh + (uint32_t)(ng * 16 + bRow) * SR + bCol + ks * 32;
                ldmx4(kbh, adr);
                ldmx4(kbl, adr + TSZ);
                #pragma unroll
                for (int jj = 0; jj < 2; jj++) {
                    const int nt = ng * 2 + jj, hf = jj * 2;
                    mma16816(sacc[nt], qah[ks], &kbh[hf]);
                    mma16816(sacc[nt], qah[ks], &kbl[hf]);
                    mma16816(sacc[nt], qal[ks], &kbh[hf]);
                }
            }
        }

        // ---- causal mask (diagonal tile only) ----
        if (kt == qt) {
            int r0 = w * 16 + g, r1 = r0 + 8;
            #pragma unroll
            for (int nt = 0; nt < 8; nt++) {
                int c0 = nt * 8 + tg * 2;
                if (c0     > r0) sacc[nt][0] = -1e30f;
                if (c0 + 1 > r0) sacc[nt][1] = -1e30f;
                if (c0     > r1) sacc[nt][2] = -1e30f;
                if (c0 + 1 > r1) sacc[nt][3] = -1e30f;
            }
        }

        // ---- online softmax ----
        float mx0 = -INFINITY, mx1 = -INFINITY;
        #pragma unroll
        for (int nt = 0; nt < 8; nt++) {
            mx0 = fmaxf(mx0, fmaxf(sacc[nt][0], sacc[nt][1]));
            mx1 = fmaxf(mx1, fmaxf(sacc[nt][2], sacc[nt][3]));
        }
        mx0 = fmaxf(mx0, __shfl_xor_sync(0xffffffffu, mx0, 1));
        mx0 = fmaxf(mx0, __shfl_xor_sync(0xffffffffu, mx0, 2));
        mx1 = fmaxf(mx1, __shfl_xor_sync(0xffffffffu, mx1, 1));
        mx1 = fmaxf(mx1, __shfl_xor_sync(0xffffffffu, mx1, 2));

        float mn0 = fmaxf(m0v, mx0), mn1 = fmaxf(m1v, mx1);
        float cr0 = __expf(m0v - mn0), cr1 = __expf(m1v - mn1);
        m0v = mn0; m1v = mn1;
        l0v *= cr0; l1v *= cr1;
        #pragma unroll
        for (int nt = 0; nt < 8; nt++) {
            oacc[nt][0] *= cr0; oacc[nt][1] *= cr0;
            oacc[nt][2] *= cr1; oacc[nt][3] *= cr1;
        }
        float rs0 = 0.0f, rs1 = 0.0f;

        // ---- P = exp(S-m); O += P @ V (hi/lo 3-product), fused per key-step ----
        #pragma unroll
        for (int ks = 0; ks < 4; ks++) {
            float p[2][4];
            #pragma unroll
            for (int jj = 0; jj < 2; jj++) {
                const int nt = 2 * ks + jj;
                p[jj][0] = __expf(sacc[nt][0] - mn0);
                p[jj][1] = __expf(sacc[nt][1] - mn0);
                p[jj][2] = __expf(sacc[nt][2] - mn1);
                p[jj][3] = __expf(sacc[nt][3] - mn1);
                rs0 += p[jj][0] + p[jj][1];
                rs1 += p[jj][2] + p[jj][3];
            }
            uint32_t pah[4], pal[4];
            split2(p[0][0], p[0][1], pah[0], pal[0]);
            split2(p[0][2], p[0][3], pah[1], pal[1]);
            split2(p[1][0], p[1][1], pah[2], pal[2]);
            split2(p[1][2], p[1][3], pah[3], pal[3]);

            #pragma unroll
            for (int ng = 0; ng < 4; ng++) {
                // V^T fragments via trans ldmatrix on [key][d] tile:
                // rows = key ks*16 + (lane&15), col-half d = ng*16 + ((lane&16)>>1)
                uint32_t vbh[4], vbl[4];
                uint32_t adr = sb + oVh + (uint32_t)(ks * 16 + vRow) * SR
                               + (uint32_t)ng * 32 + vColb;
                ldmx4t(vbh, adr);
                ldmx4t(vbl, adr + TSZ);
                #pragma unroll
                for (int jj = 0; jj < 2; jj++) {
                    const int nt = ng * 2 + jj, hf = jj * 2;
                    mma16816(oacc[nt], pah, &vbh[hf]);
                    mma16816(oacc[nt], pah, &vbl[hf]);
                    mma16816(oacc[nt], pal, &vbh[hf]);
                }
            }
        }
        rs0 += __shfl_xor_sync(0xffffffffu, rs0, 1);
        rs0 += __shfl_xor_sync(0xffffffffu, rs0, 2);
        rs1 += __shfl_xor_sync(0xffffffffu, rs1, 1);
        rs1 += __shfl_xor_sync(0xffffffffu, rs1, 2);
        l0v += rs0; l1v += rs1;
    }

    // ---- epilogue: normalize, split to bf16 hi/lo, store ----
    const float i0 = 1.0f / l0v, i1 = 1.0f / l1v;
    const int r0 = q0 + w * 16 + g;
    #pragma unroll
    for (int nt = 0; nt < 8; nt++) {
        const int col = h * 64 + nt * 8 + tg * 2;
        const size_t o0 = ((size_t)(b * SEQ + r0)) * DIM_ + col;
        const size_t o1 = o0 + (size_t)8 * DIM_;
        uint32_t H, L;
        split2(oacc[nt][0] * i0, oacc[nt][1] * i0, H, L);
        *(uint32_t*)&oh[o0] = H;
        *(uint32_t*)&ol[o0] = L;
        split2(oacc[nt][2] * i1, oacc[nt][3] * i1, H, L);
        *(uint32_t*)&oh[o1] = H;
        *(uint32_t*)&ol[o1] = L;
    }
}

// ---------------------------------------------------------------------------
extern "C" void kernel_launch(void* const* d_in, const int* in_sizes, int n_in,
                              void* d_out, int out_size) {
    const float* x  = (const float*)d_in[0];
    const float* wq = (const float*)d_in[1];
    const float* wk = (const float*)d_in[2];
    const float* wv = (const float*)d_in[3];
    const float* wo = (const float*)d_in[4];
    float* out = (float*)d_out;

    float* qkv;
    cudaGetSymbolAddress((void**)&qkv, g_qkv);
    __nv_bfloat16 *xh, *xl, *ah, *al, *wh, *wl, *woh, *wol;
    cudaGetSymbolAddress((void**)&xh,  g_xh);  cudaGetSymbolAddress((void**)&xl,  g_xl);
    cudaGetSymbolAddress((void**)&ah,  g_ah);  cudaGetSymbolAddress((void**)&al,  g_al);
    cudaGetSymbolAddress((void**)&wh,  g_wh);  cudaGetSymbolAddress((void**)&wl,  g_wl);
    cudaGetSymbolAddress((void**)&woh, g_woh); cudaGetSymbolAddress((void**)&wol, g_wol);

    cudaFuncSetAttribute(mma_gemm, cudaFuncAttributeMaxDynamicSharedMemorySize, GEMM_SMEM);
    cudaFuncSetAttribute(flash_tc, cudaFuncAttributeMaxDynamicSharedMemorySize, FLASH_SMEM);

    const int M = MTOT;

    // ---- convert input + weights (fused transposed weight buffer) ----
    {
        int n = M * DIM_;
        split_bf16<<<(n + 255) / 256, 256>>>(x, xh, xl, n);
        dim3 blk(32, 8);
        transpose_split<<<dim3(DIM_ / 32, DIM_ / 32), blk>>>(
            wq, wh, wl, DIM_, DIM_);
        transpose_split<<<dim3(KVD / 32, DIM_ / 32), blk>>>(
            wk, wh + (size_t)DIM_ * DIM_, wl + (size_t)DIM_ * DIM_, DIM_, KVD);
        transpose_split<<<dim3(KVD / 32, DIM_ / 32), blk>>>(
            wv, wh + (size_t)(DIM_ + KVD) * DIM_, wl + (size_t)(DIM_ + KVD) * DIM_, DIM_, KVD);
        transpose_split<<<dim3(DIM_ / 32, DIM_ / 32), blk>>>(
            wo, woh, wol, DIM_, DIM_);
    }

    // ---- fused QKV projection ----
    mma_gemm<<<dim3(QKVW / 128, M / 128), 256, GEMM_SMEM>>>(xh, xl, wh, wl, qkv, QKVW, DIM_);

    // ---- RoPE on q and k sections ----
    rope2<<<(M * (DIM_ / 2) + 255) / 256, 256>>>(qkv, DIM_, QKVW);
    rope2<<<(M * (KVD  / 2) + 255) / 256, 256>>>(qkv + DIM_, KVD, QKVW);

    // ---- tensor-core causal GQA flash attention (writes bf16 hi/lo) ----
    flash_tc<<<dim3(SEQ / 64, NH, B_), 128, FLASH_SMEM>>>(qkv, ah, al);

    // ---- output projection ----
    mma_gemm<<<dim3(DIM_ / 128, M / 128), 256, GEMM_SMEM>>>(ah, al, woh, wol, out, DIM_, DIM_);
}

// round 8
// speedup vs baseline: 1.0632x; 1.0632x over previous
#include <cuda_runtime.h>
#include <cuda_bf16.h>
#include <math.h>
#include <stdint.h>

#define B_   2
#define SEQ  1024
#define DIM_ 2048
#define KVD  512
#define NH   32
#define NKV  8
#define HD   64
#define MTOT (B_ * SEQ)   // 2048
#define QKVW 3072         // fused q|k|v width

// ---------------- scratch (__device__ globals; allocation-guard safe) ------
__device__ float g_qkv[MTOT * QKVW];
__device__ __nv_bfloat16 g_xh[MTOT * DIM_], g_xl[MTOT * DIM_];
__device__ __nv_bfloat16 g_ah[MTOT * DIM_], g_al[MTOT * DIM_];
// fused transposed weights [3072][2048]: rows 0-2047 = wq^T, 2048-2559 = wk^T, 2560-3071 = wv^T
__device__ __nv_bfloat16 g_wh[QKVW * DIM_], g_wl[QKVW * DIM_];
__device__ __nv_bfloat16 g_woh[DIM_ * DIM_], g_wol[DIM_ * DIM_];

// ---------------- helpers ---------------------------------------------------
__device__ __forceinline__ uint32_t smem_u32(const void* p) {
    uint32_t a;
    asm("{ .reg .u64 t; cvta.to.shared.u64 t, %1; cvt.u32.u64 %0, t; }"
        : "=r"(a) : "l"(p));
    return a;
}
__device__ __forceinline__ void cp16(uint32_t dst, const void* src) {
    uint64_t g = __cvta_generic_to_global(src);
    asm volatile("cp.async.cg.shared.global [%0], [%1], 16;" :: "r"(dst), "l"(g));
}
__device__ __forceinline__ void ldmx4(uint32_t* r, uint32_t addr) {
    asm volatile("ldmatrix.sync.aligned.m8n8.x4.shared.b16 {%0,%1,%2,%3}, [%4];"
                 : "=r"(r[0]), "=r"(r[1]), "=r"(r[2]), "=r"(r[3]) : "r"(addr));
}
__device__ __forceinline__ void ldmx4t(uint32_t* r, uint32_t addr) {
    asm volatile("ldmatrix.sync.aligned.m8n8.x4.trans.shared.b16 {%0,%1,%2,%3}, [%4];"
                 : "=r"(r[0]), "=r"(r[1]), "=r"(r[2]), "=r"(r[3]) : "r"(addr));
}
__device__ __forceinline__ void mma16816(float* c, const uint32_t* a, const uint32_t* b) {
    asm volatile(
        "mma.sync.aligned.m16n8k16.row.col.f32.bf16.bf16.f32 "
        "{%0,%1,%2,%3}, {%4,%5,%6,%7}, {%8,%9}, {%0,%1,%2,%3};"
        : "+f"(c[0]), "+f"(c[1]), "+f"(c[2]), "+f"(c[3])
        : "r"(a[0]), "r"(a[1]), "r"(a[2]), "r"(a[3]), "r"(b[0]), "r"(b[1]));
}
// split pair (a,b) into packed bf16x2 hi and lo words
__device__ __forceinline__ void split2(float a, float b, uint32_t& hi, uint32_t& lo) {
    __nv_bfloat16 ha = __float2bfloat16(a), hb = __float2bfloat16(b);
    __nv_bfloat16 la = __float2bfloat16(a - __bfloat162float(ha));
    __nv_bfloat16 lb = __float2bfloat16(b - __bfloat162float(hb));
    __nv_bfloat162 th; th.x = ha; th.y = hb;
    __nv_bfloat162 tl; tl.x = la; tl.y = lb;
    hi = *reinterpret_cast<uint32_t*>(&th);
    lo = *reinterpret_cast<uint32_t*>(&tl);
}

// ---------------- conversion kernels ---------------------------------------
__global__ void split_bf16(const float* __restrict__ src,
                           __nv_bfloat16* __restrict__ hi,
                           __nv_bfloat16* __restrict__ lo, int n) {
    int i = blockIdx.x * blockDim.x + threadIdx.x;
    if (i >= n) return;
    float v = src[i];
    __nv_bfloat16 h = __float2bfloat16(v);
    hi[i] = h;
    lo[i] = __float2bfloat16(v - __bfloat162float(h));
}

// W [K,N] row-major -> hi/lo [N,K] row-major (N local to this call)
__global__ void transpose_split(const float* __restrict__ W,
                                __nv_bfloat16* __restrict__ hi,
                                __nv_bfloat16* __restrict__ lo, int K, int N) {
    __shared__ float t[32][33];
    int k0 = blockIdx.y * 32, n0 = blockIdx.x * 32;
    int tx = threadIdx.x, ty = threadIdx.y;   // 32 x 8
    #pragma unroll
    for (int r = ty; r < 32; r += 8)
        t[r][tx] = W[(size_t)(k0 + r) * N + n0 + tx];
    __syncthreads();
    #pragma unroll
    for (int r = ty; r < 32; r += 8) {
        float v = t[tx][r];   // W[k0+tx][n0+r]
        __nv_bfloat16 h = __float2bfloat16(v);
        size_t o = (size_t)(n0 + r) * K + k0 + tx;
        hi[o] = h;
        lo[o] = __float2bfloat16(v - __bfloat162float(h));
    }
}

// ---------------- mma.sync bf16 GEMM, 3-stage cp.async pipeline -------------
// C[M,N] = (Ah+Al)[M,K] @ (Bh+Bl)^T with B stored [N,K] row-major.
// 128x128 block tile, BK=32, 256 threads (8 warps, each 32m x 64n).
// SMEM rows padded to 80B (stride 40 bf16) => conflict-free ldmatrix.
#define ROWB       80
#define TILE_B     (128 * ROWB)          // 10240 bytes per operand tile
#define STAGE_B    (4 * TILE_B)          // 40960 (Ah, Al, Bh, Bl)
#define NSTAGE     3
#define GEMM_SMEM  (NSTAGE * STAGE_B)    // 122880

__global__ __launch_bounds__(256)
void mma_gemm(const __nv_bfloat16* __restrict__ Ah, const __nv_bfloat16* __restrict__ Al,
              const __nv_bfloat16* __restrict__ Bh, const __nv_bfloat16* __restrict__ Bl,
              float* __restrict__ C, int N, int K) {
    extern __shared__ char sm[];
    const uint32_t sbase = smem_u32(sm);
    const int tid  = threadIdx.x;
    const int wid  = tid >> 5;
    const int lane = tid & 31;
    const int wm = wid & 3;
    const int wn = wid >> 2;
    const int m0 = blockIdx.y * 128, n0 = blockIdx.x * 128;

    float acc[2][8][4];
    #pragma unroll
    for (int i = 0; i < 2; i++)
        #pragma unroll
        for (int j = 0; j < 8; j++)
            #pragma unroll
            for (int q = 0; q < 4; q++) acc[i][j][q] = 0.0f;

    const __nv_bfloat16* base[4] = {
        Ah + (size_t)m0 * K, Al + (size_t)m0 * K,
        Bh + (size_t)n0 * K, Bl + (size_t)n0 * K };

    // per-thread load coords: 2 chunks of 16B per operand tile per stage
    const int r0 = tid >> 2, c0 = tid & 3;
    const int r1 = (tid + 256) >> 2, c1 = tid & 3;

    auto load_stage = [&](int cidx) {
        const int k0 = cidx << 5;
        const uint32_t db = sbase + (uint32_t)(cidx % NSTAGE) * STAGE_B;
        #pragma unroll
        for (int t = 0; t < 4; t++) {
            const uint32_t tb = db + t * TILE_B;
            cp16(tb + r0 * ROWB + c0 * 16, base[t] + (size_t)r0 * K + k0 + c0 * 8);
            cp16(tb + r1 * ROWB + c1 * 16, base[t] + (size_t)r1 * K + k0 + c1 * 8);
        }
        asm volatile("cp.async.commit_group;");
    };

    const int aRow  = lane & 15;
    const uint32_t aColb = (uint32_t)(lane >> 4) * 16;
    const int bRow  = ((lane & 16) >> 1) + (lane & 7);
    const uint32_t bColb = (uint32_t)((lane >> 3) & 1) * 16;

    const int NC = K >> 5;
    load_stage(0);
    load_stage(1);

    for (int c = 0; c < NC; c++) {
        if (c + 2 < NC) load_stage(c + 2);
        else            asm volatile("cp.async.commit_group;");
        asm volatile("cp.async.wait_group 2;");
        __syncthreads();

        const uint32_t db = sbase + (uint32_t)(c % NSTAGE) * STAGE_B;
        #pragma unroll
        for (int ks = 0; ks < 2; ks++) {
            const uint32_t kb = (uint32_t)ks * 32;
            uint32_t ah[2][4], al[2][4];
            #pragma unroll
            for (int mt = 0; mt < 2; mt++) {
                uint32_t addr = db + (uint32_t)(wm * 32 + mt * 16 + aRow) * ROWB + aColb + kb;
                ldmx4(ah[mt], addr);
                ldmx4(al[mt], addr + TILE_B);
            }
            #pragma unroll
            for (int ng = 0; ng < 4; ng++) {
                uint32_t bh[4], bl[4];
                uint32_t addr = db + 2 * TILE_B +
                                (uint32_t)(wn * 64 + ng * 16 + bRow) * ROWB + bColb + kb;
                ldmx4(bh, addr);
                ldmx4(bl, addr + TILE_B);
                #pragma unroll
                for (int mt = 0; mt < 2; mt++)
                    #pragma unroll
                    for (int jj = 0; jj < 2; jj++) {
                        const int nt = ng * 2 + jj, hf = jj * 2;
                        mma16816(acc[mt][nt], ah[mt], &bh[hf]);
                        mma16816(acc[mt][nt], ah[mt], &bl[hf]);
                        mma16816(acc[mt][nt], al[mt], &bh[hf]);
                    }
            }
        }
        __syncthreads();
    }

    const int g = lane >> 2, tg = lane & 3;
    #pragma unroll
    for (int mt = 0; mt < 2; mt++)
        #pragma unroll
        for (int nt = 0; nt < 8; nt++) {
            const int row = m0 + wm * 32 + mt * 16 + g;
            const int col = n0 + wn * 64 + nt * 8 + tg * 2;
            *(float2*)&C[(size_t)row * N + col] =
                make_float2(acc[mt][nt][0], acc[mt][nt][1]);
            *(float2*)&C[(size_t)(row + 8) * N + col] =
                make_float2(acc[mt][nt][2], acc[mt][nt][3]);
        }
}

// ---------------- RoPE (strided view) ---------------------------------------
__global__ void rope2(float* __restrict__ x, int width, int stride) {
    const int pairsPerRow = width >> 1;
    int idx = blockIdx.x * blockDim.x + threadIdx.x;
    int total = MTOT * pairsPerRow;
    if (idx >= total) return;
    int row = idx / pairsPerRow;
    int p   = idx - row * pairsPerRow;
    int n   = row & (SEQ - 1);
    int i   = p & 31;
    float freq = expf(-(float)i * (9.2103403719761836f / 32.0f));
    float ph = (float)n * freq;
    float sn, cs;
    sincosf(ph, &sn, &cs);
    float* base = x + (size_t)row * stride + 2 * p;
    float x0 = base[0], x1 = base[1];
    base[0] = x0 * cs - x1 * sn;
    base[1] = x0 * sn + x1 * cs;
}

// ---------------- tensor-core flash attention --------------------------------
// block = 128 thr (4 warps), tile = 64 queries x 64 dim, key tiles of 64.
// smem: Qh Ql Kh Kl Vh Vl, each 64 rows x 144B stride (K-style layout for V;
// V^T fragments come from ldmatrix.trans).
#define SR 144
#define TSZ (64 * SR)            // 9216
#define FLASH_SMEM (6 * TSZ)     // 55296

__global__ __launch_bounds__(128)
void flash_tc(const float* __restrict__ qkv,
              __nv_bfloat16* __restrict__ oh, __nv_bfloat16* __restrict__ ol) {
    extern __shared__ char sm[];
    const uint32_t sb = smem_u32(sm);
    const int tid = threadIdx.x, w = tid >> 5, lane = tid & 31;
    const int qt = blockIdx.x, h = blockIdx.y, b = blockIdx.z, kvh = h >> 2;
    const int q0 = qt * 64;
    const int oQh = 0, oQl = TSZ, oKh = 2*TSZ, oKl = 3*TSZ, oVh = 4*TSZ, oVl = 5*TSZ;

    // ---- load Q tile (scaled by 1/sqrt(hd)=0.125), split hi/lo ----
    {
        int r = tid >> 1, dh = (tid & 1) * 32;
        const float* src = qkv + ((size_t)(b * SEQ + q0 + r)) * QKVW + h * 64 + dh;
        #pragma unroll
        for (int j = 0; j < 8; j++) {
            float4 v = *(const float4*)(src + j * 4);
            v.x *= 0.125f; v.y *= 0.125f; v.z *= 0.125f; v.w *= 0.125f;
            uint32_t h01, l01, h23, l23;
            split2(v.x, v.y, h01, l01);
            split2(v.z, v.w, h23, l23);
            int off = r * SR + (dh + j * 4) * 2;
            *(uint2*)(sm + oQh + off) = make_uint2(h01, h23);
            *(uint2*)(sm + oQl + off) = make_uint2(l01, l23);
        }
    }
    __syncthreads();

    // Q A-fragments (per warp: rows w*16..w*16+15, 4 k-steps over d)
    uint32_t qah[4][4], qal[4][4];
    {
        int aRow = lane & 15;
        uint32_t aCol = (uint32_t)(lane >> 4) * 16;
        #pragma unroll
        for (int ks = 0; ks < 4; ks++) {
            uint32_t ad = sb + oQh + (uint32_t)(w * 16 + aRow) * SR + aCol + ks * 32;
            ldmx4(qah[ks], ad);
            ldmx4(qal[ks], ad + TSZ);
        }
    }

    const int bRow = ((lane & 16) >> 1) | (lane & 7);
    const uint32_t bCol = (uint32_t)((lane >> 3) & 1) * 16;
    // trans-ldmatrix lane->addr for V (B-frag of P@V): row = key, col-half = d
    const int vRow = lane & 15;
    const uint32_t vColb = (uint32_t)((lane & 16) >> 1) * 2;  // 0 or 16 bytes (d offset 0/8)
    const int g = lane >> 2, tg = lane & 3;

    float oacc[8][4];
    #pragma unroll
    for (int nt = 0; nt < 8; nt++)
        #pragma unroll
        for (int q = 0; q < 4; q++) oacc[nt][q] = 0.0f;
    float m0v = -INFINITY, m1v = -INFINITY, l0v = 0.0f, l1v = 0.0f;

    for (int kt = 0; kt <= qt; kt++) {
        __syncthreads();   // protect smem K/V from previous iteration's readers
        // ---- load K,V tile (both [key][d] layout, hi/lo split) ----
        {
            int r = tid >> 1, dh = (tid & 1) * 32;
            const float* ksrc = qkv + ((size_t)(b * SEQ + kt * 64 + r)) * QKVW
                                + DIM_ + kvh * 64 + dh;
            const float* vsrc = ksrc + KVD;
            #pragma unroll
            for (int j = 0; j < 8; j++) {
                int off = r * SR + (dh + j * 4) * 2;
                float4 kv = *(const float4*)(ksrc + j * 4);
                uint32_t h01, l01, h23, l23;
                split2(kv.x, kv.y, h01, l01);
                split2(kv.z, kv.w, h23, l23);
                *(uint2*)(sm + oKh + off) = make_uint2(h01, h23);
                *(uint2*)(sm + oKl + off) = make_uint2(l01, l23);

                float4 vv = *(const float4*)(vsrc + j * 4);
                split2(vv.x, vv.y, h01, l01);
                split2(vv.z, vv.w, h23, l23);
                *(uint2*)(sm + oVh + off) = make_uint2(h01, h23);
                *(uint2*)(sm + oVl + off) = make_uint2(l01, l23);
            }
        }
        __syncthreads();

        // ---- S = Q @ K^T (hi/lo 3-product) ----
        float sacc[8][4];
        #pragma unroll
        for (int nt = 0; nt < 8; nt++)
            #pragma unroll
            for (int q = 0; q < 4; q++) sacc[nt][q] = 0.0f;

        #pragma unroll
        for (int ks = 0; ks < 4; ks++) {
            #pragma unroll
            for (int ng = 0; ng < 4; ng++) {
                uint32_t kbh[4], kbl[4];
                uint32_t adr = sb + oKh + (uint32_t)(ng * 16 + bRow) * SR + bCol + ks * 32;
                ldmx4(kbh, adr);
                ldmx4(kbl, adr + TSZ);
                #pragma unroll
                for (int jj = 0; jj < 2; jj++) {
                    const int nt = ng * 2 + jj, hf = jj * 2;
                    mma16816(sacc[nt], qah[ks], &kbh[hf]);
                    mma16816(sacc[nt], qah[ks], &kbl[hf]);
                    mma16816(sacc[nt], qal[ks], &kbh[hf]);
                }
            }
        }

        // ---- causal mask (diagonal tile only) ----
        if (kt == qt) {
            int r0 = w * 16 + g, r1 = r0 + 8;
            #pragma unroll
            for (int nt = 0; nt < 8; nt++) {
                int c0 = nt * 8 + tg * 2;
                if (c0     > r0) sacc[nt][0] = -1e30f;
                if (c0 + 1 > r0) sacc[nt][1] = -1e30f;
                if (c0     > r1) sacc[nt][2] = -1e30f;
                if (c0 + 1 > r1) sacc[nt][3] = -1e30f;
            }
        }

        // ---- online softmax ----
        float mx0 = -INFINITY, mx1 = -INFINITY;
        #pragma unroll
        for (int nt = 0; nt < 8; nt++) {
            mx0 = fmaxf(mx0, fmaxf(sacc[nt][0], sacc[nt][1]));
            mx1 = fmaxf(mx1, fmaxf(sacc[nt][2], sacc[nt][3]));
        }
        mx0 = fmaxf(mx0, __shfl_xor_sync(0xffffffffu, mx0, 1));
        mx0 = fmaxf(mx0, __shfl_xor_sync(0xffffffffu, mx0, 2));
        mx1 = fmaxf(mx1, __shfl_xor_sync(0xffffffffu, mx1, 1));
        mx1 = fmaxf(mx1, __shfl_xor_sync(0xffffffffu, mx1, 2));

        float mn0 = fmaxf(m0v, mx0), mn1 = fmaxf(m1v, mx1);
        float cr0 = __expf(m0v - mn0), cr1 = __expf(m1v - mn1);
        m0v = mn0; m1v = mn1;
        l0v *= cr0; l1v *= cr1;
        #pragma unroll
        for (int nt = 0; nt < 8; nt++) {
            oacc[nt][0] *= cr0; oacc[nt][1] *= cr0;
            oacc[nt][2] *= cr1; oacc[nt][3] *= cr1;
        }
        float rs0 = 0.0f, rs1 = 0.0f;

        // ---- P = exp(S-m); O += P @ V (hi/lo 3-product), fused per key-step ----
        #pragma unroll
        for (int ks = 0; ks < 4; ks++) {
            float p[2][4];
            #pragma unroll
            for (int jj = 0; jj < 2; jj++) {
                const int nt = 2 * ks + jj;
                p[jj][0] = __expf(sacc[nt][0] - mn0);
                p[jj][1] = __expf(sacc[nt][1] - mn0);
                p[jj][2] = __expf(sacc[nt][2] - mn1);
                p[jj][3] = __expf(sacc[nt][3] - mn1);
                rs0 += p[jj][0] + p[jj][1];
                rs1 += p[jj][2] + p[jj][3];
            }
            uint32_t pah[4], pal[4];
            split2(p[0][0], p[0][1], pah[0], pal[0]);
            split2(p[0][2], p[0][3], pah[1], pal[1]);
            split2(p[1][0], p[1][1], pah[2], pal[2]);
            split2(p[1][2], p[1][3], pah[3], pal[3]);

            #pragma unroll
            for (int ng = 0; ng < 4; ng++) {
                uint32_t vbh[4], vbl[4];
                uint32_t adr = sb + oVh + (uint32_t)(ks * 16 + vRow) * SR
                               + (uint32_t)ng * 32 + vColb;
                ldmx4t(vbh, adr);
                ldmx4t(vbl, adr + TSZ);
                #pragma unroll
                for (int jj = 0; jj < 2; jj++) {
                    const int nt = ng * 2 + jj, hf = jj * 2;
                    mma16816(oacc[nt], pah, &vbh[hf]);
                    mma16816(oacc[nt], pah, &vbl[hf]);
                    mma16816(oacc[nt], pal, &vbh[hf]);
                }
            }
        }
        rs0 += __shfl_xor_sync(0xffffffffu, rs0, 1);
        rs0 += __shfl_xor_sync(0xffffffffu, rs0, 2);
        rs1 += __shfl_xor_sync(0xffffffffu, rs1, 1);
        rs1 += __shfl_xor_sync(0xffffffffu, rs1, 2);
        l0v += rs0; l1v += rs1;
    }

    // ---- epilogue: normalize, split to bf16 hi/lo, store ----
    const float i0 = 1.0f / l0v, i1 = 1.0f / l1v;
    const int r0 = q0 + w * 16 + g;
    #pragma unroll
    for (int nt = 0; nt < 8; nt++) {
        const int col = h * 64 + nt * 8 + tg * 2;
        const size_t o0 = ((size_t)(b * SEQ + r0)) * DIM_ + col;
        const size_t o1 = o0 + (size_t)8 * DIM_;
        uint32_t H, L;
        split2(oacc[nt][0] * i0, oacc[nt][1] * i0, H, L);
        *(uint32_t*)&oh[o0] = H;
        *(uint32_t*)&ol[o0] = L;
        split2(oacc[nt][2] * i1, oacc[nt][3] * i1, H, L);
        *(uint32_t*)&oh[o1] = H;
        *(uint32_t*)&ol[o1] = L;
    }
}

// ---------------------------------------------------------------------------
extern "C" void kernel_launch(void* const* d_in, const int* in_sizes, int n_in,
                              void* d_out, int out_size) {
    const float* x  = (const float*)d_in[0];
    const float* wq = (const float*)d_in[1];
    const float* wk = (const float*)d_in[2];
    const float* wv = (const float*)d_in[3];
    const float* wo = (const float*)d_in[4];
    float* out = (float*)d_out;

    float* qkv;
    cudaGetSymbolAddress((void**)&qkv, g_qkv);
    __nv_bfloat16 *xh, *xl, *ah, *al, *wh, *wl, *woh, *wol;
    cudaGetSymbolAddress((void**)&xh,  g_xh);  cudaGetSymbolAddress((void**)&xl,  g_xl);
    cudaGetSymbolAddress((void**)&ah,  g_ah);  cudaGetSymbolAddress((void**)&al,  g_al);
    cudaGetSymbolAddress((void**)&wh,  g_wh);  cudaGetSymbolAddress((void**)&wl,  g_wl);
    cudaGetSymbolAddress((void**)&woh, g_woh); cudaGetSymbolAddress((void**)&wol, g_wol);

    cudaFuncSetAttribute(mma_gemm, cudaFuncAttributeMaxDynamicSharedMemorySize, GEMM_SMEM);
    cudaFuncSetAttribute(flash_tc, cudaFuncAttributeMaxDynamicSharedMemorySize, FLASH_SMEM);

    const int M = MTOT;

    // ---- convert input + weights (fused transposed weight buffer) ----
    {
        int n = M * DIM_;
        split_bf16<<<(n + 255) / 256, 256>>>(x, xh, xl, n);
        dim3 blk(32, 8);
        transpose_split<<<dim3(DIM_ / 32, DIM_ / 32), blk>>>(
            wq, wh, wl, DIM_, DIM_);
        transpose_split<<<dim3(KVD / 32, DIM_ / 32), blk>>>(
            wk, wh + (size_t)DIM_ * DIM_, wl + (size_t)DIM_ * DIM_, DIM_, KVD);
        transpose_split<<<dim3(KVD / 32, DIM_ / 32), blk>>>(
            wv, wh + (size_t)(DIM_ + KVD) * DIM_, wl + (size_t)(DIM_ + KVD) * DIM_, DIM_, KVD);
        transpose_split<<<dim3(DIM_ / 32, DIM_ / 32), blk>>>(
            wo, woh, wol, DIM_, DIM_);
    }

    // ---- fused QKV projection ----
    mma_gemm<<<dim3(QKVW / 128, M / 128), 256, GEMM_SMEM>>>(xh, xl, wh, wl, qkv, QKVW, DIM_);

    // ---- RoPE on q and k sections ----
    rope2<<<(M * (DIM_ / 2) + 255) / 256, 256>>>(qkv, DIM_, QKVW);
    rope2<<<(M * (KVD  / 2) + 255) / 256, 256>>>(qkv + DIM_, KVD, QKVW);

    // ---- tensor-core causal GQA flash attention (writes bf16 hi/lo) ----
    flash_tc<<<dim3(SEQ / 64, NH, B_), 128, FLASH_SMEM>>>(qkv, ah, al);

    // ---- output projection ----
    mma_gemm<<<dim3(DIM_ / 128, M / 128), 256, GEMM_SMEM>>>(ah, al, woh, wol, out, DIM_, DIM_);
}

// round 9
// speedup vs baseline: 1.2358x; 1.1624x over previous
#include <cuda_runtime.h>
#include <cuda_bf16.h>
#include <math.h>
#include <stdint.h>

#define B_   2
#define SEQ  1024
#define DIM_ 2048
#define KVD  512
#define NH   32
#define NKV  8
#define HD   64
#define MTOT (B_ * SEQ)   // 2048
#define QKVW 3072         // fused q|k|v width
#define NQT  (SEQ / 64)   // 16 q-tiles

// ---------------- scratch (__device__ globals; allocation-guard safe) ------
__device__ float g_qkv[MTOT * QKVW];
__device__ __nv_bfloat16 g_xh[MTOT * DIM_], g_xl[MTOT * DIM_];
__device__ __nv_bfloat16 g_ah[MTOT * DIM_], g_al[MTOT * DIM_];
// fused transposed weights [3072][2048]: rows 0-2047 = wq^T, 2048-2559 = wk^T, 2560-3071 = wv^T
__device__ __nv_bfloat16 g_wh[QKVW * DIM_], g_wl[QKVW * DIM_];
__device__ __nv_bfloat16 g_woh[DIM_ * DIM_], g_wol[DIM_ * DIM_];

// ---------------- helpers ---------------------------------------------------
__device__ __forceinline__ uint32_t smem_u32(const void* p) {
    uint32_t a;
    asm("{ .reg .u64 t; cvta.to.shared.u64 t, %1; cvt.u32.u64 %0, t; }"
        : "=r"(a) : "l"(p));
    return a;
}
__device__ __forceinline__ void cp16(uint32_t dst, const void* src) {
    uint64_t g = __cvta_generic_to_global(src);
    asm volatile("cp.async.cg.shared.global [%0], [%1], 16;" :: "r"(dst), "l"(g));
}
__device__ __forceinline__ void ldmx4(uint32_t* r, uint32_t addr) {
    asm volatile("ldmatrix.sync.aligned.m8n8.x4.shared.b16 {%0,%1,%2,%3}, [%4];"
                 : "=r"(r[0]), "=r"(r[1]), "=r"(r[2]), "=r"(r[3]) : "r"(addr));
}
__device__ __forceinline__ void ldmx4t(uint32_t* r, uint32_t addr) {
    asm volatile("ldmatrix.sync.aligned.m8n8.x4.trans.shared.b16 {%0,%1,%2,%3}, [%4];"
                 : "=r"(r[0]), "=r"(r[1]), "=r"(r[2]), "=r"(r[3]) : "r"(addr));
}
__device__ __forceinline__ void mma16816(float* c, const uint32_t* a, const uint32_t* b) {
    asm volatile(
        "mma.sync.aligned.m16n8k16.row.col.f32.bf16.bf16.f32 "
        "{%0,%1,%2,%3}, {%4,%5,%6,%7}, {%8,%9}, {%0,%1,%2,%3};"
        : "+f"(c[0]), "+f"(c[1]), "+f"(c[2]), "+f"(c[3])
        : "r"(a[0]), "r"(a[1]), "r"(a[2]), "r"(a[3]), "r"(b[0]), "r"(b[1]));
}
// split pair (a,b) into packed bf16x2 hi and lo words
__device__ __forceinline__ void split2(float a, float b, uint32_t& hi, uint32_t& lo) {
    __nv_bfloat16 ha = __float2bfloat16(a), hb = __float2bfloat16(b);
    __nv_bfloat16 la = __float2bfloat16(a - __bfloat162float(ha));
    __nv_bfloat16 lb = __float2bfloat16(b - __bfloat162float(hb));
    __nv_bfloat162 th; th.x = ha; th.y = hb;
    __nv_bfloat162 tl; tl.x = la; tl.y = lb;
    hi = *reinterpret_cast<uint32_t*>(&th);
    lo = *reinterpret_cast<uint32_t*>(&tl);
}

// ---------------- conversion kernels ---------------------------------------
__global__ void split_bf16(const float* __restrict__ src,
                           __nv_bfloat16* __restrict__ hi,
                           __nv_bfloat16* __restrict__ lo, int n) {
    int i = blockIdx.x * blockDim.x + threadIdx.x;
    if (i >= n) return;
    float v = src[i];
    __nv_bfloat16 h = __float2bfloat16(v);
    hi[i] = h;
    lo[i] = __float2bfloat16(v - __bfloat162float(h));
}

// All 4 weights in ONE launch. K = 2048 rows for every weight.
// blockIdx.x segments: [0,64) wq | [64,80) wk | [80,96) wv | [96,160) wo
__global__ void transpose_all(const float* __restrict__ wq, const float* __restrict__ wk,
                              const float* __restrict__ wv, const float* __restrict__ wo,
                              __nv_bfloat16* __restrict__ wh, __nv_bfloat16* __restrict__ wl,
                              __nv_bfloat16* __restrict__ woh, __nv_bfloat16* __restrict__ wol) {
    __shared__ float t[32][33];
    const int bx = blockIdx.x;
    const float* W; __nv_bfloat16 *hi, *lo; int N, nb;
    if (bx < 64)       { W = wq; hi = wh;  lo = wl;  N = DIM_; nb = bx; }
    else if (bx < 80)  { W = wk; hi = wh  + (size_t)DIM_ * DIM_;
                         lo = wl + (size_t)DIM_ * DIM_;            N = KVD;  nb = bx - 64; }
    else if (bx < 96)  { W = wv; hi = wh  + (size_t)(DIM_ + KVD) * DIM_;
                         lo = wl + (size_t)(DIM_ + KVD) * DIM_;    N = KVD;  nb = bx - 80; }
    else               { W = wo; hi = woh; lo = wol; N = DIM_; nb = bx - 96; }

    const int k0 = blockIdx.y * 32, n0 = nb * 32;
    const int tx = threadIdx.x, ty = threadIdx.y;   // 32 x 8
    #pragma unroll
    for (int r = ty; r < 32; r += 8)
        t[r][tx] = W[(size_t)(k0 + r) * N + n0 + tx];
    __syncthreads();
    #pragma unroll
    for (int r = ty; r < 32; r += 8) {
        float v = t[tx][r];   // W[k0+tx][n0+r]
        __nv_bfloat16 h = __float2bfloat16(v);
        size_t o = (size_t)(n0 + r) * DIM_ + k0 + tx;
        hi[o] = h;
        lo[o] = __float2bfloat16(v - __bfloat162float(h));
    }
}

// ---------------- mma.sync bf16 GEMM, 4-stage, single-barrier chunks --------
#define ROWB       80
#define TILE_B     (128 * ROWB)          // 10240 bytes per operand tile
#define STAGE_B    (4 * TILE_B)          // 40960 (Ah, Al, Bh, Bl)
#define NSTAGE     4
#define GEMM_SMEM  (NSTAGE * STAGE_B)    // 163840

__global__ __launch_bounds__(256)
void mma_gemm(const __nv_bfloat16* __restrict__ Ah, const __nv_bfloat16* __restrict__ Al,
              const __nv_bfloat16* __restrict__ Bh, const __nv_bfloat16* __restrict__ Bl,
              float* __restrict__ C, int N, int K) {
    extern __shared__ char sm[];
    const uint32_t sbase = smem_u32(sm);
    const int tid  = threadIdx.x;
    const int wid  = tid >> 5;
    const int lane = tid & 31;
    const int wm = wid & 3;
    const int wn = wid >> 2;
    const int m0 = blockIdx.y * 128, n0 = blockIdx.x * 128;

    float acc[2][8][4];
    #pragma unroll
    for (int i = 0; i < 2; i++)
        #pragma unroll
        for (int j = 0; j < 8; j++)
            #pragma unroll
            for (int q = 0; q < 4; q++) acc[i][j][q] = 0.0f;

    const __nv_bfloat16* base[4] = {
        Ah + (size_t)m0 * K, Al + (size_t)m0 * K,
        Bh + (size_t)n0 * K, Bl + (size_t)n0 * K };

    const int r0 = tid >> 2, c0 = tid & 3;
    const int r1 = (tid + 256) >> 2, c1 = tid & 3;

    auto load_stage = [&](int cidx) {
        const int k0 = cidx << 5;
        const uint32_t db = sbase + (uint32_t)(cidx & (NSTAGE - 1)) * STAGE_B;
        #pragma unroll
        for (int t = 0; t < 4; t++) {
            const uint32_t tb = db + t * TILE_B;
            cp16(tb + r0 * ROWB + c0 * 16, base[t] + (size_t)r0 * K + k0 + c0 * 8);
            cp16(tb + r1 * ROWB + c1 * 16, base[t] + (size_t)r1 * K + k0 + c1 * 8);
        }
        asm volatile("cp.async.commit_group;");
    };

    const int aRow  = lane & 15;
    const uint32_t aColb = (uint32_t)(lane >> 4) * 16;
    const int bRow  = ((lane & 16) >> 1) + (lane & 7);
    const uint32_t bColb = (uint32_t)((lane >> 3) & 1) * 16;

    const int NC = K >> 5;
    load_stage(0);
    load_stage(1);

    for (int c = 0; c < NC; c++) {
        if (c + 2 < NC) load_stage(c + 2);
        else            asm volatile("cp.async.commit_group;");
        asm volatile("cp.async.wait_group 2;");
        __syncthreads();   // single barrier: stage (c+2)%4 written next iter was
                           // last read at iter c-2, fenced by two such barriers.

        const uint32_t db = sbase + (uint32_t)(c & (NSTAGE - 1)) * STAGE_B;
        #pragma unroll
        for (int ks = 0; ks < 2; ks++) {
            const uint32_t kb = (uint32_t)ks * 32;
            uint32_t ah[2][4], al[2][4];
            #pragma unroll
            for (int mt = 0; mt < 2; mt++) {
                uint32_t addr = db + (uint32_t)(wm * 32 + mt * 16 + aRow) * ROWB + aColb + kb;
                ldmx4(ah[mt], addr);
                ldmx4(al[mt], addr + TILE_B);
            }
            #pragma unroll
            for (int ng = 0; ng < 4; ng++) {
                uint32_t bh[4], bl[4];
                uint32_t addr = db + 2 * TILE_B +
                                (uint32_t)(wn * 64 + ng * 16 + bRow) * ROWB + bColb + kb;
                ldmx4(bh, addr);
                ldmx4(bl, addr + TILE_B);
                #pragma unroll
                for (int mt = 0; mt < 2; mt++)
                    #pragma unroll
                    for (int jj = 0; jj < 2; jj++) {
                        const int nt = ng * 2 + jj, hf = jj * 2;
                        mma16816(acc[mt][nt], ah[mt], &bh[hf]);
                        mma16816(acc[mt][nt], ah[mt], &bl[hf]);
                        mma16816(acc[mt][nt], al[mt], &bh[hf]);
                    }
            }
        }
    }

    const int g = lane >> 2, tg = lane & 3;
    #pragma unroll
    for (int mt = 0; mt < 2; mt++)
        #pragma unroll
        for (int nt = 0; nt < 8; nt++) {
            const int row = m0 + wm * 32 + mt * 16 + g;
            const int col = n0 + wn * 64 + nt * 8 + tg * 2;
            *(float2*)&C[(size_t)row * N + col] =
                make_float2(acc[mt][nt][0], acc[mt][nt][1]);
            *(float2*)&C[(size_t)(row + 8) * N + col] =
                make_float2(acc[mt][nt][2], acc[mt][nt][3]);
        }
}

// ---------------- fused RoPE (q + k sections, one launch) --------------------
// rows of 1280 pairs: p<1024 -> q (col 2p), else k (col 2048 + 2(p-1024))
__global__ void rope_all(float* __restrict__ qkv) {
    int idx = blockIdx.x * blockDim.x + threadIdx.x;
    const int PPR = (DIM_ + KVD) >> 1;   // 1280
    if (idx >= MTOT * PPR) return;
    int row = idx / PPR;
    int p   = idx - row * PPR;
    int col = (p < (DIM_ >> 1)) ? 2 * p : DIM_ + 2 * (p - (DIM_ >> 1));
    int n   = row & (SEQ - 1);
    int i   = p & 31;
    float freq = expf(-(float)i * (9.2103403719761836f / 32.0f));
    float ph = (float)n * freq;
    float sn, cs;
    sincosf(ph, &sn, &cs);
    float* base = qkv + (size_t)row * QKVW + col;
    float x0 = base[0], x1 = base[1];
    base[0] = x0 * cs - x1 * sn;
    base[1] = x0 * sn + x1 * cs;
}

// ---------------- tensor-core flash attention (paired q-tiles) ---------------
// grid (NQT/2, NH, B_): CTA x handles qt = x and qt = NQT-1-x (uniform 17 units).
#define SR 144
#define TSZ (64 * SR)            // 9216
#define FLASH_SMEM (6 * TSZ)     // 55296

__global__ __launch_bounds__(128)
void flash_tc(const float* __restrict__ qkv,
              __nv_bfloat16* __restrict__ oh, __nv_bfloat16* __restrict__ ol) {
    extern __shared__ char sm[];
    const uint32_t sb = smem_u32(sm);
    const int tid = threadIdx.x, w = tid >> 5, lane = tid & 31;
    const int h = blockIdx.y, b = blockIdx.z, kvh = h >> 2;
    const int oQh = 0, oQl = TSZ, oKh = 2*TSZ, oKl = 3*TSZ, oVh = 4*TSZ, oVl = 5*TSZ;

    const int bRow = ((lane & 16) >> 1) | (lane & 7);
    const uint32_t bCol = (uint32_t)((lane >> 3) & 1) * 16;
    const int vRow = lane & 15;
    const uint32_t vColb = (uint32_t)((lane & 16) >> 1) * 2;
    const int g = lane >> 2, tg = lane & 3;

    #pragma unroll 1
    for (int pass = 0; pass < 2; pass++) {
        const int qt = pass ? (NQT - 1 - (int)blockIdx.x) : (int)blockIdx.x;
        const int q0 = qt * 64;

        __syncthreads();   // all threads past previous pass's smem reads
        // ---- load Q tile (scaled by 0.125), split hi/lo ----
        {
            int r = tid >> 1, dh = (tid & 1) * 32;
            const float* src = qkv + ((size_t)(b * SEQ + q0 + r)) * QKVW + h * 64 + dh;
            #pragma unroll
            for (int j = 0; j < 8; j++) {
                float4 v = *(const float4*)(src + j * 4);
                v.x *= 0.125f; v.y *= 0.125f; v.z *= 0.125f; v.w *= 0.125f;
                uint32_t h01, l01, h23, l23;
                split2(v.x, v.y, h01, l01);
                split2(v.z, v.w, h23, l23);
                int off = r * SR + (dh + j * 4) * 2;
                *(uint2*)(sm + oQh + off) = make_uint2(h01, h23);
                *(uint2*)(sm + oQl + off) = make_uint2(l01, l23);
            }
        }
        __syncthreads();

        uint32_t qah[4][4], qal[4][4];
        {
            int aRow = lane & 15;
            uint32_t aCol = (uint32_t)(lane >> 4) * 16;
            #pragma unroll
            for (int ks = 0; ks < 4; ks++) {
                uint32_t ad = sb + oQh + (uint32_t)(w * 16 + aRow) * SR + aCol + ks * 32;
                ldmx4(qah[ks], ad);
                ldmx4(qal[ks], ad + TSZ);
            }
        }

        float oacc[8][4];
        #pragma unroll
        for (int nt = 0; nt < 8; nt++)
            #pragma unroll
            for (int q = 0; q < 4; q++) oacc[nt][q] = 0.0f;
        float m0v = -INFINITY, m1v = -INFINITY, l0v = 0.0f, l1v = 0.0f;

        for (int kt = 0; kt <= qt; kt++) {
            __syncthreads();
            // ---- load K,V tile ([key][d], hi/lo split) ----
            {
                int r = tid >> 1, dh = (tid & 1) * 32;
                const float* ksrc = qkv + ((size_t)(b * SEQ + kt * 64 + r)) * QKVW
                                    + DIM_ + kvh * 64 + dh;
                const float* vsrc = ksrc + KVD;
                #pragma unroll
                for (int j = 0; j < 8; j++) {
                    int off = r * SR + (dh + j * 4) * 2;
                    float4 kv = *(const float4*)(ksrc + j * 4);
                    uint32_t h01, l01, h23, l23;
                    split2(kv.x, kv.y, h01, l01);
                    split2(kv.z, kv.w, h23, l23);
                    *(uint2*)(sm + oKh + off) = make_uint2(h01, h23);
                    *(uint2*)(sm + oKl + off) = make_uint2(l01, l23);

                    float4 vv = *(const float4*)(vsrc + j * 4);
                    split2(vv.x, vv.y, h01, l01);
                    split2(vv.z, vv.w, h23, l23);
                    *(uint2*)(sm + oVh + off) = make_uint2(h01, h23);
                    *(uint2*)(sm + oVl + off) = make_uint2(l01, l23);
                }
            }
            __syncthreads();

            // ---- S = Q @ K^T ----
            float sacc[8][4];
            #pragma unroll
            for (int nt = 0; nt < 8; nt++)
                #pragma unroll
                for (int q = 0; q < 4; q++) sacc[nt][q] = 0.0f;

            #pragma unroll
            for (int ks = 0; ks < 4; ks++) {
                #pragma unroll
                for (int ng = 0; ng < 4; ng++) {
                    uint32_t kbh[4], kbl[4];
                    uint32_t adr = sb + oKh + (uint32_t)(ng * 16 + bRow) * SR + bCol + ks * 32;
                    ldmx4(kbh, adr);
                    ldmx4(kbl, adr + TSZ);
                    #pragma unroll
                    for (int jj = 0; jj < 2; jj++) {
                        const int nt = ng * 2 + jj, hf = jj * 2;
                        mma16816(sacc[nt], qah[ks], &kbh[hf]);
                        mma16816(sacc[nt], qah[ks], &kbl[hf]);
                        mma16816(sacc[nt], qal[ks], &kbh[hf]);
                    }
                }
            }

            // ---- causal mask on diagonal tile ----
            if (kt == qt) {
                int r0 = w * 16 + g, r1 = r0 + 8;
                #pragma unroll
                for (int nt = 0; nt < 8; nt++) {
                    int c0 = nt * 8 + tg * 2;
                    if (c0     > r0) sacc[nt][0] = -1e30f;
                    if (c0 + 1 > r0) sacc[nt][1] = -1e30f;
                    if (c0     > r1) sacc[nt][2] = -1e30f;
                    if (c0 + 1 > r1) sacc[nt][3] = -1e30f;
                }
            }

            // ---- online softmax ----
            float mx0 = -INFINITY, mx1 = -INFINITY;
            #pragma unroll
            for (int nt = 0; nt < 8; nt++) {
                mx0 = fmaxf(mx0, fmaxf(sacc[nt][0], sacc[nt][1]));
                mx1 = fmaxf(mx1, fmaxf(sacc[nt][2], sacc[nt][3]));
            }
            mx0 = fmaxf(mx0, __shfl_xor_sync(0xffffffffu, mx0, 1));
            mx0 = fmaxf(mx0, __shfl_xor_sync(0xffffffffu, mx0, 2));
            mx1 = fmaxf(mx1, __shfl_xor_sync(0xffffffffu, mx1, 1));
            mx1 = fmaxf(mx1, __shfl_xor_sync(0xffffffffu, mx1, 2));

            float mn0 = fmaxf(m0v, mx0), mn1 = fmaxf(m1v, mx1);
            float cr0 = __expf(m0v - mn0), cr1 = __expf(m1v - mn1);
            m0v = mn0; m1v = mn1;
            l0v *= cr0; l1v *= cr1;
            #pragma unroll
            for (int nt = 0; nt < 8; nt++) {
                oacc[nt][0] *= cr0; oacc[nt][1] *= cr0;
                oacc[nt][2] *= cr1; oacc[nt][3] *= cr1;
            }
            float rs0 = 0.0f, rs1 = 0.0f;

            // ---- P = exp(S-m); O += P @ V ----
            #pragma unroll
            for (int ks = 0; ks < 4; ks++) {
                float p[2][4];
                #pragma unroll
                for (int jj = 0; jj < 2; jj++) {
                    const int nt = 2 * ks + jj;
                    p[jj][0] = __expf(sacc[nt][0] - mn0);
                    p[jj][1] = __expf(sacc[nt][1] - mn0);
                    p[jj][2] = __expf(sacc[nt][2] - mn1);
                    p[jj][3] = __expf(sacc[nt][3] - mn1);
                    rs0 += p[jj][0] + p[jj][1];
                    rs1 += p[jj][2] + p[jj][3];
                }
                uint32_t pah[4], pal[4];
                split2(p[0][0], p[0][1], pah[0], pal[0]);
                split2(p[0][2], p[0][3], pah[1], pal[1]);
                split2(p[1][0], p[1][1], pah[2], pal[2]);
                split2(p[1][2], p[1][3], pah[3], pal[3]);

                #pragma unroll
                for (int ng = 0; ng < 4; ng++) {
                    uint32_t vbh[4], vbl[4];
                    uint32_t adr = sb + oVh + (uint32_t)(ks * 16 + vRow) * SR
                                   + (uint32_t)ng * 32 + vColb;
                    ldmx4t(vbh, adr);
                    ldmx4t(vbl, adr + TSZ);
                    #pragma unroll
                    for (int jj = 0; jj < 2; jj++) {
                        const int nt = ng * 2 + jj, hf = jj * 2;
                        mma16816(oacc[nt], pah, &vbh[hf]);
                        mma16816(oacc[nt], pah, &vbl[hf]);
                        mma16816(oacc[nt], pal, &vbh[hf]);
                    }
                }
            }
            rs0 += __shfl_xor_sync(0xffffffffu, rs0, 1);
            rs0 += __shfl_xor_sync(0xffffffffu, rs0, 2);
            rs1 += __shfl_xor_sync(0xffffffffu, rs1, 1);
            rs1 += __shfl_xor_sync(0xffffffffu, rs1, 2);
            l0v += rs0; l1v += rs1;
        }

        // ---- epilogue ----
        const float i0 = 1.0f / l0v, i1 = 1.0f / l1v;
        const int r0 = q0 + w * 16 + g;
        #pragma unroll
        for (int nt = 0; nt < 8; nt++) {
            const int col = h * 64 + nt * 8 + tg * 2;
            const size_t o0 = ((size_t)(b * SEQ + r0)) * DIM_ + col;
            const size_t o1 = o0 + (size_t)8 * DIM_;
            uint32_t H, L;
            split2(oacc[nt][0] * i0, oacc[nt][1] * i0, H, L);
            *(uint32_t*)&oh[o0] = H;
            *(uint32_t*)&ol[o0] = L;
            split2(oacc[nt][2] * i1, oacc[nt][3] * i1, H, L);
            *(uint32_t*)&oh[o1] = H;
            *(uint32_t*)&ol[o1] = L;
        }
    }
}

// ---------------------------------------------------------------------------
extern "C" void kernel_launch(void* const* d_in, const int* in_sizes, int n_in,
                              void* d_out, int out_size) {
    const float* x  = (const float*)d_in[0];
    const float* wq = (const float*)d_in[1];
    const float* wk = (const float*)d_in[2];
    const float* wv = (const float*)d_in[3];
    const float* wo = (const float*)d_in[4];
    float* out = (float*)d_out;

    float* qkv;
    cudaGetSymbolAddress((void**)&qkv, g_qkv);
    __nv_bfloat16 *xh, *xl, *ah, *al, *wh, *wl, *woh, *wol;
    cudaGetSymbolAddress((void**)&xh,  g_xh);  cudaGetSymbolAddress((void**)&xl,  g_xl);
    cudaGetSymbolAddress((void**)&ah,  g_ah);  cudaGetSymbolAddress((void**)&al,  g_al);
    cudaGetSymbolAddress((void**)&wh,  g_wh);  cudaGetSymbolAddress((void**)&wl,  g_wl);
    cudaGetSymbolAddress((void**)&woh, g_woh); cudaGetSymbolAddress((void**)&wol, g_wol);

    cudaFuncSetAttribute(mma_gemm, cudaFuncAttributeMaxDynamicSharedMemorySize, GEMM_SMEM);
    cudaFuncSetAttribute(flash_tc, cudaFuncAttributeMaxDynamicSharedMemorySize, FLASH_SMEM);

    const int M = MTOT;

    // 0: input split
    split_bf16<<<(M * DIM_ + 255) / 256, 256>>>(x, xh, xl, M * DIM_);
    // 1: all weights transposed+split in one launch
    transpose_all<<<dim3(160, 64), dim3(32, 8)>>>(wq, wk, wv, wo, wh, wl, woh, wol);
    // 2: fused QKV projection
    mma_gemm<<<dim3(QKVW / 128, M / 128), 256, GEMM_SMEM>>>(xh, xl, wh, wl, qkv, QKVW, DIM_);
    // 3: fused RoPE (q + k)
    rope_all<<<(M * ((DIM_ + KVD) / 2) + 255) / 256, 256>>>(qkv);
    // 4: paired-tile causal GQA flash attention
    flash_tc<<<dim3(NQT / 2, NH, B_), 128, FLASH_SMEM>>>(qkv, ah, al);
    // 5: output projection
    mma_gemm<<<dim3(DIM_ / 128, M / 128), 256, GEMM_SMEM>>>(ah, al, woh, wol, out, DIM_, DIM_);
}

// round 10
// speedup vs baseline: 1.6067x; 1.3002x over previous
#include <cuda_runtime.h>
#include <cuda_fp16.h>
#include <math.h>
#include <stdint.h>

#define B_   2
#define SEQ  1024
#define DIM_ 2048
#define KVD  512
#define NH   32
#define NKV  8
#define HD   64
#define MTOT (B_ * SEQ)   // 2048
#define QKVW 3072         // fused q|k|v width
#define NQT  (SEQ / 64)   // 16 q-tiles

// ---------------- scratch (__device__ globals; allocation-guard safe) ------
__device__ float g_qkv[MTOT * QKVW];
__device__ __half g_xh[MTOT * DIM_];          // fp16(x)
__device__ __half g_ah[MTOT * DIM_];          // fp16 attention output
// fused transposed weights [3072][2048] hi/lo fp16: wq^T | wk^T | wv^T
__device__ __half g_wh[QKVW * DIM_], g_wl[QKVW * DIM_];
__device__ __half g_woh[DIM_ * DIM_], g_wol[DIM_ * DIM_];

// ---------------- helpers ---------------------------------------------------
__device__ __forceinline__ uint32_t smem_u32(const void* p) {
    uint32_t a;
    asm("{ .reg .u64 t; cvta.to.shared.u64 t, %1; cvt.u32.u64 %0, t; }"
        : "=r"(a) : "l"(p));
    return a;
}
__device__ __forceinline__ void cp16(uint32_t dst, const void* src) {
    uint64_t g = __cvta_generic_to_global(src);
    asm volatile("cp.async.cg.shared.global [%0], [%1], 16;" :: "r"(dst), "l"(g));
}
__device__ __forceinline__ void ldmx4(uint32_t* r, uint32_t addr) {
    asm volatile("ldmatrix.sync.aligned.m8n8.x4.shared.b16 {%0,%1,%2,%3}, [%4];"
                 : "=r"(r[0]), "=r"(r[1]), "=r"(r[2]), "=r"(r[3]) : "r"(addr));
}
__device__ __forceinline__ void ldmx4t(uint32_t* r, uint32_t addr) {
    asm volatile("ldmatrix.sync.aligned.m8n8.x4.trans.shared.b16 {%0,%1,%2,%3}, [%4];"
                 : "=r"(r[0]), "=r"(r[1]), "=r"(r[2]), "=r"(r[3]) : "r"(addr));
}
__device__ __forceinline__ void mma16816(float* c, const uint32_t* a, const uint32_t* b) {
    asm volatile(
        "mma.sync.aligned.m16n8k16.row.col.f32.f16.f16.f32 "
        "{%0,%1,%2,%3}, {%4,%5,%6,%7}, {%8,%9}, {%0,%1,%2,%3};"
        : "+f"(c[0]), "+f"(c[1]), "+f"(c[2]), "+f"(c[3])
        : "r"(a[0]), "r"(a[1]), "r"(a[2]), "r"(a[3]), "r"(b[0]), "r"(b[1]));
}
// pack two floats into fp16x2 word
__device__ __forceinline__ uint32_t pack2h(float a, float b) {
    __half2 t = __floats2half2_rn(a, b);
    return *reinterpret_cast<uint32_t*>(&t);
}
// hi/lo fp16 split of pair
__device__ __forceinline__ void split2h(float a, float b, uint32_t& hi, uint32_t& lo) {
    __half ha = __float2half_rn(a), hb = __float2half_rn(b);
    __half la = __float2half_rn(a - __half2float(ha));
    __half lb = __float2half_rn(b - __half2float(hb));
    __half2 th; th.x = ha; th.y = hb;
    __half2 tl; tl.x = la; tl.y = lb;
    hi = *reinterpret_cast<uint32_t*>(&th);
    lo = *reinterpret_cast<uint32_t*>(&tl);
}

// ---------------- conversion kernels ---------------------------------------
__global__ void convert_x(const float* __restrict__ src, __half* __restrict__ dst, int n) {
    int i = blockIdx.x * blockDim.x + threadIdx.x;
    if (i >= n) return;
    dst[i] = __float2half_rn(src[i]);
}

// All 4 weights transposed + hi/lo split, ONE launch. K = 2048 for all.
// blockIdx.x segments: [0,64) wq | [64,80) wk | [80,96) wv | [96,160) wo
__global__ void transpose_all(const float* __restrict__ wq, const float* __restrict__ wk,
                              const float* __restrict__ wv, const float* __restrict__ wo,
                              __half* __restrict__ wh, __half* __restrict__ wl,
                              __half* __restrict__ woh, __half* __restrict__ wol) {
    __shared__ float t[32][33];
    const int bx = blockIdx.x;
    const float* W; __half *hi, *lo; int N, nb;
    if (bx < 64)       { W = wq; hi = wh;  lo = wl;  N = DIM_; nb = bx; }
    else if (bx < 80)  { W = wk; hi = wh + (size_t)DIM_ * DIM_;
                         lo = wl + (size_t)DIM_ * DIM_;            N = KVD;  nb = bx - 64; }
    else if (bx < 96)  { W = wv; hi = wh + (size_t)(DIM_ + KVD) * DIM_;
                         lo = wl + (size_t)(DIM_ + KVD) * DIM_;    N = KVD;  nb = bx - 80; }
    else               { W = wo; hi = woh; lo = wol; N = DIM_; nb = bx - 96; }

    const int k0 = blockIdx.y * 32, n0 = nb * 32;
    const int tx = threadIdx.x, ty = threadIdx.y;   // 32 x 8
    #pragma unroll
    for (int r = ty; r < 32; r += 8)
        t[r][tx] = W[(size_t)(k0 + r) * N + n0 + tx];
    __syncthreads();
    #pragma unroll
    for (int r = ty; r < 32; r += 8) {
        float v = t[tx][r];   // W[k0+tx][n0+r]
        __half h = __float2half_rn(v);
        size_t o = (size_t)(n0 + r) * DIM_ + k0 + tx;
        hi[o] = h;
        lo[o] = __float2half_rn(v - __half2float(h));
    }
}

// ---------------- mma.sync fp16 GEMM, 4-stage, 2-product --------------------
// C[M,N] = Ah[M,K] @ (Bh+Bl)^T, B stored [N,K] row-major.
// 128x128 tile, BK=32, 256 threads (8 warps: 32m x 64n each).
#define ROWB       80
#define TILE_B     (128 * ROWB)          // 10240 bytes per operand tile
#define STAGE_B    (3 * TILE_B)          // 30720 (Ah, Bh, Bl)
#define NSTAGE     4
#define GEMM_SMEM  (NSTAGE * STAGE_B)    // 122880

__global__ __launch_bounds__(256)
void mma_gemm(const __half* __restrict__ Ah,
              const __half* __restrict__ Bh, const __half* __restrict__ Bl,
              float* __restrict__ C, int N, int K) {
    extern __shared__ char sm[];
    const uint32_t sbase = smem_u32(sm);
    const int tid  = threadIdx.x;
    const int wid  = tid >> 5;
    const int lane = tid & 31;
    const int wm = wid & 3;
    const int wn = wid >> 2;
    const int m0 = blockIdx.y * 128, n0 = blockIdx.x * 128;

    float acc[2][8][4];
    #pragma unroll
    for (int i = 0; i < 2; i++)
        #pragma unroll
        for (int j = 0; j < 8; j++)
            #pragma unroll
            for (int q = 0; q < 4; q++) acc[i][j][q] = 0.0f;

    const __half* base[3] = {
        Ah + (size_t)m0 * K, Bh + (size_t)n0 * K, Bl + (size_t)n0 * K };

    const int r0 = tid >> 2, c0 = tid & 3;
    const int r1 = (tid + 256) >> 2, c1 = tid & 3;

    auto load_stage = [&](int cidx) {
        const int k0 = cidx << 5;
        const uint32_t db = sbase + (uint32_t)(cidx & (NSTAGE - 1)) * STAGE_B;
        #pragma unroll
        for (int t = 0; t < 3; t++) {
            const uint32_t tb = db + t * TILE_B;
            cp16(tb + r0 * ROWB + c0 * 16, base[t] + (size_t)r0 * K + k0 + c0 * 8);
            cp16(tb + r1 * ROWB + c1 * 16, base[t] + (size_t)r1 * K + k0 + c1 * 8);
        }
        asm volatile("cp.async.commit_group;");
    };

    const int aRow  = lane & 15;
    const uint32_t aColb = (uint32_t)(lane >> 4) * 16;
    const int bRow  = ((lane & 16) >> 1) + (lane & 7);
    const uint32_t bColb = (uint32_t)((lane >> 3) & 1) * 16;

    const int NC = K >> 5;
    load_stage(0);
    load_stage(1);

    for (int c = 0; c < NC; c++) {
        if (c + 2 < NC) load_stage(c + 2);
        else            asm volatile("cp.async.commit_group;");
        asm volatile("cp.async.wait_group 2;");
        __syncthreads();   // single barrier: stage reused only after 2 more barriers

        const uint32_t db = sbase + (uint32_t)(c & (NSTAGE - 1)) * STAGE_B;
        #pragma unroll
        for (int ks = 0; ks < 2; ks++) {
            const uint32_t kb = (uint32_t)ks * 32;
            uint32_t ah[2][4];
            #pragma unroll
            for (int mt = 0; mt < 2; mt++)
                ldmx4(ah[mt], db + (uint32_t)(wm * 32 + mt * 16 + aRow) * ROWB + aColb + kb);
            #pragma unroll
            for (int ng = 0; ng < 4; ng++) {
                uint32_t bh[4], bl[4];
                uint32_t addr = db + TILE_B +
                                (uint32_t)(wn * 64 + ng * 16 + bRow) * ROWB + bColb + kb;
                ldmx4(bh, addr);
                ldmx4(bl, addr + TILE_B);
                #pragma unroll
                for (int mt = 0; mt < 2; mt++)
                    #pragma unroll
                    for (int jj = 0; jj < 2; jj++) {
                        const int nt = ng * 2 + jj, hf = jj * 2;
                        mma16816(acc[mt][nt], ah[mt], &bh[hf]);
                        mma16816(acc[mt][nt], ah[mt], &bl[hf]);
                    }
            }
        }
    }

    const int g = lane >> 2, tg = lane & 3;
    #pragma unroll
    for (int mt = 0; mt < 2; mt++)
        #pragma unroll
        for (int nt = 0; nt < 8; nt++) {
            const int row = m0 + wm * 32 + mt * 16 + g;
            const int col = n0 + wn * 64 + nt * 8 + tg * 2;
            *(float2*)&C[(size_t)row * N + col] =
                make_float2(acc[mt][nt][0], acc[mt][nt][1]);
            *(float2*)&C[(size_t)(row + 8) * N + col] =
                make_float2(acc[mt][nt][2], acc[mt][nt][3]);
        }
}

// ---------------- fused RoPE (q + k sections, one launch) --------------------
__global__ void rope_all(float* __restrict__ qkv) {
    int idx = blockIdx.x * blockDim.x + threadIdx.x;
    const int PPR = (DIM_ + KVD) >> 1;   // 1280
    if (idx >= MTOT * PPR) return;
    int row = idx / PPR;
    int p   = idx - row * PPR;
    int col = (p < (DIM_ >> 1)) ? 2 * p : DIM_ + 2 * (p - (DIM_ >> 1));
    int n   = row & (SEQ - 1);
    int i   = p & 31;
    float freq = expf(-(float)i * (9.2103403719761836f / 32.0f));
    float ph = (float)n * freq;
    float sn, cs;
    sincosf(ph, &sn, &cs);
    float* base = qkv + (size_t)row * QKVW + col;
    float x0 = base[0], x1 = base[1];
    base[0] = x0 * cs - x1 * sn;
    base[1] = x0 * sn + x1 * cs;
}

// ---------------- tensor-core flash attention (fp16 2-product) ---------------
// grid (NQT/2, NH, B_): CTA x handles qt = x and qt = NQT-1-x (uniform load).
// smem tiles: Qh, Kh, Kl, Vh, Vl — 64 rows x 144B stride.
#define SR 144
#define TSZ (64 * SR)            // 9216
#define FLASH_SMEM (5 * TSZ)     // 46080

__global__ __launch_bounds__(128)
void flash_tc(const float* __restrict__ qkv, __half* __restrict__ oh) {
    extern __shared__ char sm[];
    const uint32_t sb = smem_u32(sm);
    const int tid = threadIdx.x, w = tid >> 5, lane = tid & 31;
    const int h = blockIdx.y, b = blockIdx.z, kvh = h >> 2;
    const int oQh = 0, oKh = TSZ, oKl = 2*TSZ, oVh = 3*TSZ, oVl = 4*TSZ;

    const int bRow = ((lane & 16) >> 1) | (lane & 7);
    const uint32_t bCol = (uint32_t)((lane >> 3) & 1) * 16;
    const int vRow = lane & 15;
    const uint32_t vColb = (uint32_t)((lane & 16) >> 1) * 2;
    const int g = lane >> 2, tg = lane & 3;

    #pragma unroll 1
    for (int pass = 0; pass < 2; pass++) {
        const int qt = pass ? (NQT - 1 - (int)blockIdx.x) : (int)blockIdx.x;
        const int q0 = qt * 64;

        __syncthreads();
        // ---- load Q tile (scaled 0.125) as fp16 hi only ----
        {
            int r = tid >> 1, dh = (tid & 1) * 32;
            const float* src = qkv + ((size_t)(b * SEQ + q0 + r)) * QKVW + h * 64 + dh;
            #pragma unroll
            for (int j = 0; j < 8; j++) {
                float4 v = *(const float4*)(src + j * 4);
                int off = r * SR + (dh + j * 4) * 2;
                *(uint2*)(sm + oQh + off) =
                    make_uint2(pack2h(v.x * 0.125f, v.y * 0.125f),
                               pack2h(v.z * 0.125f, v.w * 0.125f));
            }
        }
        __syncthreads();

        uint32_t qah[4][4];
        {
            int aRow = lane & 15;
            uint32_t aCol = (uint32_t)(lane >> 4) * 16;
            #pragma unroll
            for (int ks = 0; ks < 4; ks++)
                ldmx4(qah[ks], sb + oQh + (uint32_t)(w * 16 + aRow) * SR + aCol + ks * 32);
        }

        float oacc[8][4];
        #pragma unroll
        for (int nt = 0; nt < 8; nt++)
            #pragma unroll
            for (int q = 0; q < 4; q++) oacc[nt][q] = 0.0f;
        float m0v = -INFINITY, m1v = -INFINITY, l0v = 0.0f, l1v = 0.0f;

        for (int kt = 0; kt <= qt; kt++) {
            __syncthreads();
            // ---- load K (hi/lo) and V (hi/lo) tiles, [key][d] layout ----
            {
                int r = tid >> 1, dh = (tid & 1) * 32;
                const float* ksrc = qkv + ((size_t)(b * SEQ + kt * 64 + r)) * QKVW
                                    + DIM_ + kvh * 64 + dh;
                const float* vsrc = ksrc + KVD;
                #pragma unroll
                for (int j = 0; j < 8; j++) {
                    int off = r * SR + (dh + j * 4) * 2;
                    float4 kv = *(const float4*)(ksrc + j * 4);
                    uint32_t h01, l01, h23, l23;
                    split2h(kv.x, kv.y, h01, l01);
                    split2h(kv.z, kv.w, h23, l23);
                    *(uint2*)(sm + oKh + off) = make_uint2(h01, h23);
                    *(uint2*)(sm + oKl + off) = make_uint2(l01, l23);

                    float4 vv = *(const float4*)(vsrc + j * 4);
                    split2h(vv.x, vv.y, h01, l01);
                    split2h(vv.z, vv.w, h23, l23);
                    *(uint2*)(sm + oVh + off) = make_uint2(h01, h23);
                    *(uint2*)(sm + oVl + off) = make_uint2(l01, l23);
                }
            }
            __syncthreads();

            // ---- S = Qh @ (Kh+Kl)^T ----
            float sacc[8][4];
            #pragma unroll
            for (int nt = 0; nt < 8; nt++)
                #pragma unroll
                for (int q = 0; q < 4; q++) sacc[nt][q] = 0.0f;

            #pragma unroll
            for (int ks = 0; ks < 4; ks++) {
                #pragma unroll
                for (int ng = 0; ng < 4; ng++) {
                    uint32_t kbh[4], kbl[4];
                    uint32_t adr = sb + oKh + (uint32_t)(ng * 16 + bRow) * SR + bCol + ks * 32;
                    ldmx4(kbh, adr);
                    ldmx4(kbl, adr + TSZ);
                    #pragma unroll
                    for (int jj = 0; jj < 2; jj++) {
                        const int nt = ng * 2 + jj, hf = jj * 2;
                        mma16816(sacc[nt], qah[ks], &kbh[hf]);
                        mma16816(sacc[nt], qah[ks], &kbl[hf]);
                    }
                }
            }

            // ---- causal mask on diagonal tile ----
            if (kt == qt) {
                int r0 = w * 16 + g, r1 = r0 + 8;
                #pragma unroll
                for (int nt = 0; nt < 8; nt++) {
                    int c0 = nt * 8 + tg * 2;
                    if (c0     > r0) sacc[nt][0] = -1e30f;
                    if (c0 + 1 > r0) sacc[nt][1] = -1e30f;
                    if (c0     > r1) sacc[nt][2] = -1e30f;
                    if (c0 + 1 > r1) sacc[nt][3] = -1e30f;
                }
            }

            // ---- online softmax ----
            float mx0 = -INFINITY, mx1 = -INFINITY;
            #pragma unroll
            for (int nt = 0; nt < 8; nt++) {
                mx0 = fmaxf(mx0, fmaxf(sacc[nt][0], sacc[nt][1]));
                mx1 = fmaxf(mx1, fmaxf(sacc[nt][2], sacc[nt][3]));
            }
            mx0 = fmaxf(mx0, __shfl_xor_sync(0xffffffffu, mx0, 1));
            mx0 = fmaxf(mx0, __shfl_xor_sync(0xffffffffu, mx0, 2));
            mx1 = fmaxf(mx1, __shfl_xor_sync(0xffffffffu, mx1, 1));
            mx1 = fmaxf(mx1, __shfl_xor_sync(0xffffffffu, mx1, 2));

            float mn0 = fmaxf(m0v, mx0), mn1 = fmaxf(m1v, mx1);
            float cr0 = __expf(m0v - mn0), cr1 = __expf(m1v - mn1);
            m0v = mn0; m1v = mn1;
            l0v *= cr0; l1v *= cr1;
            #pragma unroll
            for (int nt = 0; nt < 8; nt++) {
                oacc[nt][0] *= cr0; oacc[nt][1] *= cr0;
                oacc[nt][2] *= cr1; oacc[nt][3] *= cr1;
            }
            float rs0 = 0.0f, rs1 = 0.0f;

            // ---- P = exp(S-m) (fp16); O += Ph @ (Vh+Vl) ----
            #pragma unroll
            for (int ks = 0; ks < 4; ks++) {
                float p[2][4];
                #pragma unroll
                for (int jj = 0; jj < 2; jj++) {
                    const int nt = 2 * ks + jj;
                    p[jj][0] = __expf(sacc[nt][0] - mn0);
                    p[jj][1] = __expf(sacc[nt][1] - mn0);
                    p[jj][2] = __expf(sacc[nt][2] - mn1);
                    p[jj][3] = __expf(sacc[nt][3] - mn1);
                    rs0 += p[jj][0] + p[jj][1];
                    rs1 += p[jj][2] + p[jj][3];
                }
                uint32_t pah[4];
                pah[0] = pack2h(p[0][0], p[0][1]);
                pah[1] = pack2h(p[0][2], p[0][3]);
                pah[2] = pack2h(p[1][0], p[1][1]);
                pah[3] = pack2h(p[1][2], p[1][3]);

                #pragma unroll
                for (int ng = 0; ng < 4; ng++) {
                    uint32_t vbh[4], vbl[4];
                    uint32_t adr = sb + oVh + (uint32_t)(ks * 16 + vRow) * SR
                                   + (uint32_t)ng * 32 + vColb;
                    ldmx4t(vbh, adr);
                    ldmx4t(vbl, adr + TSZ);
                    #pragma unroll
                    for (int jj = 0; jj < 2; jj++) {
                        const int nt = ng * 2 + jj, hf = jj * 2;
                        mma16816(oacc[nt], pah, &vbh[hf]);
                        mma16816(oacc[nt], pah, &vbl[hf]);
                    }
                }
            }
            rs0 += __shfl_xor_sync(0xffffffffu, rs0, 1);
            rs0 += __shfl_xor_sync(0xffffffffu, rs0, 2);
            rs1 += __shfl_xor_sync(0xffffffffu, rs1, 1);
            rs1 += __shfl_xor_sync(0xffffffffu, rs1, 2);
            l0v += rs0; l1v += rs1;
        }

        // ---- epilogue: normalize, fp16 convert, store ----
        const float i0 = 1.0f / l0v, i1 = 1.0f / l1v;
        const int r0 = q0 + w * 16 + g;
        #pragma unroll
        for (int nt = 0; nt < 8; nt++) {
            const int col = h * 64 + nt * 8 + tg * 2;
            const size_t o0 = ((size_t)(b * SEQ + r0)) * DIM_ + col;
            const size_t o1 = o0 + (size_t)8 * DIM_;
            *(uint32_t*)&oh[o0] = pack2h(oacc[nt][0] * i0, oacc[nt][1] * i0);
            *(uint32_t*)&oh[o1] = pack2h(oacc[nt][2] * i1, oacc[nt][3] * i1);
        }
    }
}

// ---------------------------------------------------------------------------
extern "C" void kernel_launch(void* const* d_in, const int* in_sizes, int n_in,
                              void* d_out, int out_size) {
    const float* x  = (const float*)d_in[0];
    const float* wq = (const float*)d_in[1];
    const float* wk = (const float*)d_in[2];
    const float* wv = (const float*)d_in[3];
    const float* wo = (const float*)d_in[4];
    float* out = (float*)d_out;

    float* qkv;
    cudaGetSymbolAddress((void**)&qkv, g_qkv);
    __half *xh, *ah, *wh, *wl, *woh, *wol;
    cudaGetSymbolAddress((void**)&xh,  g_xh);
    cudaGetSymbolAddress((void**)&ah,  g_ah);
    cudaGetSymbolAddress((void**)&wh,  g_wh);  cudaGetSymbolAddress((void**)&wl,  g_wl);
    cudaGetSymbolAddress((void**)&woh, g_woh); cudaGetSymbolAddress((void**)&wol, g_wol);

    cudaFuncSetAttribute(mma_gemm, cudaFuncAttributeMaxDynamicSharedMemorySize, GEMM_SMEM);
    cudaFuncSetAttribute(flash_tc, cudaFuncAttributeMaxDynamicSharedMemorySize, FLASH_SMEM);

    const int M = MTOT;

    // 0: x -> fp16
    convert_x<<<(M * DIM_ + 255) / 256, 256>>>(x, xh, M * DIM_);
    // 1: all weights transposed + hi/lo split
    transpose_all<<<dim3(160, 64), dim3(32, 8)>>>(wq, wk, wv, wo, wh, wl, woh, wol);
    // 2: fused QKV projection (2-product fp16)
    mma_gemm<<<dim3(QKVW / 128, M / 128), 256, GEMM_SMEM>>>(xh, wh, wl, qkv, QKVW, DIM_);
    // 3: fused RoPE (q + k)
    rope_all<<<(M * ((DIM_ + KVD) / 2) + 255) / 256, 256>>>(qkv);
    // 4: paired-tile causal GQA flash attention (fp16 2-product)
    flash_tc<<<dim3(NQT / 2, NH, B_), 128, FLASH_SMEM>>>(qkv, ah);
    // 5: output projection
    mma_gemm<<<dim3(DIM_ / 128, M / 128), 256, GEMM_SMEM>>>(ah, woh, wol, out, DIM_, DIM_);
}

// round 11
// speedup vs baseline: 1.8426x; 1.1468x over previous
#include <cuda_runtime.h>
#include <cuda_fp16.h>
#include <math.h>
#include <stdint.h>

#define B_   2
#define SEQ  1024
#define DIM_ 2048
#define KVD  512
#define NH   32
#define NKV  8
#define HD   64
#define MTOT (B_ * SEQ)   // 2048
#define QKVW 3072         // fused q|k|v width
#define NQT  (SEQ / 64)   // 16 q-tiles

// ---------------- scratch (__device__ globals; allocation-guard safe) ------
__device__ float g_qkv[MTOT * QKVW];
__device__ __half g_xh[MTOT * DIM_];          // fp16(x)
__device__ __half g_ah[MTOT * DIM_];          // fp16 attention output
__device__ __half g_qh[MTOT * DIM_];          // fp16 roped+scaled Q
__device__ __half g_kh[MTOT * KVD], g_kl[MTOT * KVD];   // roped K hi/lo
__device__ __half g_vh[MTOT * KVD], g_vl[MTOT * KVD];   // V hi/lo
// fused transposed weights [3072][2048] hi/lo fp16: wq^T | wk^T | wv^T
__device__ __half g_wh[QKVW * DIM_], g_wl[QKVW * DIM_];
__device__ __half g_woh[DIM_ * DIM_], g_wol[DIM_ * DIM_];

// ---------------- helpers ---------------------------------------------------
__device__ __forceinline__ uint32_t smem_u32(const void* p) {
    uint32_t a;
    asm("{ .reg .u64 t; cvta.to.shared.u64 t, %1; cvt.u32.u64 %0, t; }"
        : "=r"(a) : "l"(p));
    return a;
}
__device__ __forceinline__ void cp16(uint32_t dst, const void* src) {
    uint64_t g = __cvta_generic_to_global(src);
    asm volatile("cp.async.cg.shared.global [%0], [%1], 16;" :: "r"(dst), "l"(g));
}
__device__ __forceinline__ void ldmx4(uint32_t* r, uint32_t addr) {
    asm volatile("ldmatrix.sync.aligned.m8n8.x4.shared.b16 {%0,%1,%2,%3}, [%4];"
                 : "=r"(r[0]), "=r"(r[1]), "=r"(r[2]), "=r"(r[3]) : "r"(addr));
}
__device__ __forceinline__ void ldmx4t(uint32_t* r, uint32_t addr) {
    asm volatile("ldmatrix.sync.aligned.m8n8.x4.trans.shared.b16 {%0,%1,%2,%3}, [%4];"
                 : "=r"(r[0]), "=r"(r[1]), "=r"(r[2]), "=r"(r[3]) : "r"(addr));
}
__device__ __forceinline__ void mma16816(float* c, const uint32_t* a, const uint32_t* b) {
    asm volatile(
        "mma.sync.aligned.m16n8k16.row.col.f32.f16.f16.f32 "
        "{%0,%1,%2,%3}, {%4,%5,%6,%7}, {%8,%9}, {%0,%1,%2,%3};"
        : "+f"(c[0]), "+f"(c[1]), "+f"(c[2]), "+f"(c[3])
        : "r"(a[0]), "r"(a[1]), "r"(a[2]), "r"(a[3]), "r"(b[0]), "r"(b[1]));
}
__device__ __forceinline__ uint32_t pack2h(float a, float b) {
    __half2 t = __floats2half2_rn(a, b);
    return *reinterpret_cast<uint32_t*>(&t);
}
__device__ __forceinline__ void split2h(float a, float b, uint32_t& hi, uint32_t& lo) {
    __half ha = __float2half_rn(a), hb = __float2half_rn(b);
    __half la = __float2half_rn(a - __half2float(ha));
    __half lb = __float2half_rn(b - __half2float(hb));
    __half2 th; th.x = ha; th.y = hb;
    __half2 tl; tl.x = la; tl.y = lb;
    hi = *reinterpret_cast<uint32_t*>(&th);
    lo = *reinterpret_cast<uint32_t*>(&tl);
}

// ---------------- fused weight transpose + x conversion ----------------------
// bx in [0,160): weight transpose+split (as before); bx in [160,416): x->fp16.
__global__ void transpose_all(const float* __restrict__ wq, const float* __restrict__ wk,
                              const float* __restrict__ wv, const float* __restrict__ wo,
                              const float* __restrict__ x,  __half* __restrict__ xh,
                              __half* __restrict__ wh, __half* __restrict__ wl,
                              __half* __restrict__ woh, __half* __restrict__ wol) {
    const int bx = blockIdx.x;
    const int tx = threadIdx.x, ty = threadIdx.y;   // 32 x 8
    if (bx >= 160) {
        int idx = (((bx - 160) * gridDim.y + blockIdx.y) << 8) + (ty << 5) + tx;
        if (idx < MTOT * DIM_) xh[idx] = __float2half_rn(x[idx]);
        return;
    }
    __shared__ float t[32][33];
    const float* W; __half *hi, *lo; int N, nb;
    if (bx < 64)       { W = wq; hi = wh;  lo = wl;  N = DIM_; nb = bx; }
    else if (bx < 80)  { W = wk; hi = wh + (size_t)DIM_ * DIM_;
                         lo = wl + (size_t)DIM_ * DIM_;            N = KVD;  nb = bx - 64; }
    else if (bx < 96)  { W = wv; hi = wh + (size_t)(DIM_ + KVD) * DIM_;
                         lo = wl + (size_t)(DIM_ + KVD) * DIM_;    N = KVD;  nb = bx - 80; }
    else               { W = wo; hi = woh; lo = wol; N = DIM_; nb = bx - 96; }

    const int k0 = blockIdx.y * 32, n0 = nb * 32;
    #pragma unroll
    for (int r = ty; r < 32; r += 8)
        t[r][tx] = W[(size_t)(k0 + r) * N + n0 + tx];
    __syncthreads();
    #pragma unroll
    for (int r = ty; r < 32; r += 8) {
        float v = t[tx][r];
        __half h = __float2half_rn(v);
        size_t o = (size_t)(n0 + r) * DIM_ + k0 + tx;
        hi[o] = h;
        lo[o] = __float2half_rn(v - __half2float(h));
    }
}

// ---------------- mma.sync fp16 GEMM, 4-stage, 2-product --------------------
#define ROWB       80
#define TILE_B     (128 * ROWB)
#define STAGE_B    (3 * TILE_B)
#define NSTAGE     4
#define GEMM_SMEM  (NSTAGE * STAGE_B)    // 122880

__global__ __launch_bounds__(256)
void mma_gemm(const __half* __restrict__ Ah,
              const __half* __restrict__ Bh, const __half* __restrict__ Bl,
              float* __restrict__ C, int N, int K) {
    extern __shared__ char sm[];
    const uint32_t sbase = smem_u32(sm);
    const int tid  = threadIdx.x;
    const int wid  = tid >> 5;
    const int lane = tid & 31;
    const int wm = wid & 3;
    const int wn = wid >> 2;
    const int m0 = blockIdx.y * 128, n0 = blockIdx.x * 128;

    float acc[2][8][4];
    #pragma unroll
    for (int i = 0; i < 2; i++)
        #pragma unroll
        for (int j = 0; j < 8; j++)
            #pragma unroll
            for (int q = 0; q < 4; q++) acc[i][j][q] = 0.0f;

    const __half* base[3] = {
        Ah + (size_t)m0 * K, Bh + (size_t)n0 * K, Bl + (size_t)n0 * K };

    const int r0 = tid >> 2, c0 = tid & 3;
    const int r1 = (tid + 256) >> 2, c1 = tid & 3;

    auto load_stage = [&](int cidx) {
        const int k0 = cidx << 5;
        const uint32_t db = sbase + (uint32_t)(cidx & (NSTAGE - 1)) * STAGE_B;
        #pragma unroll
        for (int t = 0; t < 3; t++) {
            const uint32_t tb = db + t * TILE_B;
            cp16(tb + r0 * ROWB + c0 * 16, base[t] + (size_t)r0 * K + k0 + c0 * 8);
            cp16(tb + r1 * ROWB + c1 * 16, base[t] + (size_t)r1 * K + k0 + c1 * 8);
        }
        asm volatile("cp.async.commit_group;");
    };

    const int aRow  = lane & 15;
    const uint32_t aColb = (uint32_t)(lane >> 4) * 16;
    const int bRow  = ((lane & 16) >> 1) + (lane & 7);
    const uint32_t bColb = (uint32_t)((lane >> 3) & 1) * 16;

    const int NC = K >> 5;
    load_stage(0);
    load_stage(1);

    for (int c = 0; c < NC; c++) {
        if (c + 2 < NC) load_stage(c + 2);
        else            asm volatile("cp.async.commit_group;");
        asm volatile("cp.async.wait_group 2;");
        __syncthreads();

        const uint32_t db = sbase + (uint32_t)(c & (NSTAGE - 1)) * STAGE_B;
        #pragma unroll
        for (int ks = 0; ks < 2; ks++) {
            const uint32_t kb = (uint32_t)ks * 32;
            uint32_t ah[2][4];
            #pragma unroll
            for (int mt = 0; mt < 2; mt++)
                ldmx4(ah[mt], db + (uint32_t)(wm * 32 + mt * 16 + aRow) * ROWB + aColb + kb);
            #pragma unroll
            for (int ng = 0; ng < 4; ng++) {
                uint32_t bh[4], bl[4];
                uint32_t addr = db + TILE_B +
                                (uint32_t)(wn * 64 + ng * 16 + bRow) * ROWB + bColb + kb;
                ldmx4(bh, addr);
                ldmx4(bl, addr + TILE_B);
                #pragma unroll
                for (int mt = 0; mt < 2; mt++)
                    #pragma unroll
                    for (int jj = 0; jj < 2; jj++) {
                        const int nt = ng * 2 + jj, hf = jj * 2;
                        mma16816(acc[mt][nt], ah[mt], &bh[hf]);
                        mma16816(acc[mt][nt], ah[mt], &bl[hf]);
                    }
            }
        }
    }

    const int g = lane >> 2, tg = lane & 3;
    #pragma unroll
    for (int mt = 0; mt < 2; mt++)
        #pragma unroll
        for (int nt = 0; nt < 8; nt++) {
            const int row = m0 + wm * 32 + mt * 16 + g;
            const int col = n0 + wn * 64 + nt * 8 + tg * 2;
            *(float2*)&C[(size_t)row * N + col] =
                make_float2(acc[mt][nt][0], acc[mt][nt][1]);
            *(float2*)&C[(size_t)(row + 8) * N + col] =
                make_float2(acc[mt][nt][2], acc[mt][nt][3]);
        }
}

// ---------------- prep: rope + fp16 conversion (once) ------------------------
// per row: 1024 q pairs (rope, *0.125, fp16) | 256 k pairs (rope, hi/lo)
//          | 256 v pairs (hi/lo)
__global__ void prep_attn(const float* __restrict__ qkv,
                          __half* __restrict__ qh,
                          __half* __restrict__ kh, __half* __restrict__ kl,
                          __half* __restrict__ vh, __half* __restrict__ vl) {
    const int PPR = 1536;
    int idx = blockIdx.x * blockDim.x + threadIdx.x;
    if (idx >= MTOT * PPR) return;
    int row = idx / PPR;
    int p   = idx - row * PPR;
    int n   = row & (SEQ - 1);
    const float* src = qkv + (size_t)row * QKVW;

    if (p < 1024) {
        int i = p & 31;
        float freq = expf(-(float)i * (9.2103403719761836f / 32.0f));
        float ph = (float)n * freq, sn, cs;
        sincosf(ph, &sn, &cs);
        float x0 = src[2 * p], x1 = src[2 * p + 1];
        *(uint32_t*)&qh[(size_t)row * DIM_ + 2 * p] =
            pack2h((x0 * cs - x1 * sn) * 0.125f, (x0 * sn + x1 * cs) * 0.125f);
    } else if (p < 1280) {
        int i2 = p - 1024, i = i2 & 31;
        float freq = expf(-(float)i * (9.2103403719761836f / 32.0f));
        float ph = (float)n * freq, sn, cs;
        sincosf(ph, &sn, &cs);
        float x0 = src[DIM_ + 2 * i2], x1 = src[DIM_ + 2 * i2 + 1];
        float y0 = x0 * cs - x1 * sn, y1 = x0 * sn + x1 * cs;
        uint32_t H, L;
        split2h(y0, y1, H, L);
        *(uint32_t*)&kh[(size_t)row * KVD + 2 * i2] = H;
        *(uint32_t*)&kl[(size_t)row * KVD + 2 * i2] = L;
    } else {
        int i2 = p - 1280;
        float x0 = src[DIM_ + KVD + 2 * i2], x1 = src[DIM_ + KVD + 2 * i2 + 1];
        uint32_t H, L;
        split2h(x0, x1, H, L);
        *(uint32_t*)&vh[(size_t)row * KVD + 2 * i2] = H;
        *(uint32_t*)&vl[(size_t)row * KVD + 2 * i2] = L;
    }
}

// ---------------- flash v2: fp16 inputs, cp.async double-buffered K/V --------
// smem: Qh (1 tile) + 2 stages x {Kh, Kl, Vh, Vl}; each tile 64 x 144B.
#define SR 144
#define TSZ (64 * SR)             // 9216
#define FLASH_SMEM (9 * TSZ)      // 82944

__global__ __launch_bounds__(128)
void flash_tc(const __half* __restrict__ qh,
              const __half* __restrict__ kh, const __half* __restrict__ kl,
              const __half* __restrict__ vh, const __half* __restrict__ vl,
              __half* __restrict__ oh) {
    extern __shared__ char sm[];
    const uint32_t sb = smem_u32(sm);
    const int tid = threadIdx.x, w = tid >> 5, lane = tid & 31;
    const int h = blockIdx.y, b = blockIdx.z, kvh = h >> 2;

    const int bRow = ((lane & 16) >> 1) | (lane & 7);
    const uint32_t bCol = (uint32_t)((lane >> 3) & 1) * 16;
    const int vRow = lane & 15;
    const uint32_t vColb = (uint32_t)((lane & 16) >> 1) * 2;
    const int g = lane >> 2, tg = lane & 3;

    auto loadkv = [&](int kt, int s) {
        const uint32_t stg = sb + TSZ + (uint32_t)s * (4 * TSZ);
        const size_t rowbase = (size_t)(b * SEQ + kt * 64) * KVD + kvh * 64;
        #pragma unroll
        for (int u = 0; u < 16; u++) {
            int id = tid + u * 128;
            int c16 = id & 7, r = (id >> 3) & 63, t = id >> 9;
            const __half* src = (t == 0 ? kh : t == 1 ? kl : t == 2 ? vh : vl)
                                + rowbase + (size_t)r * KVD + c16 * 8;
            cp16(stg + (uint32_t)t * TSZ + (uint32_t)r * SR + (uint32_t)c16 * 16, src);
        }
        asm volatile("cp.async.commit_group;");
    };

    #pragma unroll 1
    for (int pass = 0; pass < 2; pass++) {
        const int qt = pass ? (NQT - 1 - (int)blockIdx.x) : (int)blockIdx.x;
        const int q0 = qt * 64;

        // ---- Q tile via cp.async (pre-roped, pre-scaled fp16) ----
        {
            const __half* src = qh + (size_t)(b * SEQ + q0) * DIM_ + h * 64;
            #pragma unroll
            for (int u = 0; u < 4; u++) {
                int id = tid + u * 128;
                int c16 = id & 7, r = id >> 3;
                cp16(sb + (uint32_t)r * SR + (uint32_t)c16 * 16,
                     src + (size_t)r * DIM_ + c16 * 8);
            }
            asm volatile("cp.async.commit_group;");
            asm volatile("cp.async.wait_group 0;");
            __syncthreads();
        }
        uint32_t qah[4][4];
        {
            int aRow = lane & 15;
            uint32_t aCol = (uint32_t)(lane >> 4) * 16;
            #pragma unroll
            for (int ks = 0; ks < 4; ks++)
                ldmx4(qah[ks], sb + (uint32_t)(w * 16 + aRow) * SR + aCol + ks * 32);
        }

        float oacc[8][4];
        #pragma unroll
        for (int nt = 0; nt < 8; nt++)
            #pragma unroll
            for (int q = 0; q < 4; q++) oacc[nt][q] = 0.0f;
        float m0v = -INFINITY, m1v = -INFINITY, l0v = 0.0f, l1v = 0.0f;

        loadkv(0, 0);
        for (int kt = 0; kt <= qt; kt++) {
            if (kt + 1 <= qt) loadkv(kt + 1, (kt + 1) & 1);
            else              asm volatile("cp.async.commit_group;");
            asm volatile("cp.async.wait_group 1;");
            __syncthreads();                       // stage kt visible to all warps

            const uint32_t stg = sb + TSZ + (uint32_t)(kt & 1) * (4 * TSZ);
            const uint32_t oKh = stg, oVh = stg + 2 * TSZ;

            // ---- S = Qh @ (Kh+Kl)^T ----
            float sacc[8][4];
            #pragma unroll
            for (int nt = 0; nt < 8; nt++)
                #pragma unroll
                for (int q = 0; q < 4; q++) sacc[nt][q] = 0.0f;

            #pragma unroll
            for (int ks = 0; ks < 4; ks++) {
                #pragma unroll
                for (int ng = 0; ng < 4; ng++) {
                    uint32_t kbh[4], kbl[4];
                    uint32_t adr = oKh + (uint32_t)(ng * 16 + bRow) * SR + bCol + ks * 32;
                    ldmx4(kbh, adr);
                    ldmx4(kbl, adr + TSZ);
                    #pragma unroll
                    for (int jj = 0; jj < 2; jj++) {
                        const int nt = ng * 2 + jj, hf = jj * 2;
                        mma16816(sacc[nt], qah[ks], &kbh[hf]);
                        mma16816(sacc[nt], qah[ks], &kbl[hf]);
                    }
                }
            }

            // ---- causal mask on diagonal tile ----
            if (kt == qt) {
                int r0 = w * 16 + g, r1 = r0 + 8;
                #pragma unroll
                for (int nt = 0; nt < 8; nt++) {
                    int c0 = nt * 8 + tg * 2;
                    if (c0     > r0) sacc[nt][0] = -1e30f;
                    if (c0 + 1 > r0) sacc[nt][1] = -1e30f;
                    if (c0     > r1) sacc[nt][2] = -1e30f;
                    if (c0 + 1 > r1) sacc[nt][3] = -1e30f;
                }
            }

            // ---- online softmax ----
            float mx0 = -INFINITY, mx1 = -INFINITY;
            #pragma unroll
            for (int nt = 0; nt < 8; nt++) {
                mx0 = fmaxf(mx0, fmaxf(sacc[nt][0], sacc[nt][1]));
                mx1 = fmaxf(mx1, fmaxf(sacc[nt][2], sacc[nt][3]));
            }
            mx0 = fmaxf(mx0, __shfl_xor_sync(0xffffffffu, mx0, 1));
            mx0 = fmaxf(mx0, __shfl_xor_sync(0xffffffffu, mx0, 2));
            mx1 = fmaxf(mx1, __shfl_xor_sync(0xffffffffu, mx1, 1));
            mx1 = fmaxf(mx1, __shfl_xor_sync(0xffffffffu, mx1, 2));

            float mn0 = fmaxf(m0v, mx0), mn1 = fmaxf(m1v, mx1);
            float cr0 = __expf(m0v - mn0), cr1 = __expf(m1v - mn1);
            m0v = mn0; m1v = mn1;
            l0v *= cr0; l1v *= cr1;
            #pragma unroll
            for (int nt = 0; nt < 8; nt++) {
                oacc[nt][0] *= cr0; oacc[nt][1] *= cr0;
                oacc[nt][2] *= cr1; oacc[nt][3] *= cr1;
            }
            float rs0 = 0.0f, rs1 = 0.0f;

            // ---- P = exp(S-m) (fp16); O += Ph @ (Vh+Vl) ----
            #pragma unroll
            for (int ks = 0; ks < 4; ks++) {
                float p[2][4];
                #pragma unroll
                for (int jj = 0; jj < 2; jj++) {
                    const int nt = 2 * ks + jj;
                    p[jj][0] = __expf(sacc[nt][0] - mn0);
                    p[jj][1] = __expf(sacc[nt][1] - mn0);
                    p[jj][2] = __expf(sacc[nt][2] - mn1);
                    p[jj][3] = __expf(sacc[nt][3] - mn1);
                    rs0 += p[jj][0] + p[jj][1];
                    rs1 += p[jj][2] + p[jj][3];
                }
                uint32_t pah[4];
                pah[0] = pack2h(p[0][0], p[0][1]);
                pah[1] = pack2h(p[0][2], p[0][3]);
                pah[2] = pack2h(p[1][0], p[1][1]);
                pah[3] = pack2h(p[1][2], p[1][3]);

                #pragma unroll
                for (int ng = 0; ng < 4; ng++) {
                    uint32_t vbh[4], vbl[4];
                    uint32_t adr = oVh + (uint32_t)(ks * 16 + vRow) * SR
                                   + (uint32_t)ng * 32 + vColb;
                    ldmx4t(vbh, adr);
                    ldmx4t(vbl, adr + TSZ);
                    #pragma unroll
                    for (int jj = 0; jj < 2; jj++) {
                        const int nt = ng * 2 + jj, hf = jj * 2;
                        mma16816(oacc[nt], pah, &vbh[hf]);
                        mma16816(oacc[nt], pah, &vbl[hf]);
                    }
                }
            }
            rs0 += __shfl_xor_sync(0xffffffffu, rs0, 1);
            rs0 += __shfl_xor_sync(0xffffffffu, rs0, 2);
            rs1 += __shfl_xor_sync(0xffffffffu, rs1, 1);
            rs1 += __shfl_xor_sync(0xffffffffu, rs1, 2);
            l0v += rs0; l1v += rs1;

            __syncthreads();   // all warps done with stage kt before it's overwritten
        }

        // ---- epilogue: normalize, fp16, store ----
        const float i0 = 1.0f / l0v, i1 = 1.0f / l1v;
        const int r0 = q0 + w * 16 + g;
        #pragma unroll
        for (int nt = 0; nt < 8; nt++) {
            const int col = h * 64 + nt * 8 + tg * 2;
            const size_t o0 = ((size_t)(b * SEQ + r0)) * DIM_ + col;
            const size_t o1 = o0 + (size_t)8 * DIM_;
            *(uint32_t*)&oh[o0] = pack2h(oacc[nt][0] * i0, oacc[nt][1] * i0);
            *(uint32_t*)&oh[o1] = pack2h(oacc[nt][2] * i1, oacc[nt][3] * i1);
        }
    }
}

// ---------------------------------------------------------------------------
extern "C" void kernel_launch(void* const* d_in, const int* in_sizes, int n_in,
                              void* d_out, int out_size) {
    const float* x  = (const float*)d_in[0];
    const float* wq = (const float*)d_in[1];
    const float* wk = (const float*)d_in[2];
    const float* wv = (const float*)d_in[3];
    const float* wo = (const float*)d_in[4];
    float* out = (float*)d_out;

    float* qkv;
    cudaGetSymbolAddress((void**)&qkv, g_qkv);
    __half *xh, *ah, *qh, *kh, *kl, *vh, *vl, *wh, *wl, *woh, *wol;
    cudaGetSymbolAddress((void**)&xh,  g_xh);
    cudaGetSymbolAddress((void**)&ah,  g_ah);
    cudaGetSymbolAddress((void**)&qh,  g_qh);
    cudaGetSymbolAddress((void**)&kh,  g_kh);  cudaGetSymbolAddress((void**)&kl,  g_kl);
    cudaGetSymbolAddress((void**)&vh,  g_vh);  cudaGetSymbolAddress((void**)&vl,  g_vl);
    cudaGetSymbolAddress((void**)&wh,  g_wh);  cudaGetSymbolAddress((void**)&wl,  g_wl);
    cudaGetSymbolAddress((void**)&woh, g_woh); cudaGetSymbolAddress((void**)&wol, g_wol);

    cudaFuncSetAttribute(mma_gemm, cudaFuncAttributeMaxDynamicSharedMemorySize, GEMM_SMEM);
    cudaFuncSetAttribute(flash_tc, cudaFuncAttributeMaxDynamicSharedMemorySize, FLASH_SMEM);

    const int M = MTOT;

    // 0: weights transpose+split AND x->fp16 (fused)
    transpose_all<<<dim3(416, 64), dim3(32, 8)>>>(wq, wk, wv, wo, x, xh,
                                                  wh, wl, woh, wol);
    // 1: fused QKV projection
    mma_gemm<<<dim3(QKVW / 128, M / 128), 256, GEMM_SMEM>>>(xh, wh, wl, qkv, QKVW, DIM_);
    // 2: rope + fp16 split (once)
    prep_attn<<<(M * 1536 + 255) / 256, 256>>>(qkv, qh, kh, kl, vh, vl);
    // 3: flash attention (profiled slot)
    flash_tc<<<dim3(NQT / 2, NH, B_), 128, FLASH_SMEM>>>(qh, kh, kl, vh, vl, ah);
    // 4: output projection
    mma_gemm<<<dim3(DIM_ / 128, M / 128), 256, GEMM_SMEM>>>(ah, woh, wol, out, DIM_, DIM_);
}

// round 12
// speedup vs baseline: 1.9049x; 1.0338x over previous
#include <cuda_runtime.h>
#include <cuda_fp16.h>
#include <math.h>
#include <stdint.h>

#define B_   2
#define SEQ  1024
#define DIM_ 2048
#define KVD  512
#define NH   32
#define NKV  8
#define HD   64
#define MTOT (B_ * SEQ)   // 2048
#define QKVW 3072         // fused q|k|v width
#define NQT  (SEQ / 64)   // 16 q-tiles

// ---------------- scratch (__device__ globals; allocation-guard safe) ------
__device__ float g_qkv[MTOT * QKVW];
__device__ __half g_xh[MTOT * DIM_];          // fp16(x)
__device__ __half g_ah[MTOT * DIM_];          // fp16 attention output
__device__ __half g_qh[MTOT * DIM_];          // fp16 roped+scaled Q
__device__ __half g_kh[MTOT * KVD], g_kl[MTOT * KVD];   // roped K hi/lo
__device__ __half g_vh[MTOT * KVD], g_vl[MTOT * KVD];   // V hi/lo
// fused transposed weights [3072][2048] hi/lo fp16: wq^T | wk^T | wv^T
__device__ __half g_wh[QKVW * DIM_], g_wl[QKVW * DIM_];
__device__ __half g_woh[DIM_ * DIM_], g_wol[DIM_ * DIM_];

// ---------------- helpers ---------------------------------------------------
__device__ __forceinline__ uint32_t smem_u32(const void* p) {
    uint32_t a;
    asm("{ .reg .u64 t; cvta.to.shared.u64 t, %1; cvt.u32.u64 %0, t; }"
        : "=r"(a) : "l"(p));
    return a;
}
__device__ __forceinline__ void cp16(uint32_t dst, const void* src) {
    uint64_t g = __cvta_generic_to_global(src);
    asm volatile("cp.async.cg.shared.global [%0], [%1], 16;" :: "r"(dst), "l"(g));
}
__device__ __forceinline__ void ldmx4(uint32_t* r, uint32_t addr) {
    asm volatile("ldmatrix.sync.aligned.m8n8.x4.shared.b16 {%0,%1,%2,%3}, [%4];"
                 : "=r"(r[0]), "=r"(r[1]), "=r"(r[2]), "=r"(r[3]) : "r"(addr));
}
__device__ __forceinline__ void ldmx4t(uint32_t* r, uint32_t addr) {
    asm volatile("ldmatrix.sync.aligned.m8n8.x4.trans.shared.b16 {%0,%1,%2,%3}, [%4];"
                 : "=r"(r[0]), "=r"(r[1]), "=r"(r[2]), "=r"(r[3]) : "r"(addr));
}
__device__ __forceinline__ void mma16816(float* c, const uint32_t* a, const uint32_t* b) {
    asm volatile(
        "mma.sync.aligned.m16n8k16.row.col.f32.f16.f16.f32 "
        "{%0,%1,%2,%3}, {%4,%5,%6,%7}, {%8,%9}, {%0,%1,%2,%3};"
        : "+f"(c[0]), "+f"(c[1]), "+f"(c[2]), "+f"(c[3])
        : "r"(a[0]), "r"(a[1]), "r"(a[2]), "r"(a[3]), "r"(b[0]), "r"(b[1]));
}
__device__ __forceinline__ uint32_t pack2h(float a, float b) {
    __half2 t = __floats2half2_rn(a, b);
    return *reinterpret_cast<uint32_t*>(&t);
}
__device__ __forceinline__ void split2h(float a, float b, uint32_t& hi, uint32_t& lo) {
    __half ha = __float2half_rn(a), hb = __float2half_rn(b);
    __half la = __float2half_rn(a - __half2float(ha));
    __half lb = __float2half_rn(b - __half2float(hb));
    __half2 th; th.x = ha; th.y = hb;
    __half2 tl; tl.x = la; tl.y = lb;
    hi = *reinterpret_cast<uint32_t*>(&th);
    lo = *reinterpret_cast<uint32_t*>(&tl);
}

// ---------------- fused weight transpose + x conversion ----------------------
__global__ void transpose_all(const float* __restrict__ wq, const float* __restrict__ wk,
                              const float* __restrict__ wv, const float* __restrict__ wo,
                              const float* __restrict__ x,  __half* __restrict__ xh,
                              __half* __restrict__ wh, __half* __restrict__ wl,
                              __half* __restrict__ woh, __half* __restrict__ wol) {
    const int bx = blockIdx.x;
    const int tx = threadIdx.x, ty = threadIdx.y;   // 32 x 8
    if (bx >= 160) {
        int idx = (((bx - 160) * gridDim.y + blockIdx.y) << 8) + (ty << 5) + tx;
        if (idx < MTOT * DIM_) xh[idx] = __float2half_rn(x[idx]);
        return;
    }
    __shared__ float t[32][33];
    const float* W; __half *hi, *lo; int N, nb;
    if (bx < 64)       { W = wq; hi = wh;  lo = wl;  N = DIM_; nb = bx; }
    else if (bx < 80)  { W = wk; hi = wh + (size_t)DIM_ * DIM_;
                         lo = wl + (size_t)DIM_ * DIM_;            N = KVD;  nb = bx - 64; }
    else if (bx < 96)  { W = wv; hi = wh + (size_t)(DIM_ + KVD) * DIM_;
                         lo = wl + (size_t)(DIM_ + KVD) * DIM_;    N = KVD;  nb = bx - 80; }
    else               { W = wo; hi = woh; lo = wol; N = DIM_; nb = bx - 96; }

    const int k0 = blockIdx.y * 32, n0 = nb * 32;
    #pragma unroll
    for (int r = ty; r < 32; r += 8)
        t[r][tx] = W[(size_t)(k0 + r) * N + n0 + tx];
    __syncthreads();
    #pragma unroll
    for (int r = ty; r < 32; r += 8) {
        float v = t[tx][r];
        __half h = __float2half_rn(v);
        size_t o = (size_t)(n0 + r) * DIM_ + k0 + tx;
        hi[o] = h;
        lo[o] = __float2half_rn(v - __half2float(h));
    }
}

// ---------------- mma.sync fp16 GEMM, 3-stage, 2 CTAs/SM --------------------
#define ROWB       80
#define TILE_B     (128 * ROWB)
#define STAGE_B    (3 * TILE_B)          // Ah, Bh, Bl
#define NSTAGE     3
#define GEMM_SMEM  (NSTAGE * STAGE_B)    // 92160 -> 2 CTAs/SM

__global__ __launch_bounds__(256, 2)
void mma_gemm(const __half* __restrict__ Ah,
              const __half* __restrict__ Bh, const __half* __restrict__ Bl,
              float* __restrict__ C, int N, int K) {
    extern __shared__ char sm[];
    const uint32_t sbase = smem_u32(sm);
    const int tid  = threadIdx.x;
    const int wid  = tid >> 5;
    const int lane = tid & 31;
    const int wm = wid & 3;
    const int wn = wid >> 2;
    const int m0 = blockIdx.y * 128, n0 = blockIdx.x * 128;

    float acc[2][8][4];
    #pragma unroll
    for (int i = 0; i < 2; i++)
        #pragma unroll
        for (int j = 0; j < 8; j++)
            #pragma unroll
            for (int q = 0; q < 4; q++) acc[i][j][q] = 0.0f;

    const __half* base[3] = {
        Ah + (size_t)m0 * K, Bh + (size_t)n0 * K, Bl + (size_t)n0 * K };

    const int r0 = tid >> 2, c0 = tid & 3;
    const int r1 = (tid + 256) >> 2, c1 = tid & 3;

    auto load_stage = [&](int cidx) {
        const int k0 = cidx << 5;
        const uint32_t db = sbase + (uint32_t)(cidx % NSTAGE) * STAGE_B;
        #pragma unroll
        for (int t = 0; t < 3; t++) {
            const uint32_t tb = db + t * TILE_B;
            cp16(tb + r0 * ROWB + c0 * 16, base[t] + (size_t)r0 * K + k0 + c0 * 8);
            cp16(tb + r1 * ROWB + c1 * 16, base[t] + (size_t)r1 * K + k0 + c1 * 8);
        }
        asm volatile("cp.async.commit_group;");
    };

    const int aRow  = lane & 15;
    const uint32_t aColb = (uint32_t)(lane >> 4) * 16;
    const int bRow  = ((lane & 16) >> 1) + (lane & 7);
    const uint32_t bColb = (uint32_t)((lane >> 3) & 1) * 16;

    const int NC = K >> 5;
    load_stage(0);
    load_stage(1);

    for (int c = 0; c < NC; c++) {
        // stage c ready when <=1 group pending (c+1 still in flight)
        asm volatile("cp.async.wait_group 1;");
        __syncthreads();
        // Issue next load AFTER the barrier: it overwrites stage (c-1)%3,
        // whose readers (iter c-1 compute) are proven done by this barrier.
        if (c + 2 < NC) load_stage(c + 2);
        else            asm volatile("cp.async.commit_group;");

        const uint32_t db = sbase + (uint32_t)(c % NSTAGE) * STAGE_B;
        #pragma unroll
        for (int ks = 0; ks < 2; ks++) {
            const uint32_t kb = (uint32_t)ks * 32;
            uint32_t ah[2][4];
            #pragma unroll
            for (int mt = 0; mt < 2; mt++)
                ldmx4(ah[mt], db + (uint32_t)(wm * 32 + mt * 16 + aRow) * ROWB + aColb + kb);
            #pragma unroll
            for (int ng = 0; ng < 4; ng++) {
                uint32_t bh[4], bl[4];
                uint32_t addr = db + TILE_B +
                                (uint32_t)(wn * 64 + ng * 16 + bRow) * ROWB + bColb + kb;
                ldmx4(bh, addr);
                ldmx4(bl, addr + TILE_B);
                #pragma unroll
                for (int mt = 0; mt < 2; mt++)
                    #pragma unroll
                    for (int jj = 0; jj < 2; jj++) {
                        const int nt = ng * 2 + jj, hf = jj * 2;
                        mma16816(acc[mt][nt], ah[mt], &bh[hf]);
                        mma16816(acc[mt][nt], ah[mt], &bl[hf]);
                    }
            }
        }
    }

    const int g = lane >> 2, tg = lane & 3;
    #pragma unroll
    for (int mt = 0; mt < 2; mt++)
        #pragma unroll
        for (int nt = 0; nt < 8; nt++) {
            const int row = m0 + wm * 32 + mt * 16 + g;
            const int col = n0 + wn * 64 + nt * 8 + tg * 2;
            *(float2*)&C[(size_t)row * N + col] =
                make_float2(acc[mt][nt][0], acc[mt][nt][1]);
            *(float2*)&C[(size_t)(row + 8) * N + col] =
                make_float2(acc[mt][nt][2], acc[mt][nt][3]);
        }
}

// ---------------- prep: rope + fp16 conversion (once) ------------------------
__global__ void prep_attn(const float* __restrict__ qkv,
                          __half* __restrict__ qh,
                          __half* __restrict__ kh, __half* __restrict__ kl,
                          __half* __restrict__ vh, __half* __restrict__ vl) {
    const int PPR = 1536;
    int idx = blockIdx.x * blockDim.x + threadIdx.x;
    if (idx >= MTOT * PPR) return;
    int row = idx / PPR;
    int p   = idx - row * PPR;
    int n   = row & (SEQ - 1);
    const float* src = qkv + (size_t)row * QKVW;

    if (p < 1024) {
        int i = p & 31;
        float freq = expf(-(float)i * (9.2103403719761836f / 32.0f));
        float ph = (float)n * freq, sn, cs;
        sincosf(ph, &sn, &cs);
        float x0 = src[2 * p], x1 = src[2 * p + 1];
        *(uint32_t*)&qh[(size_t)row * DIM_ + 2 * p] =
            pack2h((x0 * cs - x1 * sn) * 0.125f, (x0 * sn + x1 * cs) * 0.125f);
    } else if (p < 1280) {
        int i2 = p - 1024, i = i2 & 31;
        float freq = expf(-(float)i * (9.2103403719761836f / 32.0f));
        float ph = (float)n * freq, sn, cs;
        sincosf(ph, &sn, &cs);
        float x0 = src[DIM_ + 2 * i2], x1 = src[DIM_ + 2 * i2 + 1];
        float y0 = x0 * cs - x1 * sn, y1 = x0 * sn + x1 * cs;
        uint32_t H, L;
        split2h(y0, y1, H, L);
        *(uint32_t*)&kh[(size_t)row * KVD + 2 * i2] = H;
        *(uint32_t*)&kl[(size_t)row * KVD + 2 * i2] = L;
    } else {
        int i2 = p - 1280;
        float x0 = src[DIM_ + KVD + 2 * i2], x1 = src[DIM_ + KVD + 2 * i2 + 1];
        uint32_t H, L;
        split2h(x0, x1, H, L);
        *(uint32_t*)&vh[(size_t)row * KVD + 2 * i2] = H;
        *(uint32_t*)&vl[(size_t)row * KVD + 2 * i2] = L;
    }
}

// ---------------- flash v2: fp16 inputs, cp.async double-buffered K/V --------
#define SR 144
#define TSZ (64 * SR)             // 9216
#define FLASH_SMEM (9 * TSZ)      // 82944

__global__ __launch_bounds__(128)
void flash_tc(const __half* __restrict__ qh,
              const __half* __restrict__ kh, const __half* __restrict__ kl,
              const __half* __restrict__ vh, const __half* __restrict__ vl,
              __half* __restrict__ oh) {
    extern __shared__ char sm[];
    const uint32_t sb = smem_u32(sm);
    const int tid = threadIdx.x, w = tid >> 5, lane = tid & 31;
    const int h = blockIdx.y, b = blockIdx.z, kvh = h >> 2;

    const int bRow = ((lane & 16) >> 1) | (lane & 7);
    const uint32_t bCol = (uint32_t)((lane >> 3) & 1) * 16;
    const int vRow = lane & 15;
    const uint32_t vColb = (uint32_t)((lane & 16) >> 1) * 2;
    const int g = lane >> 2, tg = lane & 3;

    auto loadkv = [&](int kt, int s) {
        const uint32_t stg = sb + TSZ + (uint32_t)s * (4 * TSZ);
        const size_t rowbase = (size_t)(b * SEQ + kt * 64) * KVD + kvh * 64;
        #pragma unroll
        for (int u = 0; u < 16; u++) {
            int id = tid + u * 128;
            int c16 = id & 7, r = (id >> 3) & 63, t = id >> 9;
            const __half* src = (t == 0 ? kh : t == 1 ? kl : t == 2 ? vh : vl)
                                + rowbase + (size_t)r * KVD + c16 * 8;
            cp16(stg + (uint32_t)t * TSZ + (uint32_t)r * SR + (uint32_t)c16 * 16, src);
        }
        asm volatile("cp.async.commit_group;");
    };

    #pragma unroll 1
    for (int pass = 0; pass < 2; pass++) {
        const int qt = pass ? (NQT - 1 - (int)blockIdx.x) : (int)blockIdx.x;
        const int q0 = qt * 64;

        {
            const __half* src = qh + (size_t)(b * SEQ + q0) * DIM_ + h * 64;
            #pragma unroll
            for (int u = 0; u < 4; u++) {
                int id = tid + u * 128;
                int c16 = id & 7, r = id >> 3;
                cp16(sb + (uint32_t)r * SR + (uint32_t)c16 * 16,
                     src + (size_t)r * DIM_ + c16 * 8);
            }
            asm volatile("cp.async.commit_group;");
            asm volatile("cp.async.wait_group 0;");
            __syncthreads();
        }
        uint32_t qah[4][4];
        {
            int aRow = lane & 15;
            uint32_t aCol = (uint32_t)(lane >> 4) * 16;
            #pragma unroll
            for (int ks = 0; ks < 4; ks++)
                ldmx4(qah[ks], sb + (uint32_t)(w * 16 + aRow) * SR + aCol + ks * 32);
        }

        float oacc[8][4];
        #pragma unroll
        for (int nt = 0; nt < 8; nt++)
            #pragma unroll
            for (int q = 0; q < 4; q++) oacc[nt][q] = 0.0f;
        float m0v = -INFINITY, m1v = -INFINITY, l0v = 0.0f, l1v = 0.0f;

        loadkv(0, 0);
        for (int kt = 0; kt <= qt; kt++) {
            if (kt + 1 <= qt) loadkv(kt + 1, (kt + 1) & 1);
            else              asm volatile("cp.async.commit_group;");
            asm volatile("cp.async.wait_group 1;");
            __syncthreads();

            const uint32_t stg = sb + TSZ + (uint32_t)(kt & 1) * (4 * TSZ);
            const uint32_t oKh = stg, oVh = stg + 2 * TSZ;

            float sacc[8][4];
            #pragma unroll
            for (int nt = 0; nt < 8; nt++)
                #pragma unroll
                for (int q = 0; q < 4; q++) sacc[nt][q] = 0.0f;

            #pragma unroll
            for (int ks = 0; ks < 4; ks++) {
                #pragma unroll
                for (int ng = 0; ng < 4; ng++) {
                    uint32_t kbh[4], kbl[4];
                    uint32_t adr = oKh + (uint32_t)(ng * 16 + bRow) * SR + bCol + ks * 32;
                    ldmx4(kbh, adr);
                    ldmx4(kbl, adr + TSZ);
                    #pragma unroll
                    for (int jj = 0; jj < 2; jj++) {
                        const int nt = ng * 2 + jj, hf = jj * 2;
                        mma16816(sacc[nt], qah[ks], &kbh[hf]);
                        mma16816(sacc[nt], qah[ks], &kbl[hf]);
                    }
                }
            }

            if (kt == qt) {
                int r0 = w * 16 + g, r1 = r0 + 8;
                #pragma unroll
                for (int nt = 0; nt < 8; nt++) {
                    int c0 = nt * 8 + tg * 2;
                    if (c0     > r0) sacc[nt][0] = -1e30f;
                    if (c0 + 1 > r0) sacc[nt][1] = -1e30f;
                    if (c0     > r1) sacc[nt][2] = -1e30f;
                    if (c0 + 1 > r1) sacc[nt][3] = -1e30f;
                }
            }

            float mx0 = -INFINITY, mx1 = -INFINITY;
            #pragma unroll
            for (int nt = 0; nt < 8; nt++) {
                mx0 = fmaxf(mx0, fmaxf(sacc[nt][0], sacc[nt][1]));
                mx1 = fmaxf(mx1, fmaxf(sacc[nt][2], sacc[nt][3]));
            }
            mx0 = fmaxf(mx0, __shfl_xor_sync(0xffffffffu, mx0, 1));
            mx0 = fmaxf(mx0, __shfl_xor_sync(0xffffffffu, mx0, 2));
            mx1 = fmaxf(mx1, __shfl_xor_sync(0xffffffffu, mx1, 1));
            mx1 = fmaxf(mx1, __shfl_xor_sync(0xffffffffu, mx1, 2));

            float mn0 = fmaxf(m0v, mx0), mn1 = fmaxf(m1v, mx1);
            float cr0 = __expf(m0v - mn0), cr1 = __expf(m1v - mn1);
            m0v = mn0; m1v = mn1;
            l0v *= cr0; l1v *= cr1;
            #pragma unroll
            for (int nt = 0; nt < 8; nt++) {
                oacc[nt][0] *= cr0; oacc[nt][1] *= cr0;
                oacc[nt][2] *= cr1; oacc[nt][3] *= cr1;
            }
            float rs0 = 0.0f, rs1 = 0.0f;

            #pragma unroll
            for (int ks = 0; ks < 4; ks++) {
                float p[2][4];
                #pragma unroll
                for (int jj = 0; jj < 2; jj++) {
                    const int nt = 2 * ks + jj;
                    p[jj][0] = __expf(sacc[nt][0] - mn0);
                    p[jj][1] = __expf(sacc[nt][1] - mn0);
                    p[jj][2] = __expf(sacc[nt][2] - mn1);
                    p[jj][3] = __expf(sacc[nt][3] - mn1);
                    rs0 += p[jj][0] + p[jj][1];
                    rs1 += p[jj][2] + p[jj][3];
                }
                uint32_t pah[4];
                pah[0] = pack2h(p[0][0], p[0][1]);
                pah[1] = pack2h(p[0][2], p[0][3]);
                pah[2] = pack2h(p[1][0], p[1][1]);
                pah[3] = pack2h(p[1][2], p[1][3]);

                #pragma unroll
                for (int ng = 0; ng < 4; ng++) {
                    uint32_t vbh[4], vbl[4];
                    uint32_t adr = oVh + (uint32_t)(ks * 16 + vRow) * SR
                                   + (uint32_t)ng * 32 + vColb;
                    ldmx4t(vbh, adr);
                    ldmx4t(vbl, adr + TSZ);
                    #pragma unroll
                    for (int jj = 0; jj < 2; jj++) {
                        const int nt = ng * 2 + jj, hf = jj * 2;
                        mma16816(oacc[nt], pah, &vbh[hf]);
                        mma16816(oacc[nt], pah, &vbl[hf]);
                    }
                }
            }
            rs0 += __shfl_xor_sync(0xffffffffu, rs0, 1);
            rs0 += __shfl_xor_sync(0xffffffffu, rs0, 2);
            rs1 += __shfl_xor_sync(0xffffffffu, rs1, 1);
            rs1 += __shfl_xor_sync(0xffffffffu, rs1, 2);
            l0v += rs0; l1v += rs1;

            __syncthreads();
        }

        const float i0 = 1.0f / l0v, i1 = 1.0f / l1v;
        const int r0 = q0 + w * 16 + g;
        #pragma unroll
        for (int nt = 0; nt < 8; nt++) {
            const int col = h * 64 + nt * 8 + tg * 2;
            const size_t o0 = ((size_t)(b * SEQ + r0)) * DIM_ + col;
            const size_t o1 = o0 + (size_t)8 * DIM_;
            *(uint32_t*)&oh[o0] = pack2h(oacc[nt][0] * i0, oacc[nt][1] * i0);
            *(uint32_t*)&oh[o1] = pack2h(oacc[nt][2] * i1, oacc[nt][3] * i1);
        }
    }
}

// ---------------------------------------------------------------------------
extern "C" void kernel_launch(void* const* d_in, const int* in_sizes, int n_in,
                              void* d_out, int out_size) {
    const float* x  = (const float*)d_in[0];
    const float* wq = (const float*)d_in[1];
    const float* wk = (const float*)d_in[2];
    const float* wv = (const float*)d_in[3];
    const float* wo = (const float*)d_in[4];
    float* out = (float*)d_out;

    float* qkv;
    cudaGetSymbolAddress((void**)&qkv, g_qkv);
    __half *xh, *ah, *qh, *kh, *kl, *vh, *vl, *wh, *wl, *woh, *wol;
    cudaGetSymbolAddress((void**)&xh,  g_xh);
    cudaGetSymbolAddress((void**)&ah,  g_ah);
    cudaGetSymbolAddress((void**)&qh,  g_qh);
    cudaGetSymbolAddress((void**)&kh,  g_kh);  cudaGetSymbolAddress((void**)&kl,  g_kl);
    cudaGetSymbolAddress((void**)&vh,  g_vh);  cudaGetSymbolAddress((void**)&vl,  g_vl);
    cudaGetSymbolAddress((void**)&wh,  g_wh);  cudaGetSymbolAddress((void**)&wl,  g_wl);
    cudaGetSymbolAddress((void**)&woh, g_woh); cudaGetSymbolAddress((void**)&wol, g_wol);

    cudaFuncSetAttribute(mma_gemm, cudaFuncAttributeMaxDynamicSharedMemorySize, GEMM_SMEM);
    cudaFuncSetAttribute(flash_tc, cudaFuncAttributeMaxDynamicSharedMemorySize, FLASH_SMEM);

    const int M = MTOT;

    // 0: weights transpose+split AND x->fp16 (fused)
    transpose_all<<<dim3(416, 64), dim3(32, 8)>>>(wq, wk, wv, wo, x, xh,
                                                  wh, wl, woh, wol);
    // 1: fused QKV projection
    mma_gemm<<<dim3(QKVW / 128, M / 128), 256, GEMM_SMEM>>>(xh, wh, wl, qkv, QKVW, DIM_);
    // 2: rope + fp16 split (once)
    prep_attn<<<(M * 1536 + 255) / 256, 256>>>(qkv, qh, kh, kl, vh, vl);
    // 3: flash attention (profiled slot)
    flash_tc<<<dim3(NQT / 2, NH, B_), 128, FLASH_SMEM>>>(qh, kh, kl, vh, vl, ah);
    // 4: output projection
    mma_gemm<<<dim3(DIM_ / 128, M / 128), 256, GEMM_SMEM>>>(ah, woh, wol, out, DIM_, DIM_);
}

// round 13
// speedup vs baseline: 2.1783x; 1.1436x over previous
#include <cuda_runtime.h>
#include <cuda_fp16.h>
#include <math.h>
#include <stdint.h>

#define B_   2
#define SEQ  1024
#define DIM_ 2048
#define KVD  512
#define NH   32
#define NKV  8
#define HD   64
#define MTOT (B_ * SEQ)   // 2048
#define QKVW 3072         // fused q|k|v width

// ---------------- scratch (__device__ globals; allocation-guard safe) ------
__device__ float g_qkv[MTOT * QKVW];
__device__ __half g_xh[MTOT * DIM_];
__device__ __half g_ah[MTOT * DIM_];
__device__ __half g_qh[MTOT * DIM_];
__device__ __half g_kh[MTOT * KVD], g_kl[MTOT * KVD];
__device__ __half g_vh[MTOT * KVD], g_vl[MTOT * KVD];
__device__ __half g_wh[QKVW * DIM_], g_wl[QKVW * DIM_];
__device__ __half g_woh[DIM_ * DIM_], g_wol[DIM_ * DIM_];

// ---------------- helpers ---------------------------------------------------
__device__ __forceinline__ uint32_t smem_u32(const void* p) {
    uint32_t a;
    asm("{ .reg .u64 t; cvta.to.shared.u64 t, %1; cvt.u32.u64 %0, t; }"
        : "=r"(a) : "l"(p));
    return a;
}
__device__ __forceinline__ void cp16(uint32_t dst, const void* src) {
    uint64_t g = __cvta_generic_to_global(src);
    asm volatile("cp.async.cg.shared.global [%0], [%1], 16;" :: "r"(dst), "l"(g));
}
__device__ __forceinline__ void ldmx4(uint32_t* r, uint32_t addr) {
    asm volatile("ldmatrix.sync.aligned.m8n8.x4.shared.b16 {%0,%1,%2,%3}, [%4];"
                 : "=r"(r[0]), "=r"(r[1]), "=r"(r[2]), "=r"(r[3]) : "r"(addr));
}
__device__ __forceinline__ void ldmx4t(uint32_t* r, uint32_t addr) {
    asm volatile("ldmatrix.sync.aligned.m8n8.x4.trans.shared.b16 {%0,%1,%2,%3}, [%4];"
                 : "=r"(r[0]), "=r"(r[1]), "=r"(r[2]), "=r"(r[3]) : "r"(addr));
}
__device__ __forceinline__ void mma16816(float* c, const uint32_t* a, const uint32_t* b) {
    asm volatile(
        "mma.sync.aligned.m16n8k16.row.col.f32.f16.f16.f32 "
        "{%0,%1,%2,%3}, {%4,%5,%6,%7}, {%8,%9}, {%0,%1,%2,%3};"
        : "+f"(c[0]), "+f"(c[1]), "+f"(c[2]), "+f"(c[3])
        : "r"(a[0]), "r"(a[1]), "r"(a[2]), "r"(a[3]), "r"(b[0]), "r"(b[1]));
}
__device__ __forceinline__ uint32_t pack2h(float a, float b) {
    __half2 t = __floats2half2_rn(a, b);
    return *reinterpret_cast<uint32_t*>(&t);
}
__device__ __forceinline__ void split2h(float a, float b, uint32_t& hi, uint32_t& lo) {
    __half ha = __float2half_rn(a), hb = __float2half_rn(b);
    __half la = __float2half_rn(a - __half2float(ha));
    __half lb = __float2half_rn(b - __half2float(hb));
    __half2 th; th.x = ha; th.y = hb;
    __half2 tl; tl.x = la; tl.y = lb;
    hi = *reinterpret_cast<uint32_t*>(&th);
    lo = *reinterpret_cast<uint32_t*>(&tl);
}

// ---------------- fused weight transpose + x conversion ----------------------
__global__ void transpose_all(const float* __restrict__ wq, const float* __restrict__ wk,
                              const float* __restrict__ wv, const float* __restrict__ wo,
                              const float* __restrict__ x,  __half* __restrict__ xh,
                              __half* __restrict__ wh, __half* __restrict__ wl,
                              __half* __restrict__ woh, __half* __restrict__ wol) {
    const int bx = blockIdx.x;
    const int tx = threadIdx.x, ty = threadIdx.y;   // 32 x 8
    if (bx >= 160) {
        int idx = (((bx - 160) * gridDim.y + blockIdx.y) << 8) + (ty << 5) + tx;
        if (idx < MTOT * DIM_) xh[idx] = __float2half_rn(x[idx]);
        return;
    }
    __shared__ float t[32][33];
    const float* W; __half *hi, *lo; int N, nb;
    if (bx < 64)       { W = wq; hi = wh;  lo = wl;  N = DIM_; nb = bx; }
    else if (bx < 80)  { W = wk; hi = wh + (size_t)DIM_ * DIM_;
                         lo = wl + (size_t)DIM_ * DIM_;            N = KVD;  nb = bx - 64; }
    else if (bx < 96)  { W = wv; hi = wh + (size_t)(DIM_ + KVD) * DIM_;
                         lo = wl + (size_t)(DIM_ + KVD) * DIM_;    N = KVD;  nb = bx - 80; }
    else               { W = wo; hi = woh; lo = wol; N = DIM_; nb = bx - 96; }

    const int k0 = blockIdx.y * 32, n0 = nb * 32;
    #pragma unroll
    for (int r = ty; r < 32; r += 8)
        t[r][tx] = W[(size_t)(k0 + r) * N + n0 + tx];
    __syncthreads();
    #pragma unroll
    for (int r = ty; r < 32; r += 8) {
        float v = t[tx][r];
        __half h = __float2half_rn(v);
        size_t o = (size_t)(n0 + r) * DIM_ + k0 + tx;
        hi[o] = h;
        lo[o] = __float2half_rn(v - __half2float(h));
    }
}

// ---------------- mma.sync fp16 GEMM, templated hi/lo products --------------
#define ROWB       80
#define TILE_B     (128 * ROWB)
#define NSTAGE     3

template<bool USE_LO>
__global__ __launch_bounds__(256, 2)
void mma_gemm_t(const __half* __restrict__ Ah,
                const __half* __restrict__ Bh, const __half* __restrict__ Bl,
                float* __restrict__ C, int N, int K) {
    constexpr int NT = USE_LO ? 3 : 2;            // tiles per stage
    constexpr uint32_t STG = NT * TILE_B;
    extern __shared__ char sm[];
    const uint32_t sbase = smem_u32(sm);
    const int tid  = threadIdx.x;
    const int wid  = tid >> 5;
    const int lane = tid & 31;
    const int wm = wid & 3;
    const int wn = wid >> 2;
    const int m0 = blockIdx.y * 128, n0 = blockIdx.x * 128;

    float acc[2][8][4];
    #pragma unroll
    for (int i = 0; i < 2; i++)
        #pragma unroll
        for (int j = 0; j < 8; j++)
            #pragma unroll
            for (int q = 0; q < 4; q++) acc[i][j][q] = 0.0f;

    const __half* base[3] = {
        Ah + (size_t)m0 * K, Bh + (size_t)n0 * K, Bl + (size_t)n0 * K };

    const int r0 = tid >> 2, c0 = tid & 3;
    const int r1 = (tid + 256) >> 2, c1 = tid & 3;

    auto load_stage = [&](int cidx) {
        const int k0 = cidx << 5;
        const uint32_t db = sbase + (uint32_t)(cidx % NSTAGE) * STG;
        #pragma unroll
        for (int t = 0; t < NT; t++) {
            const uint32_t tb = db + t * TILE_B;
            cp16(tb + r0 * ROWB + c0 * 16, base[t] + (size_t)r0 * K + k0 + c0 * 8);
            cp16(tb + r1 * ROWB + c1 * 16, base[t] + (size_t)r1 * K + k0 + c1 * 8);
        }
        asm volatile("cp.async.commit_group;");
    };

    const int aRow  = lane & 15;
    const uint32_t aColb = (uint32_t)(lane >> 4) * 16;
    const int bRow  = ((lane & 16) >> 1) + (lane & 7);
    const uint32_t bColb = (uint32_t)((lane >> 3) & 1) * 16;

    const int NC = K >> 5;
    load_stage(0);
    load_stage(1);

    for (int c = 0; c < NC; c++) {
        asm volatile("cp.async.wait_group 1;");
        __syncthreads();
        if (c + 2 < NC) load_stage(c + 2);
        else            asm volatile("cp.async.commit_group;");

        const uint32_t db = sbase + (uint32_t)(c % NSTAGE) * STG;
        #pragma unroll
        for (int ks = 0; ks < 2; ks++) {
            const uint32_t kb = (uint32_t)ks * 32;
            uint32_t ah[2][4];
            #pragma unroll
            for (int mt = 0; mt < 2; mt++)
                ldmx4(ah[mt], db + (uint32_t)(wm * 32 + mt * 16 + aRow) * ROWB + aColb + kb);
            #pragma unroll
            for (int ng = 0; ng < 4; ng++) {
                uint32_t bh[4], bl[4];
                uint32_t addr = db + TILE_B +
                                (uint32_t)(wn * 64 + ng * 16 + bRow) * ROWB + bColb + kb;
                ldmx4(bh, addr);
                if (USE_LO) ldmx4(bl, addr + TILE_B);
                #pragma unroll
                for (int mt = 0; mt < 2; mt++)
                    #pragma unroll
                    for (int jj = 0; jj < 2; jj++) {
                        const int nt = ng * 2 + jj, hf = jj * 2;
                        mma16816(acc[mt][nt], ah[mt], &bh[hf]);
                        if (USE_LO) mma16816(acc[mt][nt], ah[mt], &bl[hf]);
                    }
            }
        }
    }

    const int g = lane >> 2, tg = lane & 3;
    #pragma unroll
    for (int mt = 0; mt < 2; mt++)
        #pragma unroll
        for (int nt = 0; nt < 8; nt++) {
            const int row = m0 + wm * 32 + mt * 16 + g;
            const int col = n0 + wn * 64 + nt * 8 + tg * 2;
            *(float2*)&C[(size_t)row * N + col] =
                make_float2(acc[mt][nt][0], acc[mt][nt][1]);
            *(float2*)&C[(size_t)(row + 8) * N + col] =
                make_float2(acc[mt][nt][2], acc[mt][nt][3]);
        }
}

#define GEMM_SMEM_LO (NSTAGE * 3 * TILE_B)   // 92160
#define GEMM_SMEM_HI (NSTAGE * 2 * TILE_B)   // 61440

// ---------------- prep: rope + fp16 conversion (once) ------------------------
__global__ void prep_attn(const float* __restrict__ qkv,
                          __half* __restrict__ qh,
                          __half* __restrict__ kh, __half* __restrict__ kl,
                          __half* __restrict__ vh, __half* __restrict__ vl) {
    const int PPR = 1536;
    int idx = blockIdx.x * blockDim.x + threadIdx.x;
    if (idx >= MTOT * PPR) return;
    int row = idx / PPR;
    int p   = idx - row * PPR;
    int n   = row & (SEQ - 1);
    const float* src = qkv + (size_t)row * QKVW;

    if (p < 1024) {
        int i = p & 31;
        float freq = expf(-(float)i * (9.2103403719761836f / 32.0f));
        float ph = (float)n * freq, sn, cs;
        sincosf(ph, &sn, &cs);
        float x0 = src[2 * p], x1 = src[2 * p + 1];
        *(uint32_t*)&qh[(size_t)row * DIM_ + 2 * p] =
            pack2h((x0 * cs - x1 * sn) * 0.125f, (x0 * sn + x1 * cs) * 0.125f);
    } else if (p < 1280) {
        int i2 = p - 1024, i = i2 & 31;
        float freq = expf(-(float)i * (9.2103403719761836f / 32.0f));
        float ph = (float)n * freq, sn, cs;
        sincosf(ph, &sn, &cs);
        float x0 = src[DIM_ + 2 * i2], x1 = src[DIM_ + 2 * i2 + 1];
        float y0 = x0 * cs - x1 * sn, y1 = x0 * sn + x1 * cs;
        uint32_t H, L;
        split2h(y0, y1, H, L);
        *(uint32_t*)&kh[(size_t)row * KVD + 2 * i2] = H;
        *(uint32_t*)&kl[(size_t)row * KVD + 2 * i2] = L;
    } else {
        int i2 = p - 1280;
        float x0 = src[DIM_ + KVD + 2 * i2], x1 = src[DIM_ + KVD + 2 * i2 + 1];
        uint32_t H, L;
        split2h(x0, x1, H, L);
        *(uint32_t*)&vh[(size_t)row * KVD + 2 * i2] = H;
        *(uint32_t*)&vl[(size_t)row * KVD + 2 * i2] = L;
    }
}

// ---------------- flash v3: 256 threads, 128-query tiles ----------------------
// 8 warps share each 64-key K/V stage (halves smem traffic per MMA).
// smem: Q (128 x 144B) + 2 stages x {Kh, Kl, Vh, Vl} (64 x 144B each).
#define SR 144
#define TSZ  (64 * SR)            // 9216
#define TSZQ (128 * SR)           // 18432
#define FLASH_SMEM (TSZQ + 8 * TSZ)   // 92160
#define NQB 8                     // 128-query blocks

__global__ __launch_bounds__(256)
void flash_tc(const __half* __restrict__ qh,
              const __half* __restrict__ kh, const __half* __restrict__ kl,
              const __half* __restrict__ vh, const __half* __restrict__ vl,
              __half* __restrict__ oh) {
    extern __shared__ char sm[];
    const uint32_t sb = smem_u32(sm);
    const int tid = threadIdx.x, w = tid >> 5, lane = tid & 31;
    const int h = blockIdx.y, b = blockIdx.z, kvh = h >> 2;

    const int bRow = ((lane & 16) >> 1) | (lane & 7);
    const uint32_t bCol = (uint32_t)((lane >> 3) & 1) * 16;
    const int vRow = lane & 15;
    const uint32_t vColb = (uint32_t)((lane & 16) >> 1) * 2;
    const int g = lane >> 2, tg = lane & 3;

    auto loadkv = [&](int kt, int s) {
        const uint32_t stg = sb + TSZQ + (uint32_t)s * (4 * TSZ);
        const size_t rowbase = (size_t)(b * SEQ + kt * 64) * KVD + kvh * 64;
        #pragma unroll
        for (int u = 0; u < 8; u++) {
            int id = tid + u * 256;
            int c16 = id & 7, r = (id >> 3) & 63, t = id >> 9;
            const __half* src = (t == 0 ? kh : t == 1 ? kl : t == 2 ? vh : vl)
                                + rowbase + (size_t)r * KVD + c16 * 8;
            cp16(stg + (uint32_t)t * TSZ + (uint32_t)r * SR + (uint32_t)c16 * 16, src);
        }
        asm volatile("cp.async.commit_group;");
    };

    #pragma unroll 1
    for (int pass = 0; pass < 2; pass++) {
        const int qb = pass ? (NQB - 1 - (int)blockIdx.x) : (int)blockIdx.x;
        const int q0 = qb * 128;
        const int ktmax = 2 * qb + 1;

        // ---- Q tile (128 rows) via cp.async ----
        {
            const __half* src = qh + (size_t)(b * SEQ + q0) * DIM_ + h * 64;
            #pragma unroll
            for (int u = 0; u < 4; u++) {
                int id = tid + u * 256;
                int c16 = id & 7, r = id >> 3;
                cp16(sb + (uint32_t)r * SR + (uint32_t)c16 * 16,
                     src + (size_t)r * DIM_ + c16 * 8);
            }
            asm volatile("cp.async.commit_group;");
            asm volatile("cp.async.wait_group 0;");
            __syncthreads();
        }
        uint32_t qah[4][4];
        {
            int aRow = lane & 15;
            uint32_t aCol = (uint32_t)(lane >> 4) * 16;
            #pragma unroll
            for (int ks = 0; ks < 4; ks++)
                ldmx4(qah[ks], sb + (uint32_t)(w * 16 + aRow) * SR + aCol + ks * 32);
        }

        float oacc[8][4];
        #pragma unroll
        for (int nt = 0; nt < 8; nt++)
            #pragma unroll
            for (int q = 0; q < 4; q++) oacc[nt][q] = 0.0f;
        float m0v = -INFINITY, m1v = -INFINITY, l0v = 0.0f, l1v = 0.0f;

        loadkv(0, 0);
        for (int kt = 0; kt <= ktmax; kt++) {
            if (kt + 1 <= ktmax) loadkv(kt + 1, (kt + 1) & 1);
            else                 asm volatile("cp.async.commit_group;");
            asm volatile("cp.async.wait_group 1;");
            __syncthreads();

            const uint32_t stg = sb + TSZQ + (uint32_t)(kt & 1) * (4 * TSZ);
            const uint32_t oKh = stg, oVh = stg + 2 * TSZ;

            float sacc[8][4];
            #pragma unroll
            for (int nt = 0; nt < 8; nt++)
                #pragma unroll
                for (int q = 0; q < 4; q++) sacc[nt][q] = 0.0f;

            #pragma unroll
            for (int ks = 0; ks < 4; ks++) {
                #pragma unroll
                for (int ng = 0; ng < 4; ng++) {
                    uint32_t kbh[4], kbl[4];
                    uint32_t adr = oKh + (uint32_t)(ng * 16 + bRow) * SR + bCol + ks * 32;
                    ldmx4(kbh, adr);
                    ldmx4(kbl, adr + TSZ);
                    #pragma unroll
                    for (int jj = 0; jj < 2; jj++) {
                        const int nt = ng * 2 + jj, hf = jj * 2;
                        mma16816(sacc[nt], qah[ks], &kbh[hf]);
                        mma16816(sacc[nt], qah[ks], &kbl[hf]);
                    }
                }
            }

            // ---- causal mask (global row/col compare, last two key tiles) ----
            if (kt >= 2 * qb) {
                const int qg0 = q0 + w * 16 + g, qg1 = qg0 + 8;
                #pragma unroll
                for (int nt = 0; nt < 8; nt++) {
                    int kg = kt * 64 + nt * 8 + tg * 2;
                    if (kg     > qg0) sacc[nt][0] = -1e30f;
                    if (kg + 1 > qg0) sacc[nt][1] = -1e30f;
                    if (kg     > qg1) sacc[nt][2] = -1e30f;
                    if (kg + 1 > qg1) sacc[nt][3] = -1e30f;
                }
            }

            float mx0 = -INFINITY, mx1 = -INFINITY;
            #pragma unroll
            for (int nt = 0; nt < 8; nt++) {
                mx0 = fmaxf(mx0, fmaxf(sacc[nt][0], sacc[nt][1]));
                mx1 = fmaxf(mx1, fmaxf(sacc[nt][2], sacc[nt][3]));
            }
            mx0 = fmaxf(mx0, __shfl_xor_sync(0xffffffffu, mx0, 1));
            mx0 = fmaxf(mx0, __shfl_xor_sync(0xffffffffu, mx0, 2));
            mx1 = fmaxf(mx1, __shfl_xor_sync(0xffffffffu, mx1, 1));
            mx1 = fmaxf(mx1, __shfl_xor_sync(0xffffffffu, mx1, 2));

            float mn0 = fmaxf(m0v, mx0), mn1 = fmaxf(m1v, mx1);
            float cr0 = __expf(m0v - mn0), cr1 = __expf(m1v - mn1);
            m0v = mn0; m1v = mn1;
            l0v *= cr0; l1v *= cr1;
            #pragma unroll
            for (int nt = 0; nt < 8; nt++) {
                oacc[nt][0] *= cr0; oacc[nt][1] *= cr0;
                oacc[nt][2] *= cr1; oacc[nt][3] *= cr1;
            }
            float rs0 = 0.0f, rs1 = 0.0f;

            #pragma unroll
            for (int ks = 0; ks < 4; ks++) {
                float p[2][4];
                #pragma unroll
                for (int jj = 0; jj < 2; jj++) {
                    const int nt = 2 * ks + jj;
                    p[jj][0] = __expf(sacc[nt][0] - mn0);
                    p[jj][1] = __expf(sacc[nt][1] - mn0);
                    p[jj][2] = __expf(sacc[nt][2] - mn1);
                    p[jj][3] = __expf(sacc[nt][3] - mn1);
                    rs0 += p[jj][0] + p[jj][1];
                    rs1 += p[jj][2] + p[jj][3];
                }
                uint32_t pah[4];
                pah[0] = pack2h(p[0][0], p[0][1]);
                pah[1] = pack2h(p[0][2], p[0][3]);
                pah[2] = pack2h(p[1][0], p[1][1]);
                pah[3] = pack2h(p[1][2], p[1][3]);

                #pragma unroll
                for (int ng = 0; ng < 4; ng++) {
                    uint32_t vbh[4], vbl[4];
                    uint32_t adr = oVh + (uint32_t)(ks * 16 + vRow) * SR
                                   + (uint32_t)ng * 32 + vColb;
                    ldmx4t(vbh, adr);
                    ldmx4t(vbl, adr + TSZ);
                    #pragma unroll
                    for (int jj = 0; jj < 2; jj++) {
                        const int nt = ng * 2 + jj, hf = jj * 2;
                        mma16816(oacc[nt], pah, &vbh[hf]);
                        mma16816(oacc[nt], pah, &vbl[hf]);
                    }
                }
            }
            rs0 += __shfl_xor_sync(0xffffffffu, rs0, 1);
            rs0 += __shfl_xor_sync(0xffffffffu, rs0, 2);
            rs1 += __shfl_xor_sync(0xffffffffu, rs1, 1);
            rs1 += __shfl_xor_sync(0xffffffffu, rs1, 2);
            l0v += rs0; l1v += rs1;

            __syncthreads();
        }

        const float i0 = 1.0f / l0v, i1 = 1.0f / l1v;
        const int r0 = q0 + w * 16 + g;
        #pragma unroll
        for (int nt = 0; nt < 8; nt++) {
            const int col = h * 64 + nt * 8 + tg * 2;
            const size_t o0 = ((size_t)(b * SEQ + r0)) * DIM_ + col;
            const size_t o1 = o0 + (size_t)8 * DIM_;
            *(uint32_t*)&oh[o0] = pack2h(oacc[nt][0] * i0, oacc[nt][1] * i0);
            *(uint32_t*)&oh[o1] = pack2h(oacc[nt][2] * i1, oacc[nt][3] * i1);
        }
    }
}

// ---------------------------------------------------------------------------
extern "C" void kernel_launch(void* const* d_in, const int* in_sizes, int n_in,
                              void* d_out, int out_size) {
    const float* x  = (const float*)d_in[0];
    const float* wq = (const float*)d_in[1];
    const float* wk = (const float*)d_in[2];
    const float* wv = (const float*)d_in[3];
    const float* wo = (const float*)d_in[4];
    float* out = (float*)d_out;

    float* qkv;
    cudaGetSymbolAddress((void**)&qkv, g_qkv);
    __half *xh, *ah, *qh, *kh, *kl, *vh, *vl, *wh, *wl, *woh, *wol;
    cudaGetSymbolAddress((void**)&xh,  g_xh);
    cudaGetSymbolAddress((void**)&ah,  g_ah);
    cudaGetSymbolAddress((void**)&qh,  g_qh);
    cudaGetSymbolAddress((void**)&kh,  g_kh);  cudaGetSymbolAddress((void**)&kl,  g_kl);
    cudaGetSymbolAddress((void**)&vh,  g_vh);  cudaGetSymbolAddress((void**)&vl,  g_vl);
    cudaGetSymbolAddress((void**)&wh,  g_wh);  cudaGetSymbolAddress((void**)&wl,  g_wl);
    cudaGetSymbolAddress((void**)&woh, g_woh); cudaGetSymbolAddress((void**)&wol, g_wol);

    cudaFuncSetAttribute(mma_gemm_t<true>,
                         cudaFuncAttributeMaxDynamicSharedMemorySize, GEMM_SMEM_LO);
    cudaFuncSetAttribute(mma_gemm_t<false>,
                         cudaFuncAttributeMaxDynamicSharedMemorySize, GEMM_SMEM_HI);
    cudaFuncSetAttribute(flash_tc,
                         cudaFuncAttributeMaxDynamicSharedMemorySize, FLASH_SMEM);

    const int M = MTOT;

    // 0: weights transpose+split AND x->fp16 (fused)
    transpose_all<<<dim3(416, 64), dim3(32, 8)>>>(wq, wk, wv, wo, x, xh,
                                                  wh, wl, woh, wol);
    // 1: fused QKV projection (hi+lo weights)
    mma_gemm_t<true><<<dim3(QKVW / 128, M / 128), 256, GEMM_SMEM_LO>>>(
        xh, wh, wl, qkv, QKVW, DIM_);
    // 2: rope + fp16 split (once)
    prep_attn<<<(M * 1536 + 255) / 256, 256>>>(qkv, qh, kh, kl, vh, vl);
    // 3: flash attention, 128-query tiles (profiled slot)
    flash_tc<<<dim3(NQB / 2, NH, B_), 256, FLASH_SMEM>>>(qh, kh, kl, vh, vl, ah);
    // 4: output projection (hi-only weights)
    mma_gemm_t<false><<<dim3(DIM_ / 128, M / 128), 256, GEMM_SMEM_HI>>>(
        ah, woh, wol, out, DIM_, DIM_);
}

// round 15
// speedup vs baseline: 2.2530x; 1.0343x over previous
#include <cuda_runtime.h>
#include <cuda_fp16.h>
#include <math.h>
#include <stdint.h>

#define B_   2
#define SEQ  1024
#define DIM_ 2048
#define KVD  512
#define NH   32
#define NKV  8
#define HD   64
#define MTOT (B_ * SEQ)   // 2048
#define QKVW 3072         // fused q|k|v width

// ---------------- scratch (__device__ globals; allocation-guard safe) ------
__device__ float g_qkv[MTOT * QKVW];
__device__ __half g_xh[MTOT * DIM_];
__device__ __half g_ah[MTOT * DIM_];
__device__ __half g_qh[MTOT * DIM_];
__device__ __half g_kh[MTOT * KVD];
__device__ __half g_vh[MTOT * KVD];
__device__ __half g_wh[QKVW * DIM_], g_wl[QKVW * DIM_];
__device__ __half g_woh[DIM_ * DIM_], g_wol[DIM_ * DIM_];

// ---------------- helpers ---------------------------------------------------
__device__ __forceinline__ uint32_t smem_u32(const void* p) {
    uint32_t a;
    asm("{ .reg .u64 t; cvta.to.shared.u64 t, %1; cvt.u32.u64 %0, t; }"
        : "=r"(a) : "l"(p));
    return a;
}
__device__ __forceinline__ void cp16(uint32_t dst, const void* src) {
    uint64_t g = __cvta_generic_to_global(src);
    asm volatile("cp.async.cg.shared.global [%0], [%1], 16;" :: "r"(dst), "l"(g));
}
__device__ __forceinline__ void ldmx4(uint32_t* r, uint32_t addr) {
    asm volatile("ldmatrix.sync.aligned.m8n8.x4.shared.b16 {%0,%1,%2,%3}, [%4];"
                 : "=r"(r[0]), "=r"(r[1]), "=r"(r[2]), "=r"(r[3]) : "r"(addr));
}
__device__ __forceinline__ void ldmx4t(uint32_t* r, uint32_t addr) {
    asm volatile("ldmatrix.sync.aligned.m8n8.x4.trans.shared.b16 {%0,%1,%2,%3}, [%4];"
                 : "=r"(r[0]), "=r"(r[1]), "=r"(r[2]), "=r"(r[3]) : "r"(addr));
}
__device__ __forceinline__ void mma16816(float* c, const uint32_t* a, const uint32_t* b) {
    asm volatile(
        "mma.sync.aligned.m16n8k16.row.col.f32.f16.f16.f32 "
        "{%0,%1,%2,%3}, {%4,%5,%6,%7}, {%8,%9}, {%0,%1,%2,%3};"
        : "+f"(c[0]), "+f"(c[1]), "+f"(c[2]), "+f"(c[3])
        : "r"(a[0]), "r"(a[1]), "r"(a[2]), "r"(a[3]), "r"(b[0]), "r"(b[1]));
}
__device__ __forceinline__ uint32_t pack2h(float a, float b) {
    __half2 t = __floats2half2_rn(a, b);
    return *reinterpret_cast<uint32_t*>(&t);
}

// ---------------- fused weight transpose + x conversion ----------------------
__global__ void transpose_all(const float* __restrict__ wq, const float* __restrict__ wk,
                              const float* __restrict__ wv, const float* __restrict__ wo,
                              const float* __restrict__ x,  __half* __restrict__ xh,
                              __half* __restrict__ wh, __half* __restrict__ wl,
                              __half* __restrict__ woh, __half* __restrict__ wol) {
    const int bx = blockIdx.x;
    const int tx = threadIdx.x, ty = threadIdx.y;   // 32 x 8
    if (bx >= 160) {
        int idx = (((bx - 160) * gridDim.y + blockIdx.y) << 8) + (ty << 5) + tx;
        if (idx < MTOT * DIM_) xh[idx] = __float2half_rn(x[idx]);
        return;
    }
    __shared__ float t[32][33];
    const float* W; __half *hi, *lo; int N, nb;
    if (bx < 64)       { W = wq; hi = wh;  lo = wl;  N = DIM_; nb = bx; }
    else if (bx < 80)  { W = wk; hi = wh + (size_t)DIM_ * DIM_;
                         lo = wl + (size_t)DIM_ * DIM_;            N = KVD;  nb = bx - 64; }
    else if (bx < 96)  { W = wv; hi = wh + (size_t)(DIM_ + KVD) * DIM_;
                         lo = wl + (size_t)(DIM_ + KVD) * DIM_;    N = KVD;  nb = bx - 80; }
    else               { W = wo; hi = woh; lo = wol; N = DIM_; nb = bx - 96; }

    const int k0 = blockIdx.y * 32, n0 = nb * 32;
    #pragma unroll
    for (int r = ty; r < 32; r += 8)
        t[r][tx] = W[(size_t)(k0 + r) * N + n0 + tx];
    __syncthreads();
    #pragma unroll
    for (int r = ty; r < 32; r += 8) {
        float v = t[tx][r];
        __half h = __float2half_rn(v);
        size_t o = (size_t)(n0 + r) * DIM_ + k0 + tx;
        hi[o] = h;
        lo[o] = __float2half_rn(v - __half2float(h));
    }
}

// ---------------- GEMM A: 128x64 tiles, hi+lo B (QKV projection) ------------
// Per stage: A 128 rows x 64B (512 chunks), Bh+Bl 2x64 rows x 64B (512 chunks)
// = 1024 chunks = 4 cp16/thread.
#define ROWB       80
#define TILE_A_B   (128 * ROWB)          // 10240
#define TILE_B64   (64 * ROWB)           // 5120
#define STG_N64    (TILE_A_B + 2 * TILE_B64)   // 20480
#define NSTAGE     3
#define GEMM_SMEM_N64 (NSTAGE * STG_N64)       // 61440

__global__ __launch_bounds__(256, 2)
void mma_gemm_n64(const __half* __restrict__ Ah,
                  const __half* __restrict__ Bh, const __half* __restrict__ Bl,
                  float* __restrict__ C, int N, int K) {
    extern __shared__ char sm[];
    const uint32_t sbase = smem_u32(sm);
    const int tid  = threadIdx.x;
    const int wid  = tid >> 5;
    const int lane = tid & 31;
    const int wm = wid & 3;       // 32-row slice
    const int wn = wid >> 2;      // 0..1 -> 32-col slice
    const int m0 = blockIdx.y * 128, n0 = blockIdx.x * 64;

    float acc[2][4][4];
    #pragma unroll
    for (int i = 0; i < 2; i++)
        #pragma unroll
        for (int j = 0; j < 4; j++)
            #pragma unroll
            for (int q = 0; q < 4; q++) acc[i][j][q] = 0.0f;

    const __half* Abase  = Ah + (size_t)m0 * K;
    const __half* Bbase[2] = { Bh + (size_t)n0 * K, Bl + (size_t)n0 * K };

    // A: rows 0..63 via (tid>>2, tid&3); rows 64..127 via +64
    const int ar = tid >> 2, ac = tid & 3;
    // B: chunk ids tid and tid+256 over 512 chunks: tile = id>>8, row = (id>>2)&63, c = id&3
    const int b0t = 0,        b0r = (tid >> 2) & 63,           b0c = tid & 3;
    const int b1t = 1,        b1r = b0r,                        b1c = b0c;

    auto load_stage = [&](int cidx) {
        const int k0 = cidx << 5;
        const uint32_t db = sbase + (uint32_t)(cidx % NSTAGE) * STG_N64;
        cp16(db + ar * ROWB + ac * 16,        Abase + (size_t)ar * K + k0 + ac * 8);
        cp16(db + (ar + 64) * ROWB + ac * 16, Abase + (size_t)(ar + 64) * K + k0 + ac * 8);
        cp16(db + TILE_A_B + b0t * TILE_B64 + b0r * ROWB + b0c * 16,
             Bbase[b0t] + (size_t)b0r * K + k0 + b0c * 8);
        cp16(db + TILE_A_B + b1t * TILE_B64 + b1r * ROWB + b1c * 16,
             Bbase[b1t] + (size_t)b1r * K + k0 + b1c * 8);
        asm volatile("cp.async.commit_group;");
    };

    const int aRow  = lane & 15;
    const uint32_t aColb = (uint32_t)(lane >> 4) * 16;
    const int bRow  = ((lane & 16) >> 1) + (lane & 7);
    const uint32_t bColb = (uint32_t)((lane >> 3) & 1) * 16;

    const int NC = K >> 5;
    load_stage(0);
    load_stage(1);

    for (int c = 0; c < NC; c++) {
        asm volatile("cp.async.wait_group 1;");
        __syncthreads();
        if (c + 2 < NC) load_stage(c + 2);
        else            asm volatile("cp.async.commit_group;");

        const uint32_t db = sbase + (uint32_t)(c % NSTAGE) * STG_N64;
        #pragma unroll
        for (int ks = 0; ks < 2; ks++) {
            const uint32_t kb = (uint32_t)ks * 32;
            uint32_t ah[2][4];
            #pragma unroll
            for (int mt = 0; mt < 2; mt++)
                ldmx4(ah[mt], db + (uint32_t)(wm * 32 + mt * 16 + aRow) * ROWB + aColb + kb);
            #pragma unroll
            for (int ng = 0; ng < 2; ng++) {
                uint32_t bh[4], bl[4];
                uint32_t addr = db + TILE_A_B +
                                (uint32_t)(wn * 32 + ng * 16 + bRow) * ROWB + bColb + kb;
                ldmx4(bh, addr);
                ldmx4(bl, addr + TILE_B64);
                #pragma unroll
                for (int mt = 0; mt < 2; mt++)
                    #pragma unroll
                    for (int jj = 0; jj < 2; jj++) {
                        const int nt = ng * 2 + jj, hf = jj * 2;
                        mma16816(acc[mt][nt], ah[mt], &bh[hf]);
                        mma16816(acc[mt][nt], ah[mt], &bl[hf]);
                    }
            }
        }
    }

    const int g = lane >> 2, tg = lane & 3;
    #pragma unroll
    for (int mt = 0; mt < 2; mt++)
        #pragma unroll
        for (int nt = 0; nt < 4; nt++) {
            const int row = m0 + wm * 32 + mt * 16 + g;
            const int col = n0 + wn * 32 + nt * 8 + tg * 2;
            *(float2*)&C[(size_t)row * N + col] =
                make_float2(acc[mt][nt][0], acc[mt][nt][1]);
            *(float2*)&C[(size_t)(row + 8) * N + col] =
                make_float2(acc[mt][nt][2], acc[mt][nt][3]);
        }
}

// ---------------- GEMM B: 128x128 tiles, hi-only B (WO projection) ----------
#define TILE_B_    (128 * ROWB)
#define STG_HI     (2 * TILE_B_)
#define GEMM_SMEM_HI (NSTAGE * STG_HI)   // 61440

__global__ __launch_bounds__(256, 2)
void mma_gemm_hi(const __half* __restrict__ Ah, const __half* __restrict__ Bh,
                 float* __restrict__ C, int N, int K) {
    extern __shared__ char sm[];
    const uint32_t sbase = smem_u32(sm);
    const int tid  = threadIdx.x;
    const int wid  = tid >> 5;
    const int lane = tid & 31;
    const int wm = wid & 3;
    const int wn = wid >> 2;
    const int m0 = blockIdx.y * 128, n0 = blockIdx.x * 128;

    float acc[2][8][4];
    #pragma unroll
    for (int i = 0; i < 2; i++)
        #pragma unroll
        for (int j = 0; j < 8; j++)
            #pragma unroll
            for (int q = 0; q < 4; q++) acc[i][j][q] = 0.0f;

    const __half* base[2] = { Ah + (size_t)m0 * K, Bh + (size_t)n0 * K };

    // per tile: 128 rows x 4 chunks = 512 = 2/thread
    const int r0 = tid >> 2, c0 = tid & 3;
    const int r1 = (tid + 256) >> 2, c1 = tid & 3;

    auto load_stage = [&](int cidx) {
        const int k0 = cidx << 5;
        const uint32_t db = sbase + (uint32_t)(cidx % NSTAGE) * STG_HI;
        #pragma unroll
        for (int t = 0; t < 2; t++) {
            const uint32_t tb = db + t * TILE_B_;
            cp16(tb + r0 * ROWB + c0 * 16, base[t] + (size_t)r0 * K + k0 + c0 * 8);
            cp16(tb + r1 * ROWB + c1 * 16, base[t] + (size_t)r1 * K + k0 + c1 * 8);
        }
        asm volatile("cp.async.commit_group;");
    };

    const int aRow  = lane & 15;
    const uint32_t aColb = (uint32_t)(lane >> 4) * 16;
    const int bRow  = ((lane & 16) >> 1) + (lane & 7);
    const uint32_t bColb = (uint32_t)((lane >> 3) & 1) * 16;

    const int NC = K >> 5;
    load_stage(0);
    load_stage(1);

    for (int c = 0; c < NC; c++) {
        asm volatile("cp.async.wait_group 1;");
        __syncthreads();
        if (c + 2 < NC) load_stage(c + 2);
        else            asm volatile("cp.async.commit_group;");

        const uint32_t db = sbase + (uint32_t)(c % NSTAGE) * STG_HI;
        #pragma unroll
        for (int ks = 0; ks < 2; ks++) {
            const uint32_t kb = (uint32_t)ks * 32;
            uint32_t ah[2][4];
            #pragma unroll
            for (int mt = 0; mt < 2; mt++)
                ldmx4(ah[mt], db + (uint32_t)(wm * 32 + mt * 16 + aRow) * ROWB + aColb + kb);
            #pragma unroll
            for (int ng = 0; ng < 4; ng++) {
                uint32_t bh[4];
                ldmx4(bh, db + TILE_B_ +
                          (uint32_t)(wn * 64 + ng * 16 + bRow) * ROWB + bColb + kb);
                #pragma unroll
                for (int mt = 0; mt < 2; mt++)
                    #pragma unroll
                    for (int jj = 0; jj < 2; jj++)
                        mma16816(acc[mt][ng * 2 + jj], ah[mt], &bh[jj * 2]);
            }
        }
    }

    const int g = lane >> 2, tg = lane & 3;
    #pragma unroll
    for (int mt = 0; mt < 2; mt++)
        #pragma unroll
        for (int nt = 0; nt < 8; nt++) {
            const int row = m0 + wm * 32 + mt * 16 + g;
            const int col = n0 + wn * 64 + nt * 8 + tg * 2;
            *(float2*)&C[(size_t)row * N + col] =
                make_float2(acc[mt][nt][0], acc[mt][nt][1]);
            *(float2*)&C[(size_t)(row + 8) * N + col] =
                make_float2(acc[mt][nt][2], acc[mt][nt][3]);
        }
}

// ---------------- prep: rope + fp16 conversion (hi-only K/V) -----------------
__global__ void prep_attn(const float* __restrict__ qkv,
                          __half* __restrict__ qh,
                          __half* __restrict__ kh, __half* __restrict__ vh) {
    const int PPR = 1536;
    int idx = blockIdx.x * blockDim.x + threadIdx.x;
    if (idx >= MTOT * PPR) return;
    int row = idx / PPR;
    int p   = idx - row * PPR;
    int n   = row & (SEQ - 1);
    const float* src = qkv + (size_t)row * QKVW;

    if (p < 1024) {
        int i = p & 31;
        float freq = expf(-(float)i * (9.2103403719761836f / 32.0f));
        float ph = (float)n * freq, sn, cs;
        sincosf(ph, &sn, &cs);
        float x0 = src[2 * p], x1 = src[2 * p + 1];
        *(uint32_t*)&qh[(size_t)row * DIM_ + 2 * p] =
            pack2h((x0 * cs - x1 * sn) * 0.125f, (x0 * sn + x1 * cs) * 0.125f);
    } else if (p < 1280) {
        int i2 = p - 1024, i = i2 & 31;
        float freq = expf(-(float)i * (9.2103403719761836f / 32.0f));
        float ph = (float)n * freq, sn, cs;
        sincosf(ph, &sn, &cs);
        float x0 = src[DIM_ + 2 * i2], x1 = src[DIM_ + 2 * i2 + 1];
        *(uint32_t*)&kh[(size_t)row * KVD + 2 * i2] =
            pack2h(x0 * cs - x1 * sn, x0 * sn + x1 * cs);
    } else {
        int i2 = p - 1280;
        *(uint32_t*)&vh[(size_t)row * KVD + 2 * i2] =
            pack2h(src[DIM_ + KVD + 2 * i2], src[DIM_ + KVD + 2 * i2 + 1]);
    }
}

// ---------------- flash v4: fp16 K/V hi-only, 256 thr, 128-q tiles -----------
// smem: Q (128x144B) + 2 stages x {Kh, Vh} (64x144B each) = 55296 -> 4 CTAs/SM
// Q tile: 128 rows x 8 chunks = 1024 = 4/thread.
// K/V stage: 2 tiles x 64 rows x 8 chunks = 1024 = 4/thread.
#define SR 144
#define TSZ  (64 * SR)            // 9216
#define TSZQ (128 * SR)           // 18432
#define FLASH_SMEM (TSZQ + 4 * TSZ)   // 55296
#define NQB 8

__global__ __launch_bounds__(256)
void flash_tc(const __half* __restrict__ qh,
              const __half* __restrict__ kh, const __half* __restrict__ vh,
              __half* __restrict__ oh) {
    extern __shared__ char sm[];
    const uint32_t sb = smem_u32(sm);
    const int tid = threadIdx.x, w = tid >> 5, lane = tid & 31;
    const int h = blockIdx.y, b = blockIdx.z, kvh = h >> 2;

    const int bRow = ((lane & 16) >> 1) | (lane & 7);
    const uint32_t bCol = (uint32_t)((lane >> 3) & 1) * 16;
    const int vRow = lane & 15;
    const uint32_t vColb = (uint32_t)((lane & 16) >> 1) * 2;
    const int g = lane >> 2, tg = lane & 3;

    auto loadkv = [&](int kt, int s) {
        const uint32_t stg = sb + TSZQ + (uint32_t)s * (2 * TSZ);
        const size_t rowbase = (size_t)(b * SEQ + kt * 64) * KVD + kvh * 64;
        #pragma unroll
        for (int u = 0; u < 4; u++) {
            int id = tid + u * 256;                    // 0..1023
            int c16 = id & 7, r = (id >> 3) & 63, t = id >> 9;
            const __half* src = (t == 0 ? kh : vh) + rowbase + (size_t)r * KVD + c16 * 8;
            cp16(stg + (uint32_t)t * TSZ + (uint32_t)r * SR + (uint32_t)c16 * 16, src);
        }
        asm volatile("cp.async.commit_group;");
    };

    #pragma unroll 1
    for (int pass = 0; pass < 2; pass++) {
        const int qb = pass ? (NQB - 1 - (int)blockIdx.x) : (int)blockIdx.x;
        const int q0 = qb * 128;
        const int ktmax = 2 * qb + 1;

        // ---- Q tile: 128 rows x 8 chunks = 1024 = 4/thread ----
        {
            const __half* src = qh + (size_t)(b * SEQ + q0) * DIM_ + h * 64;
            #pragma unroll
            for (int u = 0; u < 4; u++) {
                int id = tid + u * 256;                // 0..1023
                int c16 = id & 7, r = id >> 3;         // r 0..127
                cp16(sb + (uint32_t)r * SR + (uint32_t)c16 * 16,
                     src + (size_t)r * DIM_ + c16 * 8);
            }
            asm volatile("cp.async.commit_group;");
            asm volatile("cp.async.wait_group 0;");
            __syncthreads();
        }
        uint32_t qah[4][4];
        {
            int aRow = lane & 15;
            uint32_t aCol = (uint32_t)(lane >> 4) * 16;
            #pragma unroll
            for (int ks = 0; ks < 4; ks++)
                ldmx4(qah[ks], sb + (uint32_t)(w * 16 + aRow) * SR + aCol + ks * 32);
        }

        float oacc[8][4];
        #pragma unroll
        for (int nt = 0; nt < 8; nt++)
            #pragma unroll
            for (int q = 0; q < 4; q++) oacc[nt][q] = 0.0f;
        float m0v = -INFINITY, m1v = -INFINITY, l0v = 0.0f, l1v = 0.0f;

        loadkv(0, 0);
        for (int kt = 0; kt <= ktmax; kt++) {
            if (kt + 1 <= ktmax) loadkv(kt + 1, (kt + 1) & 1);
            else                 asm volatile("cp.async.commit_group;");
            asm volatile("cp.async.wait_group 1;");
            __syncthreads();

            const uint32_t stg = sb + TSZQ + (uint32_t)(kt & 1) * (2 * TSZ);
            const uint32_t oKh = stg, oVh = stg + TSZ;

            float sacc[8][4];
            #pragma unroll
            for (int nt = 0; nt < 8; nt++)
                #pragma unroll
                for (int q = 0; q < 4; q++) sacc[nt][q] = 0.0f;

            #pragma unroll
            for (int ks = 0; ks < 4; ks++) {
                #pragma unroll
                for (int ng = 0; ng < 4; ng++) {
                    uint32_t kbh[4];
                    ldmx4(kbh, oKh + (uint32_t)(ng * 16 + bRow) * SR + bCol + ks * 32);
                    #pragma unroll
                    for (int jj = 0; jj < 2; jj++)
                        mma16816(sacc[ng * 2 + jj], qah[ks], &kbh[jj * 2]);
                }
            }

            if (kt >= 2 * qb) {
                const int qg0 = q0 + w * 16 + g, qg1 = qg0 + 8;
                #pragma unroll
                for (int nt = 0; nt < 8; nt++) {
                    int kg = kt * 64 + nt * 8 + tg * 2;
                    if (kg     > qg0) sacc[nt][0] = -1e30f;
                    if (kg + 1 > qg0) sacc[nt][1] = -1e30f;
                    if (kg     > qg1) sacc[nt][2] = -1e30f;
                    if (kg + 1 > qg1) sacc[nt][3] = -1e30f;
                }
            }

            float mx0 = -INFINITY, mx1 = -INFINITY;
            #pragma unroll
            for (int nt = 0; nt < 8; nt++) {
                mx0 = fmaxf(mx0, fmaxf(sacc[nt][0], sacc[nt][1]));
                mx1 = fmaxf(mx1, fmaxf(sacc[nt][2], sacc[nt][3]));
            }
            mx0 = fmaxf(mx0, __shfl_xor_sync(0xffffffffu, mx0, 1));
            mx0 = fmaxf(mx0, __shfl_xor_sync(0xffffffffu, mx0, 2));
            mx1 = fmaxf(mx1, __shfl_xor_sync(0xffffffffu, mx1, 1));
            mx1 = fmaxf(mx1, __shfl_xor_sync(0xffffffffu, mx1, 2));

            float mn0 = fmaxf(m0v, mx0), mn1 = fmaxf(m1v, mx1);
            float cr0 = __expf(m0v - mn0), cr1 = __expf(m1v - mn1);
            m0v = mn0; m1v = mn1;
            l0v *= cr0; l1v *= cr1;
            #pragma unroll
            for (int nt = 0; nt < 8; nt++) {
                oacc[nt][0] *= cr0; oacc[nt][1] *= cr0;
                oacc[nt][2] *= cr1; oacc[nt][3] *= cr1;
            }
            float rs0 = 0.0f, rs1 = 0.0f;

            #pragma unroll
            for (int ks = 0; ks < 4; ks++) {
                float p[2][4];
                #pragma unroll
                for (int jj = 0; jj < 2; jj++) {
                    const int nt = 2 * ks + jj;
                    p[jj][0] = __expf(sacc[nt][0] - mn0);
                    p[jj][1] = __expf(sacc[nt][1] - mn0);
                    p[jj][2] = __expf(sacc[nt][2] - mn1);
                    p[jj][3] = __expf(sacc[nt][3] - mn1);
                    rs0 += p[jj][0] + p[jj][1];
                    rs1 += p[jj][2] + p[jj][3];
                }
                uint32_t pah[4];
                pah[0] = pack2h(p[0][0], p[0][1]);
                pah[1] = pack2h(p[0][2], p[0][3]);
                pah[2] = pack2h(p[1][0], p[1][1]);
                pah[3] = pack2h(p[1][2], p[1][3]);

                #pragma unroll
                for (int ng = 0; ng < 4; ng++) {
                    uint32_t vbh[4];
                    ldmx4t(vbh, oVh + (uint32_t)(ks * 16 + vRow) * SR
                                 + (uint32_t)ng * 32 + vColb);
                    #pragma unroll
                    for (int jj = 0; jj < 2; jj++)
                        mma16816(oacc[ng * 2 + jj], pah, &vbh[jj * 2]);
                }
            }
            rs0 += __shfl_xor_sync(0xffffffffu, rs0, 1);
            rs0 += __shfl_xor_sync(0xffffffffu, rs0, 2);
            rs1 += __shfl_xor_sync(0xffffffffu, rs1, 1);
            rs1 += __shfl_xor_sync(0xffffffffu, rs1, 2);
            l0v += rs0; l1v += rs1;

            __syncthreads();
        }

        const float i0 = 1.0f / l0v, i1 = 1.0f / l1v;
        const int r0 = q0 + w * 16 + g;
        #pragma unroll
        for (int nt = 0; nt < 8; nt++) {
            const int col = h * 64 + nt * 8 + tg * 2;
            const size_t o0 = ((size_t)(b * SEQ + r0)) * DIM_ + col;
            const size_t o1 = o0 + (size_t)8 * DIM_;
            *(uint32_t*)&oh[o0] = pack2h(oacc[nt][0] * i0, oacc[nt][1] * i0);
            *(uint32_t*)&oh[o1] = pack2h(oacc[nt][2] * i1, oacc[nt][3] * i1);
        }
    }
}

// ---------------------------------------------------------------------------
extern "C" void kernel_launch(void* const* d_in, const int* in_sizes, int n_in,
                              void* d_out, int out_size) {
    const float* x  = (const float*)d_in[0];
    const float* wq = (const float*)d_in[1];
    const float* wk = (const float*)d_in[2];
    const float* wv = (const float*)d_in[3];
    const float* wo = (const float*)d_in[4];
    float* out = (float*)d_out;

    float* qkv;
    cudaGetSymbolAddress((void**)&qkv, g_qkv);
    __half *xh, *ah, *qh, *kh, *vh, *wh, *wl, *woh, *wol;
    cudaGetSymbolAddress((void**)&xh,  g_xh);
    cudaGetSymbolAddress((void**)&ah,  g_ah);
    cudaGetSymbolAddress((void**)&qh,  g_qh);
    cudaGetSymbolAddress((void**)&kh,  g_kh);
    cudaGetSymbolAddress((void**)&vh,  g_vh);
    cudaGetSymbolAddress((void**)&wh,  g_wh);  cudaGetSymbolAddress((void**)&wl,  g_wl);
    cudaGetSymbolAddress((void**)&woh, g_woh); cudaGetSymbolAddress((void**)&wol, g_wol);

    cudaFuncSetAttribute(mma_gemm_n64,
                         cudaFuncAttributeMaxDynamicSharedMemorySize, GEMM_SMEM_N64);
    cudaFuncSetAttribute(mma_gemm_hi,
                         cudaFuncAttributeMaxDynamicSharedMemorySize, GEMM_SMEM_HI);
    cudaFuncSetAttribute(flash_tc,
                         cudaFuncAttributeMaxDynamicSharedMemorySize, FLASH_SMEM);

    const int M = MTOT;

    // 0: weights transpose+split AND x->fp16 (fused)
    transpose_all<<<dim3(416, 64), dim3(32, 8)>>>(wq, wk, wv, wo, x, xh,
                                                  wh, wl, woh, wol);
    // 1: fused QKV projection (128x64 tiles to shrink wave tail)
    mma_gemm_n64<<<dim3(QKVW / 64, M / 128), 256, GEMM_SMEM_N64>>>(
        xh, wh, wl, qkv, QKVW, DIM_);
    // 2: rope + fp16 (hi-only K/V)
    prep_attn<<<(M * 1536 + 255) / 256, 256>>>(qkv, qh, kh, vh);
    // 3: flash attention (profiled slot)
    flash_tc<<<dim3(NQB / 2, NH, B_), 256, FLASH_SMEM>>>(qh, kh, vh, ah);
    // 4: output projection (hi-only weights)
    mma_gemm_hi<<<dim3(DIM_ / 128, M / 128), 256, GEMM_SMEM_HI>>>(
        ah, woh, out, DIM_, DIM_);
}

// round 17
// speedup vs baseline: 2.7966x; 1.2413x over previous
#include <cuda_runtime.h>
#include <cuda_fp16.h>
#include <math.h>
#include <stdint.h>

#define B_   2
#define SEQ  1024
#define DIM_ 2048
#define KVD  512
#define NH   32
#define NKV  8
#define HD   64
#define MTOT (B_ * SEQ)   // 2048
#define QKVW 3072         // fused q|k|v width

// ---------------- scratch (__device__ globals; allocation-guard safe) ------
__device__ float g_qkv[MTOT * QKVW];
__device__ __half g_xh[MTOT * DIM_];
__device__ __half g_ah[MTOT * DIM_];
__device__ __half g_qh[MTOT * DIM_];
__device__ __half g_kh[MTOT * KVD];
__device__ __half g_vh[MTOT * KVD];
__device__ __half g_wh[QKVW * DIM_];          // fused transposed weights (hi only)
__device__ __half g_woh[DIM_ * DIM_];

// ---------------- helpers ---------------------------------------------------
__device__ __forceinline__ uint32_t smem_u32(const void* p) {
    uint32_t a;
    asm("{ .reg .u64 t; cvta.to.shared.u64 t, %1; cvt.u32.u64 %0, t; }"
        : "=r"(a) : "l"(p));
    return a;
}
__device__ __forceinline__ void cp16(uint32_t dst, const void* src) {
    uint64_t g = __cvta_generic_to_global(src);
    asm volatile("cp.async.cg.shared.global [%0], [%1], 16;" :: "r"(dst), "l"(g));
}
__device__ __forceinline__ void ldmx4(uint32_t* r, uint32_t addr) {
    asm volatile("ldmatrix.sync.aligned.m8n8.x4.shared.b16 {%0,%1,%2,%3}, [%4];"
                 : "=r"(r[0]), "=r"(r[1]), "=r"(r[2]), "=r"(r[3]) : "r"(addr));
}
__device__ __forceinline__ void ldmx4t(uint32_t* r, uint32_t addr) {
    asm volatile("ldmatrix.sync.aligned.m8n8.x4.trans.shared.b16 {%0,%1,%2,%3}, [%4];"
                 : "=r"(r[0]), "=r"(r[1]), "=r"(r[2]), "=r"(r[3]) : "r"(addr));
}
__device__ __forceinline__ void mma16816(float* c, const uint32_t* a, const uint32_t* b) {
    asm volatile(
        "mma.sync.aligned.m16n8k16.row.col.f32.f16.f16.f32 "
        "{%0,%1,%2,%3}, {%4,%5,%6,%7}, {%8,%9}, {%0,%1,%2,%3};"
        : "+f"(c[0]), "+f"(c[1]), "+f"(c[2]), "+f"(c[3])
        : "r"(a[0]), "r"(a[1]), "r"(a[2]), "r"(a[3]), "r"(b[0]), "r"(b[1]));
}
__device__ __forceinline__ uint32_t pack2h(float a, float b) {
    __half2 t = __floats2half2_rn(a, b);
    return *reinterpret_cast<uint32_t*>(&t);
}

// ---------------- fused weight transpose + x conversion (hi only) ------------
__global__ void transpose_all(const float* __restrict__ wq, const float* __restrict__ wk,
                              const float* __restrict__ wv, const float* __restrict__ wo,
                              const float* __restrict__ x,  __half* __restrict__ xh,
                              __half* __restrict__ wh, __half* __restrict__ woh) {
    const int bx = blockIdx.x;
    const int tx = threadIdx.x, ty = threadIdx.y;   // 32 x 8
    if (bx >= 160) {
        int idx = (((bx - 160) * gridDim.y + blockIdx.y) << 8) + (ty << 5) + tx;
        if (idx < MTOT * DIM_) xh[idx] = __float2half_rn(x[idx]);
        return;
    }
    __shared__ float t[32][33];
    const float* W; __half* hi; int N, nb;
    if (bx < 64)       { W = wq; hi = wh;  N = DIM_; nb = bx; }
    else if (bx < 80)  { W = wk; hi = wh + (size_t)DIM_ * DIM_;        N = KVD; nb = bx - 64; }
    else if (bx < 96)  { W = wv; hi = wh + (size_t)(DIM_ + KVD) * DIM_; N = KVD; nb = bx - 80; }
    else               { W = wo; hi = woh; N = DIM_; nb = bx - 96; }

    const int k0 = blockIdx.y * 32, n0 = nb * 32;
    #pragma unroll
    for (int r = ty; r < 32; r += 8)
        t[r][tx] = W[(size_t)(k0 + r) * N + n0 + tx];
    __syncthreads();
    #pragma unroll
    for (int r = ty; r < 32; r += 8)
        hi[(size_t)(n0 + r) * DIM_ + k0 + tx] = __float2half_rn(t[tx][r]);
}

// ---------------- GEMM A: 128x64 tiles, hi-only (QKV projection) ------------
// Per stage: A 128x64B (512 chunks = 2/thread), B 64x64B (256 chunks = 1/thread).
#define ROWB       80
#define TILE_A_B   (128 * ROWB)          // 10240
#define TILE_B64   (64 * ROWB)           // 5120
#define STG_N64    (TILE_A_B + TILE_B64) // 15360
#define NSTAGE     3
#define GEMM_SMEM_N64 (NSTAGE * STG_N64) // 46080

__global__ __launch_bounds__(256, 2)
void mma_gemm_n64(const __half* __restrict__ Ah, const __half* __restrict__ Bh,
                  float* __restrict__ C, int N, int K) {
    extern __shared__ char sm[];
    const uint32_t sbase = smem_u32(sm);
    const int tid  = threadIdx.x;
    const int wid  = tid >> 5;
    const int lane = tid & 31;
    const int wm = wid & 3;       // 32-row slice
    const int wn = wid >> 2;      // 0..1 -> 32-col slice
    const int m0 = blockIdx.y * 128, n0 = blockIdx.x * 64;

    float acc[2][4][4];
    #pragma unroll
    for (int i = 0; i < 2; i++)
        #pragma unroll
        for (int j = 0; j < 4; j++)
            #pragma unroll
            for (int q = 0; q < 4; q++) acc[i][j][q] = 0.0f;

    const __half* Abase = Ah + (size_t)m0 * K;
    const __half* Bbase = Bh + (size_t)n0 * K;

    const int ar = tid >> 2, ac = tid & 3;           // A rows 0..63 (+64)
    const int br = tid >> 2, bc = tid & 3;           // B rows 0..63

    auto load_stage = [&](int cidx) {
        const int k0 = cidx << 5;
        const uint32_t db = sbase + (uint32_t)(cidx % NSTAGE) * STG_N64;
        cp16(db + ar * ROWB + ac * 16,        Abase + (size_t)ar * K + k0 + ac * 8);
        cp16(db + (ar + 64) * ROWB + ac * 16, Abase + (size_t)(ar + 64) * K + k0 + ac * 8);
        cp16(db + TILE_A_B + br * ROWB + bc * 16, Bbase + (size_t)br * K + k0 + bc * 8);
        asm volatile("cp.async.commit_group;");
    };

    const int aRow  = lane & 15;
    const uint32_t aColb = (uint32_t)(lane >> 4) * 16;
    const int bRow  = ((lane & 16) >> 1) + (lane & 7);
    const uint32_t bColb = (uint32_t)((lane >> 3) & 1) * 16;

    const int NC = K >> 5;
    load_stage(0);
    load_stage(1);

    for (int c = 0; c < NC; c++) {
        asm volatile("cp.async.wait_group 1;");
        __syncthreads();
        if (c + 2 < NC) load_stage(c + 2);
        else            asm volatile("cp.async.commit_group;");

        const uint32_t db = sbase + (uint32_t)(c % NSTAGE) * STG_N64;
        #pragma unroll
        for (int ks = 0; ks < 2; ks++) {
            const uint32_t kb = (uint32_t)ks * 32;
            uint32_t ah[2][4];
            #pragma unroll
            for (int mt = 0; mt < 2; mt++)
                ldmx4(ah[mt], db + (uint32_t)(wm * 32 + mt * 16 + aRow) * ROWB + aColb + kb);
            #pragma unroll
            for (int ng = 0; ng < 2; ng++) {
                uint32_t bh[4];
                ldmx4(bh, db + TILE_A_B +
                          (uint32_t)(wn * 32 + ng * 16 + bRow) * ROWB + bColb + kb);
                #pragma unroll
                for (int mt = 0; mt < 2; mt++)
                    #pragma unroll
                    for (int jj = 0; jj < 2; jj++)
                        mma16816(acc[mt][ng * 2 + jj], ah[mt], &bh[jj * 2]);
            }
        }
    }

    const int g = lane >> 2, tg = lane & 3;
    #pragma unroll
    for (int mt = 0; mt < 2; mt++)
        #pragma unroll
        for (int nt = 0; nt < 4; nt++) {
            const int row = m0 + wm * 32 + mt * 16 + g;
            const int col = n0 + wn * 32 + nt * 8 + tg * 2;
            *(float2*)&C[(size_t)row * N + col] =
                make_float2(acc[mt][nt][0], acc[mt][nt][1]);
            *(float2*)&C[(size_t)(row + 8) * N + col] =
                make_float2(acc[mt][nt][2], acc[mt][nt][3]);
        }
}

// ---------------- GEMM B: 128x128 tiles, hi-only (WO projection) ------------
#define TILE_B_    (128 * ROWB)
#define STG_HI     (2 * TILE_B_)
#define GEMM_SMEM_HI (NSTAGE * STG_HI)   // 61440

__global__ __launch_bounds__(256, 2)
void mma_gemm_hi(const __half* __restrict__ Ah, const __half* __restrict__ Bh,
                 float* __restrict__ C, int N, int K) {
    extern __shared__ char sm[];
    const uint32_t sbase = smem_u32(sm);
    const int tid  = threadIdx.x;
    const int wid  = tid >> 5;
    const int lane = tid & 31;
    const int wm = wid & 3;
    const int wn = wid >> 2;
    const int m0 = blockIdx.y * 128, n0 = blockIdx.x * 128;

    float acc[2][8][4];
    #pragma unroll
    for (int i = 0; i < 2; i++)
        #pragma unroll
        for (int j = 0; j < 8; j++)
            #pragma unroll
            for (int q = 0; q < 4; q++) acc[i][j][q] = 0.0f;

    const __half* base[2] = { Ah + (size_t)m0 * K, Bh + (size_t)n0 * K };

    const int r0 = tid >> 2, c0 = tid & 3;
    const int r1 = (tid + 256) >> 2, c1 = tid & 3;

    auto load_stage = [&](int cidx) {
        const int k0 = cidx << 5;
        const uint32_t db = sbase + (uint32_t)(cidx % NSTAGE) * STG_HI;
        #pragma unroll
        for (int t = 0; t < 2; t++) {
            const uint32_t tb = db + t * TILE_B_;
            cp16(tb + r0 * ROWB + c0 * 16, base[t] + (size_t)r0 * K + k0 + c0 * 8);
            cp16(tb + r1 * ROWB + c1 * 16, base[t] + (size_t)r1 * K + k0 + c1 * 8);
        }
        asm volatile("cp.async.commit_group;");
    };

    const int aRow  = lane & 15;
    const uint32_t aColb = (uint32_t)(lane >> 4) * 16;
    const int bRow  = ((lane & 16) >> 1) + (lane & 7);
    const uint32_t bColb = (uint32_t)((lane >> 3) & 1) * 16;

    const int NC = K >> 5;
    load_stage(0);
    load_stage(1);

    for (int c = 0; c < NC; c++) {
        asm volatile("cp.async.wait_group 1;");
        __syncthreads();
        if (c + 2 < NC) load_stage(c + 2);
        else            asm volatile("cp.async.commit_group;");

        const uint32_t db = sbase + (uint32_t)(c % NSTAGE) * STG_HI;
        #pragma unroll
        for (int ks = 0; ks < 2; ks++) {
            const uint32_t kb = (uint32_t)ks * 32;
            uint32_t ah[2][4];
            #pragma unroll
            for (int mt = 0; mt < 2; mt++)
                ldmx4(ah[mt], db + (uint32_t)(wm * 32 + mt * 16 + aRow) * ROWB + aColb + kb);
            #pragma unroll
            for (int ng = 0; ng < 4; ng++) {
                uint32_t bh[4];
                ldmx4(bh, db + TILE_B_ +
                          (uint32_t)(wn * 64 + ng * 16 + bRow) * ROWB + bColb + kb);
                #pragma unroll
                for (int mt = 0; mt < 2; mt++)
                    #pragma unroll
                    for (int jj = 0; jj < 2; jj++)
                        mma16816(acc[mt][ng * 2 + jj], ah[mt], &bh[jj * 2]);
            }
        }
    }

    const int g = lane >> 2, tg = lane & 3;
    #pragma unroll
    for (int mt = 0; mt < 2; mt++)
        #pragma unroll
        for (int nt = 0; nt < 8; nt++) {
            const int row = m0 + wm * 32 + mt * 16 + g;
            const int col = n0 + wn * 64 + nt * 8 + tg * 2;
            *(float2*)&C[(size_t)row * N + col] =
                make_float2(acc[mt][nt][0], acc[mt][nt][1]);
            *(float2*)&C[(size_t)(row + 8) * N + col] =
                make_float2(acc[mt][nt][2], acc[mt][nt][3]);
        }
}

// ---------------- prep: rope + fp16 conversion -------------------------------
__global__ void prep_attn(const float* __restrict__ qkv,
                          __half* __restrict__ qh,
                          __half* __restrict__ kh, __half* __restrict__ vh) {
    const int PPR = 1536;
    int idx = blockIdx.x * blockDim.x + threadIdx.x;
    if (idx >= MTOT * PPR) return;
    int row = idx / PPR;
    int p   = idx - row * PPR;
    int n   = row & (SEQ - 1);
    const float* src = qkv + (size_t)row * QKVW;

    if (p < 1024) {
        int i = p & 31;
        float freq = expf(-(float)i * (9.2103403719761836f / 32.0f));
        float ph = (float)n * freq, sn, cs;
        sincosf(ph, &sn, &cs);
        float x0 = src[2 * p], x1 = src[2 * p + 1];
        *(uint32_t*)&qh[(size_t)row * DIM_ + 2 * p] =
            pack2h((x0 * cs - x1 * sn) * 0.125f, (x0 * sn + x1 * cs) * 0.125f);
    } else if (p < 1280) {
        int i2 = p - 1024, i = i2 & 31;
        float freq = expf(-(float)i * (9.2103403719761836f / 32.0f));
        float ph = (float)n * freq, sn, cs;
        sincosf(ph, &sn, &cs);
        float x0 = src[DIM_ + 2 * i2], x1 = src[DIM_ + 2 * i2 + 1];
        *(uint32_t*)&kh[(size_t)row * KVD + 2 * i2] =
            pack2h(x0 * cs - x1 * sn, x0 * sn + x1 * cs);
    } else {
        int i2 = p - 1280;
        *(uint32_t*)&vh[(size_t)row * KVD + 2 * i2] =
            pack2h(src[DIM_ + KVD + 2 * i2], src[DIM_ + KVD + 2 * i2 + 1]);
    }
}

// ---------------- flash v4: fp16 K/V hi-only, 256 thr, 128-q tiles -----------
#define SR 144
#define TSZ  (64 * SR)            // 9216
#define TSZQ (128 * SR)           // 18432
#define FLASH_SMEM (TSZQ + 4 * TSZ)   // 55296
#define NQB 8

__global__ __launch_bounds__(256)
void flash_tc(const __half* __restrict__ qh,
              const __half* __restrict__ kh, const __half* __restrict__ vh,
              __half* __restrict__ oh) {
    extern __shared__ char sm[];
    const uint32_t sb = smem_u32(sm);
    const int tid = threadIdx.x, w = tid >> 5, lane = tid & 31;
    const int h = blockIdx.y, b = blockIdx.z, kvh = h >> 2;

    const int bRow = ((lane & 16) >> 1) | (lane & 7);
    const uint32_t bCol = (uint32_t)((lane >> 3) & 1) * 16;
    const int vRow = lane & 15;
    const uint32_t vColb = (uint32_t)((lane & 16) >> 1) * 2;
    const int g = lane >> 2, tg = lane & 3;

    auto loadkv = [&](int kt, int s) {
        const uint32_t stg = sb + TSZQ + (uint32_t)s * (2 * TSZ);
        const size_t rowbase = (size_t)(b * SEQ + kt * 64) * KVD + kvh * 64;
        #pragma unroll
        for (int u = 0; u < 4; u++) {
            int id = tid + u * 256;                    // 0..1023
            int c16 = id & 7, r = (id >> 3) & 63, t = id >> 9;
            const __half* src = (t == 0 ? kh : vh) + rowbase + (size_t)r * KVD + c16 * 8;
            cp16(stg + (uint32_t)t * TSZ + (uint32_t)r * SR + (uint32_t)c16 * 16, src);
        }
        asm volatile("cp.async.commit_group;");
    };

    #pragma unroll 1
    for (int pass = 0; pass < 2; pass++) {
        const int qb = pass ? (NQB - 1 - (int)blockIdx.x) : (int)blockIdx.x;
        const int q0 = qb * 128;
        const int ktmax = 2 * qb + 1;

        {
            const __half* src = qh + (size_t)(b * SEQ + q0) * DIM_ + h * 64;
            #pragma unroll
            for (int u = 0; u < 4; u++) {
                int id = tid + u * 256;
                int c16 = id & 7, r = id >> 3;
                cp16(sb + (uint32_t)r * SR + (uint32_t)c16 * 16,
                     src + (size_t)r * DIM_ + c16 * 8);
            }
            asm volatile("cp.async.commit_group;");
            asm volatile("cp.async.wait_group 0;");
            __syncthreads();
        }
        uint32_t qah[4][4];
        {
            int aRow = lane & 15;
            uint32_t aCol = (uint32_t)(lane >> 4) * 16;
            #pragma unroll
            for (int ks = 0; ks < 4; ks++)
                ldmx4(qah[ks], sb + (uint32_t)(w * 16 + aRow) * SR + aCol + ks * 32);
        }

        float oacc[8][4];
        #pragma unroll
        for (int nt = 0; nt < 8; nt++)
            #pragma unroll
            for (int q = 0; q < 4; q++) oacc[nt][q] = 0.0f;
        float m0v = -INFINITY, m1v = -INFINITY, l0v = 0.0f, l1v = 0.0f;

        loadkv(0, 0);
        for (int kt = 0; kt <= ktmax; kt++) {
            if (kt + 1 <= ktmax) loadkv(kt + 1, (kt + 1) & 1);
            else                 asm volatile("cp.async.commit_group;");
            asm volatile("cp.async.wait_group 1;");
            __syncthreads();

            const uint32_t stg = sb + TSZQ + (uint32_t)(kt & 1) * (2 * TSZ);
            const uint32_t oKh = stg, oVh = stg + TSZ;

            float sacc[8][4];
            #pragma unroll
            for (int nt = 0; nt < 8; nt++)
                #pragma unroll
                for (int q = 0; q < 4; q++) sacc[nt][q] = 0.0f;

            #pragma unroll
            for (int ks = 0; ks < 4; ks++) {
                #pragma unroll
                for (int ng = 0; ng < 4; ng++) {
                    uint32_t kbh[4];
                    ldmx4(kbh, oKh + (uint32_t)(ng * 16 + bRow) * SR + bCol + ks * 32);
                    #pragma unroll
                    for (int jj = 0; jj < 2; jj++)
                        mma16816(sacc[ng * 2 + jj], qah[ks], &kbh[jj * 2]);
                }
            }

            if (kt >= 2 * qb) {
                const int qg0 = q0 + w * 16 + g, qg1 = qg0 + 8;
                #pragma unroll
                for (int nt = 0; nt < 8; nt++) {
                    int kg = kt * 64 + nt * 8 + tg * 2;
                    if (kg     > qg0) sacc[nt][0] = -1e30f;
                    if (kg + 1 > qg0) sacc[nt][1] = -1e30f;
                    if (kg     > qg1) sacc[nt][2] = -1e30f;
                    if (kg + 1 > qg1) sacc[nt][3] = -1e30f;
                }
            }

            float mx0 = -INFINITY, mx1 = -INFINITY;
            #pragma unroll
            for (int nt = 0; nt < 8; nt++) {
                mx0 = fmaxf(mx0, fmaxf(sacc[nt][0], sacc[nt][1]));
                mx1 = fmaxf(mx1, fmaxf(sacc[nt][2], sacc[nt][3]));
            }
            mx0 = fmaxf(mx0, __shfl_xor_sync(0xffffffffu, mx0, 1));
            mx0 = fmaxf(mx0, __shfl_xor_sync(0xffffffffu, mx0, 2));
            mx1 = fmaxf(mx1, __shfl_xor_sync(0xffffffffu, mx1, 1));
            mx1 = fmaxf(mx1, __shfl_xor_sync(0xffffffffu, mx1, 2));

            float mn0 = fmaxf(m0v, mx0), mn1 = fmaxf(m1v, mx1);
            float cr0 = __expf(m0v - mn0), cr1 = __expf(m1v - mn1);
            m0v = mn0; m1v = mn1;
            l0v *= cr0; l1v *= cr1;
            #pragma unroll
            for (int nt = 0; nt < 8; nt++) {
                oacc[nt][0] *= cr0; oacc[nt][1] *= cr0;
                oacc[nt][2] *= cr1; oacc[nt][3] *= cr1;
            }
            float rs0 = 0.0f, rs1 = 0.0f;

            #pragma unroll
            for (int ks = 0; ks < 4; ks++) {
                float p[2][4];
                #pragma unroll
                for (int jj = 0; jj < 2; jj++) {
                    const int nt = 2 * ks + jj;
                    p[jj][0] = __expf(sacc[nt][0] - mn0);
                    p[jj][1] = __expf(sacc[nt][1] - mn0);
                    p[jj][2] = __expf(sacc[nt][2] - mn1);
                    p[jj][3] = __expf(sacc[nt][3] - mn1);
                    rs0 += p[jj][0] + p[jj][1];
                    rs1 += p[jj][2] + p[jj][3];
                }
                uint32_t pah[4];
                pah[0] = pack2h(p[0][0], p[0][1]);
                pah[1] = pack2h(p[0][2], p[0][3]);
                pah[2] = pack2h(p[1][0], p[1][1]);
                pah[3] = pack2h(p[1][2], p[1][3]);

                #pragma unroll
                for (int ng = 0; ng < 4; ng++) {
                    uint32_t vbh[4];
                    ldmx4t(vbh, oVh + (uint32_t)(ks * 16 + vRow) * SR
                                 + (uint32_t)ng * 32 + vColb);
                    #pragma unroll
                    for (int jj = 0; jj < 2; jj++)
                        mma16816(oacc[ng * 2 + jj], pah, &vbh[jj * 2]);
                }
            }
            rs0 += __shfl_xor_sync(0xffffffffu, rs0, 1);
            rs0 += __shfl_xor_sync(0xffffffffu, rs0, 2);
            rs1 += __shfl_xor_sync(0xffffffffu, rs1, 1);
            rs1 += __shfl_xor_sync(0xffffffffu, rs1, 2);
            l0v += rs0; l1v += rs1;

            __syncthreads();
        }

        const float i0 = 1.0f / l0v, i1 = 1.0f / l1v;
        const int r0 = q0 + w * 16 + g;
        #pragma unroll
        for (int nt = 0; nt < 8; nt++) {
            const int col = h * 64 + nt * 8 + tg * 2;
            const size_t o0 = ((size_t)(b * SEQ + r0)) * DIM_ + col;
            const size_t o1 = o0 + (size_t)8 * DIM_;
            *(uint32_t*)&oh[o0] = pack2h(oacc[nt][0] * i0, oacc[nt][1] * i0);
            *(uint32_t*)&oh[o1] = pack2h(oacc[nt][2] * i1, oacc[nt][3] * i1);
        }
    }
}

// ---------------------------------------------------------------------------
extern "C" void kernel_launch(void* const* d_in, const int* in_sizes, int n_in,
                              void* d_out, int out_size) {
    const float* x  = (const float*)d_in[0];
    const float* wq = (const float*)d_in[1];
    const float* wk = (const float*)d_in[2];
    const float* wv = (const float*)d_in[3];
    const float* wo = (const float*)d_in[4];
    float* out = (float*)d_out;

    float* qkv;
    cudaGetSymbolAddress((void**)&qkv, g_qkv);
    __half *xh, *ah, *qh, *kh, *vh, *wh, *woh;
    cudaGetSymbolAddress((void**)&xh,  g_xh);
    cudaGetSymbolAddress((void**)&ah,  g_ah);
    cudaGetSymbolAddress((void**)&qh,  g_qh);
    cudaGetSymbolAddress((void**)&kh,  g_kh);
    cudaGetSymbolAddress((void**)&vh,  g_vh);
    cudaGetSymbolAddress((void**)&wh,  g_wh);
    cudaGetSymbolAddress((void**)&woh, g_woh);

    cudaFuncSetAttribute(mma_gemm_n64,
                         cudaFuncAttributeMaxDynamicSharedMemorySize, GEMM_SMEM_N64);
    cudaFuncSetAttribute(mma_gemm_hi,
                         cudaFuncAttributeMaxDynamicSharedMemorySize, GEMM_SMEM_HI);
    cudaFuncSetAttribute(flash_tc,
                         cudaFuncAttributeMaxDynamicSharedMemorySize, FLASH_SMEM);

    const int M = MTOT;

    // 0: weights transpose (hi only) AND x->fp16 (fused)
    transpose_all<<<dim3(416, 64), dim3(32, 8)>>>(wq, wk, wv, wo, x, xh, wh, woh);
    // 1: fused QKV projection (hi-only, 128x64 tiles)
    mma_gemm_n64<<<dim3(QKVW / 64, M / 128), 256, GEMM_SMEM_N64>>>(
        xh, wh, qkv, QKVW, DIM_);
    // 2: rope + fp16
    prep_attn<<<(M * 1536 + 255) / 256, 256>>>(qkv, qh, kh, vh);
    // 3: flash attention (profiled slot)
    flash_tc<<<dim3(NQB / 2, NH, B_), 256, FLASH_SMEM>>>(qh, kh, vh, ah);
    // 4: output projection (hi-only)
    mma_gemm_hi<<<dim3(DIM_ / 128, M / 128), 256, GEMM_SMEM_HI>>>(
        ah, woh, out, DIM_, DIM_);
}